// round 10
// baseline (speedup 1.0000x reference)
#include <cuda_runtime.h>
#include <cuda_fp16.h>
#include <math.h>
#include <stdint.h>

// ---------------------------------------------------------------------------
// SpatioTemporalPerformerEncoder — R10: fragment double-buffered mainloop
// ---------------------------------------------------------------------------

#define Bc     2
#define Hc     8
#define Nc     4096
#define Dc     512
#define DHc    64
#define Mc     256
#define FFc    2048
#define DEPTHc 4
#define ROWSc  8192
#define BHc    16
#define QKVW   1536

#define DN_CONST    0.35355339059327373f
#define DIAG_SCALE  0.0625f
#define RATIO_CONST 0.0625f
#define EPSK        1e-4f
#define LNEPS       1e-5f

#define HG_SMEM 61440   // 3 stages x (10240 A + 10240 B)

// ------------------------- scratch (device globals) ------------------------
__device__ __half g_ln16 [(size_t)ROWSc * Dc];
__device__ __half g_qkv16[(size_t)ROWSc * QKVW];
__device__ __half g_ff16 [(size_t)ROWSc * FFc];
__device__ __half g_att16[(size_t)ROWSc * Dc];
__device__ float  g_qp   [(size_t)BHc * Nc * Mc];
__device__ float  g_kp   [(size_t)BHc * Nc * Mc];
__device__ __half g_qp16 [(size_t)BHc * Nc * Mc];
__device__ __half g_kpT  [(size_t)BHc * Mc * Nc];
__device__ __half g_vT   [(size_t)BHc * 128 * Nc];   // rows 64..127 zero
__device__ float  g_ctxF [(size_t)BHc * 128 * Mc];
__device__ __half g_ctxT [(size_t)BHc * 128 * Mc];
__device__ float  g_ksum [BHc * Mc];
__device__ float  g_qdiag[BHc * Nc];
__device__ float  g_kdiag[BHc * Nc];
__device__ float  g_hmax [BHc];
__device__ float  g_dinv [BHc * Nc];
__device__ __half g_wqkvT[(size_t)DEPTHc * QKVW * Dc];
__device__ __half g_woT  [(size_t)DEPTHc * Dc * Dc];
__device__ __half g_wff1T[(size_t)DEPTHc * FFc * Dc];
__device__ __half g_wff2T[(size_t)DEPTHc * Dc * FFc];
__device__ __half g_projh[(size_t)DEPTHc * Mc * DHc];

// ------------------------------ helpers ------------------------------------
__device__ __forceinline__ uint32_t smem_to_u32(const void* p) {
    uint32_t a;
    asm("{ .reg .u64 t; cvta.to.shared.u64 t, %1; cvt.u32.u64 %0, t; }"
        : "=r"(a) : "l"(p));
    return a;
}
__device__ __forceinline__ uint32_t f2h2(float a, float b) {
    __half2 h = __floats2half2_rn(a, b);
    return *(uint32_t*)&h;
}
__device__ __forceinline__ void cp16(uint32_t dst, const void* src) {
    asm volatile("cp.async.cg.shared.global [%0], [%1], 16;"
                 :: "r"(dst), "l"(src));
}
#define CP_COMMIT() asm volatile("cp.async.commit_group;")
#define CP_WAIT(n)  asm volatile("cp.async.wait_group %0;" :: "n"(n))

__device__ __forceinline__ void ldsm4(uint32_t& r0, uint32_t& r1, uint32_t& r2,
                                      uint32_t& r3, uint32_t a) {
    asm volatile("ldmatrix.sync.aligned.m8n8.x4.shared.b16 {%0,%1,%2,%3}, [%4];"
                 : "=r"(r0), "=r"(r1), "=r"(r2), "=r"(r3) : "r"(a));
}
__device__ __forceinline__ void mma_f16(float c[4], const uint32_t a[4],
                                        const uint32_t b[2]) {
    asm volatile(
        "mma.sync.aligned.m16n8k16.row.col.f32.f16.f16.f32 "
        "{%0,%1,%2,%3}, {%4,%5,%6,%7}, {%8,%9}, {%0,%1,%2,%3};"
        : "+f"(c[0]), "+f"(c[1]), "+f"(c[2]), "+f"(c[3])
        : "r"(a[0]), "r"(a[1]), "r"(a[2]), "r"(a[3]), "r"(b[0]), "r"(b[1]));
}
__device__ __forceinline__ void atomicMaxF(float* a, float v) {
    if (v >= 0.0f) atomicMax((int*)a, __float_as_int(v));
    else atomicMin((unsigned int*)a, __float_as_uint(v));
}

// ------------------------- fp16 tensor-core GEMM ---------------------------
// C = scale*(A[M,K]h @ B[N,K]h^T) + epilogue. BM=BN=128, BK=32, 128 threads,
// warp tile 64x64, 3-stage cp.async pipeline + register-double-buffered frags.
// BHM 0: plain. 2: ctx (per-bh, K-split via blockIdx.y, fp32 atomic out).
// 3: attnout (per-bh, dinv row scale via R, head-merged out).
// 4: merged dd q/k (z<16: q->C, z>=16: k->C2 + fused global-max into hmaxp).
#define EPI_NONE 0
#define EPI_GELU 1
#define EPI_ADD  2
#define EPI_DINV 3

template <int EPI, int BHM, typename OutT>
__global__ __launch_bounds__(128)
void hgemm(const __half* __restrict__ A, int lda,
           const __half* __restrict__ Bh, int ldb,
           const float* __restrict__ bias, const float* __restrict__ R,
           OutT* __restrict__ C, int ldc, int K, float scale,
           int mvalid, int nvalid, float* __restrict__ C2,
           float* __restrict__ hmaxp) {
    extern __shared__ __align__(16) char smem_dyn[];
    uint32_t sBase = smem_to_u32(smem_dyn);

    int m0, n0;
    int isk = 0;
    if (BHM == 2) {
        int z = blockIdx.z;
        A += (size_t)z * 128 * lda + (size_t)blockIdx.y * K;
        Bh += (size_t)z * Mc * ldb + (size_t)blockIdx.y * K;
        C += (size_t)z * 128 * ldc;
        m0 = 0;
        n0 = blockIdx.x * 128;
    } else {
        if (BHM == 4) {
            int z = blockIdx.z;
            isk = z >> 4;
            int bh = z & 15;
            A += (size_t)(bh >> 3) * Nc * lda + (size_t)(bh & 7) * DHc +
                 (size_t)isk * Dc;
            float* Cb = isk ? C2 : (float*)C;
            C = (OutT*)(Cb + (size_t)bh * Nc * ldc);
        }
        if (BHM == 3) {
            int z = blockIdx.z;
            A += (size_t)z * Nc * lda;
            Bh += (size_t)z * 128 * ldb;
            C += (size_t)(z >> 3) * Nc * Dc + (size_t)(z & 7) * DHc;
            R += (size_t)z * Nc;
        }
        m0 = blockIdx.y * 128;
        n0 = blockIdx.x * 128;
    }

    int tid = threadIdx.x, lane = tid & 31, warp = tid >> 5;
    int wm = warp >> 1, wn = warp & 1;

    int rowC = tid >> 2, cA = (tid & 3) * 8;
    uint32_t sOff = ((uint32_t)rowC * 40 + cA) * 2;
    uint32_t fOff = (((lane & 15) * 40) + (lane >> 4) * 8) * 2;

    float c[4][8][4];
#pragma unroll
    for (int i = 0; i < 4; i++)
#pragma unroll
        for (int j = 0; j < 8; j++)
#pragma unroll
            for (int l = 0; l < 4; l++) c[i][j][l] = 0.0f;

#define ISSUE(t, buf)                                                         \
    {                                                                         \
        int k0 = (t) * 32;                                                    \
        _Pragma("unroll")                                                     \
        for (int p = 0; p < 4; p++) {                                         \
            cp16(sBase + (buf) * 10240 + sOff + p * 2560,                     \
                 A + (size_t)(m0 + rowC + p * 32) * lda + k0 + cA);           \
            cp16(sBase + 30720 + (buf) * 10240 + sOff + p * 2560,             \
                 Bh + (size_t)(n0 + rowC + p * 32) * ldb + k0 + cA);          \
        }                                                                     \
        CP_COMMIT();                                                          \
    }

    int T = K >> 5;                 // all call sites have K >= 64 (T >= 2)
    ISSUE(0, 0)
    ISSUE(1, 1)
    int buf = 0;
    for (int t = 0; t < T; t++) {
        if (t == T - 1) { CP_WAIT(0); } else { CP_WAIT(1); }
        __syncthreads();

        uint32_t aTile = sBase + buf * 10240;
        uint32_t bTile = sBase + 30720 + buf * 10240;

        // hoist ALL fragment loads for both k16 groups (register double buffer)
        uint32_t af[2][4][4], bf[2][8][2];
#pragma unroll
        for (int kk = 0; kk < 2; kk++) {
            int k16 = kk * 16;
#pragma unroll
            for (int mi = 0; mi < 4; mi++)
                ldsm4(af[kk][mi][0], af[kk][mi][1], af[kk][mi][2], af[kk][mi][3],
                      aTile + ((wm * 64 + mi * 16) * 40 + k16) * 2 + fOff);
#pragma unroll
            for (int p = 0; p < 4; p++) {
                uint32_t r0, r1, r2, r3;
                ldsm4(r0, r1, r2, r3,
                      bTile + ((wn * 64 + p * 16) * 40 + k16) * 2 + fOff);
                bf[kk][2 * p][0] = r0; bf[kk][2 * p][1] = r2;
                bf[kk][2 * p + 1][0] = r1; bf[kk][2 * p + 1][1] = r3;
            }
        }

        // overlap next-next tile's global loads with the MMA burst
        if (t + 2 < T) {
            int nb = buf + 2; if (nb >= 3) nb -= 3;
            ISSUE(t + 2, nb)
        }

#pragma unroll
        for (int kk = 0; kk < 2; kk++)
#pragma unroll
            for (int mi = 0; mi < 4; mi++)
#pragma unroll
                for (int ni = 0; ni < 8; ni++)
                    mma_f16(c[mi][ni], af[kk][mi], bf[kk][ni]);

        buf = (buf + 1 == 3) ? 0 : buf + 1;
    }
#undef ISSUE

    // epilogue
    int g = lane >> 2, tig = lane & 3;
    float tm = -1e30f;
#pragma unroll
    for (int mi = 0; mi < 4; mi++) {
#pragma unroll
        for (int ni = 0; ni < 8; ni++) {
            int rl = wm * 64 + mi * 16 + g;
            int cl = wn * 64 + ni * 8 + 2 * tig;
            if (cl >= nvalid) continue;
            int col = n0 + cl;
#pragma unroll
            for (int half = 0; half < 2; half++) {
                int rll = rl + half * 8;
                if (rll >= mvalid) continue;
                int r = m0 + rll;
                float v0 = c[mi][ni][half * 2 + 0] * scale;
                float v1 = c[mi][ni][half * 2 + 1] * scale;
                if (BHM == 4) tm = fmaxf(tm, fmaxf(v0, v1));
                if (bias) { v0 += bias[col]; v1 += bias[col + 1]; }
                if (EPI == EPI_GELU) {
                    v0 = 0.5f * v0 * (1.0f + erff(v0 * 0.70710678118654752f));
                    v1 = 0.5f * v1 * (1.0f + erff(v1 * 0.70710678118654752f));
                }
                if (EPI == EPI_ADD) {
                    v0 += R[(size_t)r * ldc + col];
                    v1 += R[(size_t)r * ldc + col + 1];
                }
                if (EPI == EPI_DINV) {
                    float di = R[r];
                    v0 *= di; v1 *= di;
                }
                if (BHM == 2) {
                    atomicAdd(&((float*)C)[(size_t)r * ldc + col], v0);
                    atomicAdd(&((float*)C)[(size_t)r * ldc + col + 1], v1);
                } else if (sizeof(OutT) == 2) {
                    __half2 hv = __floats2half2_rn(v0, v1);
                    *(__half2*)&((__half*)C)[(size_t)r * ldc + col] = hv;
                } else {
                    float2 o = {v0, v1};
                    *(float2*)&((float*)C)[(size_t)r * ldc + col] = o;
                }
            }
        }
    }
    if (BHM == 4 && isk) {
#pragma unroll
        for (int o = 16; o > 0; o >>= 1)
            tm = fmaxf(tm, __shfl_xor_sync(0xffffffffu, tm, o));
        if (lane == 0) atomicMaxF(&hmaxp[blockIdx.z & 15], tm);
    }
}

// --------------- batched weight transpose + convert to fp16 ----------------
__global__ __launch_bounds__(256)
void transpose_all(const float* __restrict__ Wqkv, const float* __restrict__ Wo,
                   const float* __restrict__ Wff1, const float* __restrict__ Wff2,
                   const float* __restrict__ proj,
                   __half* __restrict__ qkvT, __half* __restrict__ woT,
                   __half* __restrict__ ff1T, __half* __restrict__ ff2T,
                   __half* __restrict__ projh) {
    __shared__ float tbuf[32][33];
    int z = blockIdx.z;
    if (z >= 16) {
        int l = z - 16;
        int idx = (blockIdx.y * gridDim.x + blockIdx.x) * 256 + threadIdx.x;
        if (idx < Mc * DHc)
            projh[(size_t)l * Mc * DHc + idx] =
                __float2half(proj[(size_t)l * Mc * DHc + idx]);
        return;
    }
    int type = z & 3, l = z >> 2;
    int K, N;
    const float* in;
    __half* out;
    if (type == 0)      { K = Dc;  N = QKVW; in = Wqkv + (size_t)l * Dc * QKVW; out = qkvT + (size_t)l * QKVW * Dc; }
    else if (type == 1) { K = Dc;  N = Dc;   in = Wo   + (size_t)l * Dc * Dc;   out = woT  + (size_t)l * Dc * Dc; }
    else if (type == 2) { K = Dc;  N = FFc;  in = Wff1 + (size_t)l * Dc * FFc;  out = ff1T + (size_t)l * FFc * Dc; }
    else                { K = FFc; N = Dc;   in = Wff2 + (size_t)l * FFc * Dc;  out = ff2T + (size_t)l * Dc * FFc; }

    int nx = blockIdx.x * 32, kx = blockIdx.y * 32;
    if (nx >= N || kx >= K) return;
    int tx = threadIdx.x & 31, ty = threadIdx.x >> 5;
#pragma unroll
    for (int i = 0; i < 4; i++)
        tbuf[ty + i * 8][tx] = in[(size_t)(kx + ty + i * 8) * N + nx + tx];
    __syncthreads();
#pragma unroll
    for (int i = 0; i < 4; i++)
        out[(size_t)(nx + ty + i * 8) * K + kx + tx] =
            __float2half(tbuf[tx][ty + i * 8]);
}

// ------------------------------ copy x -> h --------------------------------
__global__ void copy_kernel(const float* __restrict__ x, float* __restrict__ h) {
    size_t i = (size_t)blockIdx.x * 256 + threadIdx.x;
    h[i] = x[i];
}

// ------------------- layernorm: warp per row (fp16 out) --------------------
__global__ __launch_bounds__(256)
void ln_kernel(const float* __restrict__ x, const float* __restrict__ g,
               const float* __restrict__ b, __half* __restrict__ out) {
    int w = threadIdx.x >> 5, lane = threadIdx.x & 31;
    int row = blockIdx.x * 8 + w;
    const float4* xr = (const float4*)(x + (size_t)row * Dc);
    float4 v[4];
    float s = 0.0f;
#pragma unroll
    for (int i = 0; i < 4; i++) {
        v[i] = xr[lane + i * 32];
        s += (v[i].x + v[i].y) + (v[i].z + v[i].w);
    }
#pragma unroll
    for (int o = 16; o > 0; o >>= 1) s += __shfl_xor_sync(0xffffffffu, s, o);
    float mu = s * (1.0f / Dc);
    float var = 0.0f;
#pragma unroll
    for (int i = 0; i < 4; i++) {
        v[i].x -= mu; v[i].y -= mu; v[i].z -= mu; v[i].w -= mu;
        var += v[i].x * v[i].x + v[i].y * v[i].y +
               v[i].z * v[i].z + v[i].w * v[i].w;
    }
#pragma unroll
    for (int o = 16; o > 0; o >>= 1) var += __shfl_xor_sync(0xffffffffu, var, o);
    float rs = rsqrtf(var * (1.0f / Dc) + LNEPS);
    const float4* gp = (const float4*)g;
    const float4* bp = (const float4*)b;
    __half* orow = out + (size_t)row * Dc;
#pragma unroll
    for (int i = 0; i < 4; i++) {
        float4 gg = gp[lane + i * 32], bb = bp[lane + i * 32];
        uint2 o2;
        o2.x = f2h2(v[i].x * rs * gg.x + bb.x, v[i].y * rs * gg.y + bb.y);
        o2.y = f2h2(v[i].z * rs * gg.z + bb.z, v[i].w * rs * gg.w + bb.w);
        *(uint2*)&orow[(lane + i * 32) * 4] = o2;
    }
}

// ------------------- diag: per-(bh,row) 0.5*dn^2*|q|^2, |k|^2 --------------
__global__ __launch_bounds__(256)
void diag_kernel(const __half* __restrict__ qkv, float* __restrict__ qdiag,
                 float* __restrict__ kdiag) {
    int row = blockIdx.x;
    int w = threadIdx.x >> 5, lane = threadIdx.x & 31;
    const __half* base = qkv + (size_t)row * QKVW + w * DHc;
    float q0 = __half2float(base[lane]), q1 = __half2float(base[lane + 32]);
    float k0 = __half2float(base[Dc + lane]),
          k1 = __half2float(base[Dc + lane + 32]);
    float sq = q0 * q0 + q1 * q1;
    float sk = k0 * k0 + k1 * k1;
#pragma unroll
    for (int o = 16; o > 0; o >>= 1) {
        sq += __shfl_down_sync(0xffffffffu, sq, o);
        sk += __shfl_down_sync(0xffffffffu, sk, o);
    }
    if (lane == 0) {
        int bh = (row >> 12) * Hc + w;
        int n = row & (Nc - 1);
        qdiag[(size_t)bh * Nc + n] = sq * DIAG_SCALE;
        kdiag[(size_t)bh * Nc + n] = sk * DIAG_SCALE;
    }
}

// ---------- q features: per-row max + exp, fp32 dd -> fp16 features --------
__global__ __launch_bounds__(256)
void featq_finish(const float* __restrict__ qp, const float* __restrict__ qdiag,
                  __half* __restrict__ qp16) {
    int w = threadIdx.x >> 5, lane = threadIdx.x & 31;
    int rr = blockIdx.x * 8 + w;
    const float* p = qp + (size_t)rr * Mc + lane * 8;
    float4 v0 = *(const float4*)p;
    float4 v1 = *(const float4*)(p + 4);
    float mx = fmaxf(fmaxf(fmaxf(v0.x, v0.y), fmaxf(v0.z, v0.w)),
                     fmaxf(fmaxf(v1.x, v1.y), fmaxf(v1.z, v1.w)));
#pragma unroll
    for (int o = 16; o > 0; o >>= 1)
        mx = fmaxf(mx, __shfl_xor_sync(0xffffffffu, mx, o));
    float sub = qdiag[rr] + mx;
    uint4 o;
    o.x = f2h2(RATIO_CONST * (expf(v0.x - sub) + EPSK),
               RATIO_CONST * (expf(v0.y - sub) + EPSK));
    o.y = f2h2(RATIO_CONST * (expf(v0.z - sub) + EPSK),
               RATIO_CONST * (expf(v0.w - sub) + EPSK));
    o.z = f2h2(RATIO_CONST * (expf(v1.x - sub) + EPSK),
               RATIO_CONST * (expf(v1.y - sub) + EPSK));
    o.w = f2h2(RATIO_CONST * (expf(v1.z - sub) + EPSK),
               RATIO_CONST * (expf(v1.w - sub) + EPSK));
    *(uint4*)&qp16[(size_t)rr * Mc + lane * 8] = o;
}

// -------- k features: exp + transpose -> kpT16 [bh][m][n] ------------------
__global__ __launch_bounds__(256)
void featkT(const float* __restrict__ kp, const float* __restrict__ kdiag,
            const float* __restrict__ hmax, __half* __restrict__ kpT) {
    __shared__ __half tile[32][33];
    int bh = blockIdx.z;
    int n0 = blockIdx.x * 32, m0 = blockIdx.y * 32;
    float hm = hmax[bh];
    int tx = threadIdx.x & 31, ty = threadIdx.x >> 5;
#pragma unroll
    for (int i = 0; i < 4; i++) {
        int n = n0 + ty + i * 8;
        float sub = kdiag[(size_t)bh * Nc + n] + hm;
        float v = kp[((size_t)bh * Nc + n) * Mc + m0 + tx];
        tile[ty + i * 8][tx] = __float2half(RATIO_CONST * (expf(v - sub) + EPSK));
    }
    __syncthreads();
#pragma unroll
    for (int i = 0; i < 4; i++) {
        int m = m0 + ty + i * 8;
        kpT[((size_t)bh * Mc + m) * Nc + n0 + tx] = tile[tx][ty + i * 8];
    }
}

// -------------------- v transpose: vT16 [bh][d][n] -------------------------
__global__ __launch_bounds__(256)
void vtrans(const __half* __restrict__ qkv, __half* __restrict__ vT) {
    __shared__ __half tile[32][33];
    int z = blockIdx.z;
    int b = z >> 3, h = z & 7;
    int n0 = blockIdx.x * 32, d0 = blockIdx.y * 32;
    int tx = threadIdx.x & 31, ty = threadIdx.x >> 5;
#pragma unroll
    for (int i = 0; i < 4; i++)
        tile[ty + i * 8][tx] =
            qkv[((size_t)(b * Nc + n0 + ty + i * 8)) * QKVW + 2 * Dc + h * DHc +
                d0 + tx];
    __syncthreads();
#pragma unroll
    for (int i = 0; i < 4; i++)
        vT[((size_t)z * 128 + d0 + ty + i * 8) * Nc + n0 + tx] =
            tile[tx][ty + i * 8];
}

// --------------------------- ksum from kpT ---------------------------------
__global__ __launch_bounds__(256)
void ksum_kernel(const __half* __restrict__ kpT, float* __restrict__ ksum) {
    int bh = blockIdx.y;
    int m = blockIdx.x * 8 + (threadIdx.x >> 5);
    int lane = threadIdx.x & 31;
    const uint4* row = (const uint4*)(kpT + ((size_t)bh * Mc + m) * Nc);
    float s = 0.0f;
    for (int i = lane; i < Nc / 8; i += 32) {
        uint4 u = row[i];
        __half2* hp = (__half2*)&u;
#pragma unroll
        for (int j = 0; j < 4; j++) {
            float2 f = __half22float2(hp[j]);
            s += f.x + f.y;
        }
    }
#pragma unroll
    for (int o = 16; o > 0; o >>= 1) s += __shfl_down_sync(0xffffffffu, s, o);
    if (lane == 0) ksum[bh * Mc + m] = s;
}

// ------------------ zero ctxF + init hmax (-inf) ---------------------------
__global__ void initbuf(float* __restrict__ ctxF, float* __restrict__ hmax) {
    size_t i = (size_t)blockIdx.x * 256 + threadIdx.x;
    ctxF[i] = 0.0f;
    if (i < BHc) hmax[i] = -1e30f;
}

// ------------------------- convert ctxF -> ctxT16 --------------------------
__global__ void cvtctx(const float* __restrict__ ctxF, __half* __restrict__ ctxT) {
    size_t i = (size_t)blockIdx.x * 256 + threadIdx.x;
    ctxT[i] = __float2half(ctxF[i]);
}

// ------------------------------- d_inv -------------------------------------
__global__ __launch_bounds__(256)
void dinv_kernel(const __half* __restrict__ qp16, const float* __restrict__ ksum,
                 float* __restrict__ dinv) {
    int w = threadIdx.x >> 5, lane = threadIdx.x & 31;
    int rr = blockIdx.x * 8 + w;
    int bh = rr >> 12;
    uint4 u = ((const uint4*)(qp16 + (size_t)rr * Mc))[lane];
    const float* ks = ksum + bh * Mc + lane * 8;
    __half2* hp = (__half2*)&u;
    float s = 0.0f;
#pragma unroll
    for (int j = 0; j < 4; j++) {
        float2 f = __half22float2(hp[j]);
        s += f.x * ks[2 * j] + f.y * ks[2 * j + 1];
    }
#pragma unroll
    for (int o = 16; o > 0; o >>= 1) s += __shfl_down_sync(0xffffffffu, s, o);
    if (lane == 0) dinv[rr] = 1.0f / s;
}

// ------------------------------- launch ------------------------------------
extern "C" void kernel_launch(void* const* d_in, const int* in_sizes, int n_in,
                              void* d_out, int out_size) {
    (void)in_sizes; (void)n_in; (void)out_size;
    const float* x    = (const float*)d_in[0];
    const float* proj = (const float*)d_in[1];
    const float* ln1g = (const float*)d_in[2];
    const float* ln1b = (const float*)d_in[3];
    const float* Wqkv = (const float*)d_in[4];
    const float* bqkv = (const float*)d_in[5];
    const float* Wo   = (const float*)d_in[6];
    const float* bo   = (const float*)d_in[7];
    const float* ln2g = (const float*)d_in[8];
    const float* ln2b = (const float*)d_in[9];
    const float* Wff1 = (const float*)d_in[10];
    const float* bff1 = (const float*)d_in[11];
    const float* Wff2 = (const float*)d_in[12];
    const float* bff2 = (const float*)d_in[13];
    float* h = (float*)d_out;

    static float *p_qp = 0, *p_kp = 0, *p_ctxF = 0, *p_ksum = 0, *p_qdiag = 0,
                 *p_kdiag = 0, *p_hmax = 0, *p_dinv = 0;
    static __half *p_ln16 = 0, *p_qkv16 = 0, *p_ff16 = 0, *p_att16 = 0,
                  *p_qp16 = 0, *p_kpT = 0, *p_vT = 0, *p_ctxT = 0,
                  *p_wqkvT = 0, *p_woT = 0, *p_wff1T = 0, *p_wff2T = 0,
                  *p_projh = 0;
    if (!p_qp) {
        cudaGetSymbolAddress((void**)&p_qp, g_qp);
        cudaGetSymbolAddress((void**)&p_kp, g_kp);
        cudaGetSymbolAddress((void**)&p_ctxF, g_ctxF);
        cudaGetSymbolAddress((void**)&p_ksum, g_ksum);
        cudaGetSymbolAddress((void**)&p_qdiag, g_qdiag);
        cudaGetSymbolAddress((void**)&p_kdiag, g_kdiag);
        cudaGetSymbolAddress((void**)&p_hmax, g_hmax);
        cudaGetSymbolAddress((void**)&p_dinv, g_dinv);
        cudaGetSymbolAddress((void**)&p_ln16, g_ln16);
        cudaGetSymbolAddress((void**)&p_qkv16, g_qkv16);
        cudaGetSymbolAddress((void**)&p_ff16, g_ff16);
        cudaGetSymbolAddress((void**)&p_att16, g_att16);
        cudaGetSymbolAddress((void**)&p_qp16, g_qp16);
        cudaGetSymbolAddress((void**)&p_kpT, g_kpT);
        cudaGetSymbolAddress((void**)&p_vT, g_vT);
        cudaGetSymbolAddress((void**)&p_ctxT, g_ctxT);
        cudaGetSymbolAddress((void**)&p_wqkvT, g_wqkvT);
        cudaGetSymbolAddress((void**)&p_woT, g_woT);
        cudaGetSymbolAddress((void**)&p_wff1T, g_wff1T);
        cudaGetSymbolAddress((void**)&p_wff2T, g_wff2T);
        cudaGetSymbolAddress((void**)&p_projh, g_projh);
        cudaFuncSetAttribute(hgemm<EPI_NONE, 0, __half>,
                             cudaFuncAttributeMaxDynamicSharedMemorySize, HG_SMEM);
        cudaFuncSetAttribute(hgemm<EPI_NONE, 4, float>,
                             cudaFuncAttributeMaxDynamicSharedMemorySize, HG_SMEM);
        cudaFuncSetAttribute(hgemm<EPI_NONE, 2, float>,
                             cudaFuncAttributeMaxDynamicSharedMemorySize, HG_SMEM);
        cudaFuncSetAttribute(hgemm<EPI_DINV, 3, __half>,
                             cudaFuncAttributeMaxDynamicSharedMemorySize, HG_SMEM);
        cudaFuncSetAttribute(hgemm<EPI_ADD, 0, float>,
                             cudaFuncAttributeMaxDynamicSharedMemorySize, HG_SMEM);
        cudaFuncSetAttribute(hgemm<EPI_GELU, 0, __half>,
                             cudaFuncAttributeMaxDynamicSharedMemorySize, HG_SMEM);
    }

    // launch 0: weight transposes + fp16 conversion
    transpose_all<<<dim3(64, 64, 20), 256>>>(Wqkv, Wo, Wff1, Wff2, proj,
                                             p_wqkvT, p_woT, p_wff1T, p_wff2T,
                                             p_projh);
    // launch 1
    copy_kernel<<<(ROWSc * Dc) / 256, 256>>>(x, h);

    for (int l = 0; l < DEPTHc; l++) {
        const __half* pjh = p_projh + (size_t)l * Mc * DHc;

        ln_kernel<<<ROWSc / 8, 256>>>(h, ln1g + l * Dc, ln1b + l * Dc, p_ln16);

        // launch 3 (profiled): QKV
        hgemm<EPI_NONE, 0, __half><<<dim3(QKVW / 128, ROWSc / 128), 128, HG_SMEM>>>(
            p_ln16, Dc, p_wqkvT + (size_t)l * QKVW * Dc, Dc,
            bqkv + l * QKVW, (const float*)0, p_qkv16, QKVW, Dc, 1.0f, 128, 128,
            (float*)0, (float*)0);

        initbuf<<<(BHc * 128 * Mc) / 256, 256>>>(p_ctxF, p_hmax);

        // merged dd_q/dd_k (z<16: q -> qp, z>=16: k -> kp + fused hmax)
        hgemm<EPI_NONE, 4, float><<<dim3(Mc / 128, Nc / 128, 2 * BHc), 128, HG_SMEM>>>(
            p_qkv16, QKVW, pjh, DHc, (const float*)0, (const float*)0,
            p_qp, Mc, DHc, DN_CONST, 128, 128, p_kp, p_hmax);

        diag_kernel<<<ROWSc, 256>>>(p_qkv16, p_qdiag, p_kdiag);
        featq_finish<<<(BHc * Nc) / 8, 256>>>(p_qp, p_qdiag, p_qp16);
        featkT<<<dim3(Nc / 32, Mc / 32, BHc), 256>>>(p_kp, p_kdiag, p_hmax, p_kpT);
        vtrans<<<dim3(Nc / 32, 2, BHc), 256>>>(p_qkv16, p_vT);
        ksum_kernel<<<dim3(Mc / 8, BHc), 256>>>(p_kpT, p_ksum);

        // ctx^T = vT @ kpT^T, split-K=8, fp32 atomic accumulate
        hgemm<EPI_NONE, 2, float><<<dim3(Mc / 128, 8, BHc), 128, HG_SMEM>>>(
            p_vT, Nc, p_kpT, Nc, (const float*)0, (const float*)0,
            p_ctxF, Mc, Nc / 8, 1.0f, 64, 128, (float*)0, (float*)0);
        cvtctx<<<(BHc * 128 * Mc) / 256, 256>>>(p_ctxF, p_ctxT);

        dinv_kernel<<<(BHc * Nc) / 8, 256>>>(p_qp16, p_ksum, p_dinv);

        // attnout = (qp16 @ ctxT^T) * dinv, head-merged fp16
        hgemm<EPI_DINV, 3, __half><<<dim3(1, Nc / 128, BHc), 128, HG_SMEM>>>(
            p_qp16, Mc, p_ctxT, Mc, (const float*)0, p_dinv,
            p_att16, Dc, Mc, 1.0f, 128, 64, (float*)0, (float*)0);

        // Wo + residual
        hgemm<EPI_ADD, 0, float><<<dim3(Dc / 128, ROWSc / 128), 128, HG_SMEM>>>(
            p_att16, Dc, p_woT + (size_t)l * Dc * Dc, Dc,
            bo + l * Dc, h, h, Dc, Dc, 1.0f, 128, 128, (float*)0, (float*)0);

        ln_kernel<<<ROWSc / 8, 256>>>(h, ln2g + l * Dc, ln2b + l * Dc, p_ln16);

        // FF1 + gelu
        hgemm<EPI_GELU, 0, __half><<<dim3(FFc / 128, ROWSc / 128), 128, HG_SMEM>>>(
            p_ln16, Dc, p_wff1T + (size_t)l * FFc * Dc, Dc,
            bff1 + l * FFc, (const float*)0, p_ff16, FFc, Dc, 1.0f, 128, 128,
            (float*)0, (float*)0);

        // FF2 + residual
        hgemm<EPI_ADD, 0, float><<<dim3(Dc / 128, ROWSc / 128), 128, HG_SMEM>>>(
            p_ff16, FFc, p_wff2T + (size_t)l * Dc * FFc, FFc,
            bff2 + l * Dc, h, h, Dc, FFc, 1.0f, 128, 128, (float*)0, (float*)0);
    }
}

// round 11
// speedup vs baseline: 1.1560x; 1.1560x over previous
#include <cuda_runtime.h>
#include <cuda_fp16.h>
#include <math.h>
#include <stdint.h>

// ---------------------------------------------------------------------------
// SpatioTemporalPerformerEncoder — R11: 256-thread CTAs, 64x32 warp tiles,
// 2 CTAs/SM (4 warps/SMSP) — attack warp starvation
// ---------------------------------------------------------------------------

#define Bc     2
#define Hc     8
#define Nc     4096
#define Dc     512
#define DHc    64
#define Mc     256
#define FFc    2048
#define DEPTHc 4
#define ROWSc  8192
#define BHc    16
#define QKVW   1536

#define DN_CONST    0.35355339059327373f
#define DIAG_SCALE  0.0625f
#define RATIO_CONST 0.0625f
#define EPSK        1e-4f
#define LNEPS       1e-5f

#define HG_SMEM 61440   // 3 stages x (10240 A + 10240 B)

// ------------------------- scratch (device globals) ------------------------
__device__ __half g_ln16 [(size_t)ROWSc * Dc];
__device__ __half g_qkv16[(size_t)ROWSc * QKVW];
__device__ __half g_ff16 [(size_t)ROWSc * FFc];
__device__ __half g_att16[(size_t)ROWSc * Dc];
__device__ float  g_qp   [(size_t)BHc * Nc * Mc];
__device__ float  g_kp   [(size_t)BHc * Nc * Mc];
__device__ __half g_qp16 [(size_t)BHc * Nc * Mc];
__device__ __half g_kpT  [(size_t)BHc * Mc * Nc];
__device__ __half g_vT   [(size_t)BHc * 128 * Nc];   // rows 64..127 zero
__device__ float  g_ctxF [(size_t)BHc * 128 * Mc];
__device__ __half g_ctxT [(size_t)BHc * 128 * Mc];
__device__ float  g_ksum [BHc * Mc];
__device__ float  g_qdiag[BHc * Nc];
__device__ float  g_kdiag[BHc * Nc];
__device__ float  g_hmax [BHc];
__device__ float  g_dinv [BHc * Nc];
__device__ __half g_wqkvT[(size_t)DEPTHc * QKVW * Dc];
__device__ __half g_woT  [(size_t)DEPTHc * Dc * Dc];
__device__ __half g_wff1T[(size_t)DEPTHc * FFc * Dc];
__device__ __half g_wff2T[(size_t)DEPTHc * Dc * FFc];
__device__ __half g_projh[(size_t)DEPTHc * Mc * DHc];

// ------------------------------ helpers ------------------------------------
__device__ __forceinline__ uint32_t smem_to_u32(const void* p) {
    uint32_t a;
    asm("{ .reg .u64 t; cvta.to.shared.u64 t, %1; cvt.u32.u64 %0, t; }"
        : "=r"(a) : "l"(p));
    return a;
}
__device__ __forceinline__ uint32_t f2h2(float a, float b) {
    __half2 h = __floats2half2_rn(a, b);
    return *(uint32_t*)&h;
}
__device__ __forceinline__ void cp16(uint32_t dst, const void* src) {
    asm volatile("cp.async.cg.shared.global [%0], [%1], 16;"
                 :: "r"(dst), "l"(src));
}
#define CP_COMMIT() asm volatile("cp.async.commit_group;")
#define CP_WAIT(n)  asm volatile("cp.async.wait_group %0;" :: "n"(n))

__device__ __forceinline__ void ldsm4(uint32_t& r0, uint32_t& r1, uint32_t& r2,
                                      uint32_t& r3, uint32_t a) {
    asm volatile("ldmatrix.sync.aligned.m8n8.x4.shared.b16 {%0,%1,%2,%3}, [%4];"
                 : "=r"(r0), "=r"(r1), "=r"(r2), "=r"(r3) : "r"(a));
}
__device__ __forceinline__ void mma_f16(float c[4], const uint32_t a[4],
                                        const uint32_t b[2]) {
    asm volatile(
        "mma.sync.aligned.m16n8k16.row.col.f32.f16.f16.f32 "
        "{%0,%1,%2,%3}, {%4,%5,%6,%7}, {%8,%9}, {%0,%1,%2,%3};"
        : "+f"(c[0]), "+f"(c[1]), "+f"(c[2]), "+f"(c[3])
        : "r"(a[0]), "r"(a[1]), "r"(a[2]), "r"(a[3]), "r"(b[0]), "r"(b[1]));
}
__device__ __forceinline__ void atomicMaxF(float* a, float v) {
    if (v >= 0.0f) atomicMax((int*)a, __float_as_int(v));
    else atomicMin((unsigned int*)a, __float_as_uint(v));
}

// ------------------------- fp16 tensor-core GEMM ---------------------------
// C = scale*(A[M,K]h @ B[N,K]h^T) + epilogue. BM=BN=128, BK=32, 256 threads
// (8 warps 2x4), warp tile 64x32, 3-stage cp.async pipeline, 2 CTAs/SM.
// BHM 0: plain. 2: ctx (per-bh, K-split via blockIdx.y, fp32 atomic out).
// 3: attnout (per-bh, dinv row scale via R, head-merged out).
// 4: merged dd q/k (z<16: q->C, z>=16: k->C2 + fused global-max into hmaxp).
#define EPI_NONE 0
#define EPI_GELU 1
#define EPI_ADD  2
#define EPI_DINV 3

template <int EPI, int BHM, typename OutT>
__global__ __launch_bounds__(256, 2)
void hgemm(const __half* __restrict__ A, int lda,
           const __half* __restrict__ Bh, int ldb,
           const float* __restrict__ bias, const float* __restrict__ R,
           OutT* __restrict__ C, int ldc, int K, float scale,
           int mvalid, int nvalid, float* __restrict__ C2,
           float* __restrict__ hmaxp) {
    extern __shared__ __align__(16) char smem_dyn[];
    uint32_t sBase = smem_to_u32(smem_dyn);

    int m0, n0;
    int isk = 0;
    if (BHM == 2) {
        int z = blockIdx.z;
        A += (size_t)z * 128 * lda + (size_t)blockIdx.y * K;
        Bh += (size_t)z * Mc * ldb + (size_t)blockIdx.y * K;
        C += (size_t)z * 128 * ldc;
        m0 = 0;
        n0 = blockIdx.x * 128;
    } else {
        if (BHM == 4) {
            int z = blockIdx.z;
            isk = z >> 4;
            int bh = z & 15;
            A += (size_t)(bh >> 3) * Nc * lda + (size_t)(bh & 7) * DHc +
                 (size_t)isk * Dc;
            float* Cb = isk ? C2 : (float*)C;
            C = (OutT*)(Cb + (size_t)bh * Nc * ldc);
        }
        if (BHM == 3) {
            int z = blockIdx.z;
            A += (size_t)z * Nc * lda;
            Bh += (size_t)z * 128 * ldb;
            C += (size_t)(z >> 3) * Nc * Dc + (size_t)(z & 7) * DHc;
            R += (size_t)z * Nc;
        }
        m0 = blockIdx.y * 128;
        n0 = blockIdx.x * 128;
    }

    int tid = threadIdx.x, lane = tid & 31, warp = tid >> 5;
    int wm = warp >> 2, wn = warp & 3;      // 2 x 4 warps, 64x32 tiles

    int rowC = tid >> 2, cA = (tid & 3) * 8;     // 64 rows/pass, 2 passes
    uint32_t sOff = ((uint32_t)rowC * 40 + cA) * 2;
    uint32_t fOff = (((lane & 15) * 40) + (lane >> 4) * 8) * 2;

    float c[4][4][4];
#pragma unroll
    for (int i = 0; i < 4; i++)
#pragma unroll
        for (int j = 0; j < 4; j++)
#pragma unroll
            for (int l = 0; l < 4; l++) c[i][j][l] = 0.0f;

#define ISSUE(t, buf)                                                         \
    {                                                                         \
        int k0 = (t) * 32;                                                    \
        _Pragma("unroll")                                                     \
        for (int p = 0; p < 2; p++) {                                         \
            cp16(sBase + (buf) * 10240 + sOff + p * 5120,                     \
                 A + (size_t)(m0 + rowC + p * 64) * lda + k0 + cA);           \
            cp16(sBase + 30720 + (buf) * 10240 + sOff + p * 5120,             \
                 Bh + (size_t)(n0 + rowC + p * 64) * ldb + k0 + cA);          \
        }                                                                     \
        CP_COMMIT();                                                          \
    }

    int T = K >> 5;                 // all call sites have K >= 64 (T >= 2)
    ISSUE(0, 0)
    ISSUE(1, 1)
    int buf = 0;
    for (int t = 0; t < T; t++) {
        if (t == T - 1) { CP_WAIT(0); } else { CP_WAIT(1); }
        __syncthreads();

        uint32_t aTile = sBase + buf * 10240;
        uint32_t bTile = sBase + 30720 + buf * 10240;
#pragma unroll
        for (int kk = 0; kk < 2; kk++) {
            int k16 = kk * 16;
            uint32_t af[4][4], bf[4][2];
#pragma unroll
            for (int mi = 0; mi < 4; mi++)
                ldsm4(af[mi][0], af[mi][1], af[mi][2], af[mi][3],
                      aTile + ((wm * 64 + mi * 16) * 40 + k16) * 2 + fOff);
#pragma unroll
            for (int p = 0; p < 2; p++) {
                uint32_t r0, r1, r2, r3;
                ldsm4(r0, r1, r2, r3,
                      bTile + ((wn * 32 + p * 16) * 40 + k16) * 2 + fOff);
                bf[2 * p][0] = r0; bf[2 * p][1] = r2;
                bf[2 * p + 1][0] = r1; bf[2 * p + 1][1] = r3;
            }
#pragma unroll
            for (int mi = 0; mi < 4; mi++)
#pragma unroll
                for (int ni = 0; ni < 4; ni++)
                    mma_f16(c[mi][ni], af[mi], bf[ni]);
        }
        if (t + 2 < T) {
            int nb = buf + 2; if (nb >= 3) nb -= 3;
            ISSUE(t + 2, nb)
        }
        buf = (buf + 1 == 3) ? 0 : buf + 1;
    }
#undef ISSUE

    // epilogue
    int g = lane >> 2, tig = lane & 3;
    float tm = -1e30f;
#pragma unroll
    for (int mi = 0; mi < 4; mi++) {
#pragma unroll
        for (int ni = 0; ni < 4; ni++) {
            int rl = wm * 64 + mi * 16 + g;
            int cl = wn * 32 + ni * 8 + 2 * tig;
            if (cl >= nvalid) continue;
            int col = n0 + cl;
#pragma unroll
            for (int half = 0; half < 2; half++) {
                int rll = rl + half * 8;
                if (rll >= mvalid) continue;
                int r = m0 + rll;
                float v0 = c[mi][ni][half * 2 + 0] * scale;
                float v1 = c[mi][ni][half * 2 + 1] * scale;
                if (BHM == 4) tm = fmaxf(tm, fmaxf(v0, v1));
                if (bias) { v0 += bias[col]; v1 += bias[col + 1]; }
                if (EPI == EPI_GELU) {
                    v0 = 0.5f * v0 * (1.0f + erff(v0 * 0.70710678118654752f));
                    v1 = 0.5f * v1 * (1.0f + erff(v1 * 0.70710678118654752f));
                }
                if (EPI == EPI_ADD) {
                    v0 += R[(size_t)r * ldc + col];
                    v1 += R[(size_t)r * ldc + col + 1];
                }
                if (EPI == EPI_DINV) {
                    float di = R[r];
                    v0 *= di; v1 *= di;
                }
                if (BHM == 2) {
                    atomicAdd(&((float*)C)[(size_t)r * ldc + col], v0);
                    atomicAdd(&((float*)C)[(size_t)r * ldc + col + 1], v1);
                } else if (sizeof(OutT) == 2) {
                    __half2 hv = __floats2half2_rn(v0, v1);
                    *(__half2*)&((__half*)C)[(size_t)r * ldc + col] = hv;
                } else {
                    float2 o = {v0, v1};
                    *(float2*)&((float*)C)[(size_t)r * ldc + col] = o;
                }
            }
        }
    }
    if (BHM == 4 && isk) {
#pragma unroll
        for (int o = 16; o > 0; o >>= 1)
            tm = fmaxf(tm, __shfl_xor_sync(0xffffffffu, tm, o));
        if (lane == 0) atomicMaxF(&hmaxp[blockIdx.z & 15], tm);
    }
}

// --------------- batched weight transpose + convert to fp16 ----------------
__global__ __launch_bounds__(256)
void transpose_all(const float* __restrict__ Wqkv, const float* __restrict__ Wo,
                   const float* __restrict__ Wff1, const float* __restrict__ Wff2,
                   const float* __restrict__ proj,
                   __half* __restrict__ qkvT, __half* __restrict__ woT,
                   __half* __restrict__ ff1T, __half* __restrict__ ff2T,
                   __half* __restrict__ projh) {
    __shared__ float tbuf[32][33];
    int z = blockIdx.z;
    if (z >= 16) {
        int l = z - 16;
        int idx = (blockIdx.y * gridDim.x + blockIdx.x) * 256 + threadIdx.x;
        if (idx < Mc * DHc)
            projh[(size_t)l * Mc * DHc + idx] =
                __float2half(proj[(size_t)l * Mc * DHc + idx]);
        return;
    }
    int type = z & 3, l = z >> 2;
    int K, N;
    const float* in;
    __half* out;
    if (type == 0)      { K = Dc;  N = QKVW; in = Wqkv + (size_t)l * Dc * QKVW; out = qkvT + (size_t)l * QKVW * Dc; }
    else if (type == 1) { K = Dc;  N = Dc;   in = Wo   + (size_t)l * Dc * Dc;   out = woT  + (size_t)l * Dc * Dc; }
    else if (type == 2) { K = Dc;  N = FFc;  in = Wff1 + (size_t)l * Dc * FFc;  out = ff1T + (size_t)l * FFc * Dc; }
    else                { K = FFc; N = Dc;   in = Wff2 + (size_t)l * FFc * Dc;  out = ff2T + (size_t)l * Dc * FFc; }

    int nx = blockIdx.x * 32, kx = blockIdx.y * 32;
    if (nx >= N || kx >= K) return;
    int tx = threadIdx.x & 31, ty = threadIdx.x >> 5;
#pragma unroll
    for (int i = 0; i < 4; i++)
        tbuf[ty + i * 8][tx] = in[(size_t)(kx + ty + i * 8) * N + nx + tx];
    __syncthreads();
#pragma unroll
    for (int i = 0; i < 4; i++)
        out[(size_t)(nx + ty + i * 8) * K + kx + tx] =
            __float2half(tbuf[tx][ty + i * 8]);
}

// ------------------------------ copy x -> h --------------------------------
__global__ void copy_kernel(const float* __restrict__ x, float* __restrict__ h) {
    size_t i = (size_t)blockIdx.x * 256 + threadIdx.x;
    h[i] = x[i];
}

// ------------------- layernorm: warp per row (fp16 out) --------------------
__global__ __launch_bounds__(256)
void ln_kernel(const float* __restrict__ x, const float* __restrict__ g,
               const float* __restrict__ b, __half* __restrict__ out) {
    int w = threadIdx.x >> 5, lane = threadIdx.x & 31;
    int row = blockIdx.x * 8 + w;
    const float4* xr = (const float4*)(x + (size_t)row * Dc);
    float4 v[4];
    float s = 0.0f;
#pragma unroll
    for (int i = 0; i < 4; i++) {
        v[i] = xr[lane + i * 32];
        s += (v[i].x + v[i].y) + (v[i].z + v[i].w);
    }
#pragma unroll
    for (int o = 16; o > 0; o >>= 1) s += __shfl_xor_sync(0xffffffffu, s, o);
    float mu = s * (1.0f / Dc);
    float var = 0.0f;
#pragma unroll
    for (int i = 0; i < 4; i++) {
        v[i].x -= mu; v[i].y -= mu; v[i].z -= mu; v[i].w -= mu;
        var += v[i].x * v[i].x + v[i].y * v[i].y +
               v[i].z * v[i].z + v[i].w * v[i].w;
    }
#pragma unroll
    for (int o = 16; o > 0; o >>= 1) var += __shfl_xor_sync(0xffffffffu, var, o);
    float rs = rsqrtf(var * (1.0f / Dc) + LNEPS);
    const float4* gp = (const float4*)g;
    const float4* bp = (const float4*)b;
    __half* orow = out + (size_t)row * Dc;
#pragma unroll
    for (int i = 0; i < 4; i++) {
        float4 gg = gp[lane + i * 32], bb = bp[lane + i * 32];
        uint2 o2;
        o2.x = f2h2(v[i].x * rs * gg.x + bb.x, v[i].y * rs * gg.y + bb.y);
        o2.y = f2h2(v[i].z * rs * gg.z + bb.z, v[i].w * rs * gg.w + bb.w);
        *(uint2*)&orow[(lane + i * 32) * 4] = o2;
    }
}

// ------------------- diag: per-(bh,row) 0.5*dn^2*|q|^2, |k|^2 --------------
__global__ __launch_bounds__(256)
void diag_kernel(const __half* __restrict__ qkv, float* __restrict__ qdiag,
                 float* __restrict__ kdiag) {
    int row = blockIdx.x;
    int w = threadIdx.x >> 5, lane = threadIdx.x & 31;
    const __half* base = qkv + (size_t)row * QKVW + w * DHc;
    float q0 = __half2float(base[lane]), q1 = __half2float(base[lane + 32]);
    float k0 = __half2float(base[Dc + lane]),
          k1 = __half2float(base[Dc + lane + 32]);
    float sq = q0 * q0 + q1 * q1;
    float sk = k0 * k0 + k1 * k1;
#pragma unroll
    for (int o = 16; o > 0; o >>= 1) {
        sq += __shfl_down_sync(0xffffffffu, sq, o);
        sk += __shfl_down_sync(0xffffffffu, sk, o);
    }
    if (lane == 0) {
        int bh = (row >> 12) * Hc + w;
        int n = row & (Nc - 1);
        qdiag[(size_t)bh * Nc + n] = sq * DIAG_SCALE;
        kdiag[(size_t)bh * Nc + n] = sk * DIAG_SCALE;
    }
}

// ---------- q features: per-row max + exp, fp32 dd -> fp16 features --------
__global__ __launch_bounds__(256)
void featq_finish(const float* __restrict__ qp, const float* __restrict__ qdiag,
                  __half* __restrict__ qp16) {
    int w = threadIdx.x >> 5, lane = threadIdx.x & 31;
    int rr = blockIdx.x * 8 + w;
    const float* p = qp + (size_t)rr * Mc + lane * 8;
    float4 v0 = *(const float4*)p;
    float4 v1 = *(const float4*)(p + 4);
    float mx = fmaxf(fmaxf(fmaxf(v0.x, v0.y), fmaxf(v0.z, v0.w)),
                     fmaxf(fmaxf(v1.x, v1.y), fmaxf(v1.z, v1.w)));
#pragma unroll
    for (int o = 16; o > 0; o >>= 1)
        mx = fmaxf(mx, __shfl_xor_sync(0xffffffffu, mx, o));
    float sub = qdiag[rr] + mx;
    uint4 o;
    o.x = f2h2(RATIO_CONST * (expf(v0.x - sub) + EPSK),
               RATIO_CONST * (expf(v0.y - sub) + EPSK));
    o.y = f2h2(RATIO_CONST * (expf(v0.z - sub) + EPSK),
               RATIO_CONST * (expf(v0.w - sub) + EPSK));
    o.z = f2h2(RATIO_CONST * (expf(v1.x - sub) + EPSK),
               RATIO_CONST * (expf(v1.y - sub) + EPSK));
    o.w = f2h2(RATIO_CONST * (expf(v1.z - sub) + EPSK),
               RATIO_CONST * (expf(v1.w - sub) + EPSK));
    *(uint4*)&qp16[(size_t)rr * Mc + lane * 8] = o;
}

// -------- k features: exp + transpose -> kpT16 [bh][m][n] ------------------
__global__ __launch_bounds__(256)
void featkT(const float* __restrict__ kp, const float* __restrict__ kdiag,
            const float* __restrict__ hmax, __half* __restrict__ kpT) {
    __shared__ __half tile[32][33];
    int bh = blockIdx.z;
    int n0 = blockIdx.x * 32, m0 = blockIdx.y * 32;
    float hm = hmax[bh];
    int tx = threadIdx.x & 31, ty = threadIdx.x >> 5;
#pragma unroll
    for (int i = 0; i < 4; i++) {
        int n = n0 + ty + i * 8;
        float sub = kdiag[(size_t)bh * Nc + n] + hm;
        float v = kp[((size_t)bh * Nc + n) * Mc + m0 + tx];
        tile[ty + i * 8][tx] = __float2half(RATIO_CONST * (expf(v - sub) + EPSK));
    }
    __syncthreads();
#pragma unroll
    for (int i = 0; i < 4; i++) {
        int m = m0 + ty + i * 8;
        kpT[((size_t)bh * Mc + m) * Nc + n0 + tx] = tile[tx][ty + i * 8];
    }
}

// -------------------- v transpose: vT16 [bh][d][n] -------------------------
__global__ __launch_bounds__(256)
void vtrans(const __half* __restrict__ qkv, __half* __restrict__ vT) {
    __shared__ __half tile[32][33];
    int z = blockIdx.z;
    int b = z >> 3, h = z & 7;
    int n0 = blockIdx.x * 32, d0 = blockIdx.y * 32;
    int tx = threadIdx.x & 31, ty = threadIdx.x >> 5;
#pragma unroll
    for (int i = 0; i < 4; i++)
        tile[ty + i * 8][tx] =
            qkv[((size_t)(b * Nc + n0 + ty + i * 8)) * QKVW + 2 * Dc + h * DHc +
                d0 + tx];
    __syncthreads();
#pragma unroll
    for (int i = 0; i < 4; i++)
        vT[((size_t)z * 128 + d0 + ty + i * 8) * Nc + n0 + tx] =
            tile[tx][ty + i * 8];
}

// --------------------------- ksum from kpT ---------------------------------
__global__ __launch_bounds__(256)
void ksum_kernel(const __half* __restrict__ kpT, float* __restrict__ ksum) {
    int bh = blockIdx.y;
    int m = blockIdx.x * 8 + (threadIdx.x >> 5);
    int lane = threadIdx.x & 31;
    const uint4* row = (const uint4*)(kpT + ((size_t)bh * Mc + m) * Nc);
    float s = 0.0f;
    for (int i = lane; i < Nc / 8; i += 32) {
        uint4 u = row[i];
        __half2* hp = (__half2*)&u;
#pragma unroll
        for (int j = 0; j < 4; j++) {
            float2 f = __half22float2(hp[j]);
            s += f.x + f.y;
        }
    }
#pragma unroll
    for (int o = 16; o > 0; o >>= 1) s += __shfl_down_sync(0xffffffffu, s, o);
    if (lane == 0) ksum[bh * Mc + m] = s;
}

// ------------------ zero ctxF + init hmax (-inf) ---------------------------
__global__ void initbuf(float* __restrict__ ctxF, float* __restrict__ hmax) {
    size_t i = (size_t)blockIdx.x * 256 + threadIdx.x;
    ctxF[i] = 0.0f;
    if (i < BHc) hmax[i] = -1e30f;
}

// ------------------------- convert ctxF -> ctxT16 --------------------------
__global__ void cvtctx(const float* __restrict__ ctxF, __half* __restrict__ ctxT) {
    size_t i = (size_t)blockIdx.x * 256 + threadIdx.x;
    ctxT[i] = __float2half(ctxF[i]);
}

// ------------------------------- d_inv -------------------------------------
__global__ __launch_bounds__(256)
void dinv_kernel(const __half* __restrict__ qp16, const float* __restrict__ ksum,
                 float* __restrict__ dinv) {
    int w = threadIdx.x >> 5, lane = threadIdx.x & 31;
    int rr = blockIdx.x * 8 + w;
    int bh = rr >> 12;
    uint4 u = ((const uint4*)(qp16 + (size_t)rr * Mc))[lane];
    const float* ks = ksum + bh * Mc + lane * 8;
    __half2* hp = (__half2*)&u;
    float s = 0.0f;
#pragma unroll
    for (int j = 0; j < 4; j++) {
        float2 f = __half22float2(hp[j]);
        s += f.x * ks[2 * j] + f.y * ks[2 * j + 1];
    }
#pragma unroll
    for (int o = 16; o > 0; o >>= 1) s += __shfl_down_sync(0xffffffffu, s, o);
    if (lane == 0) dinv[rr] = 1.0f / s;
}

// ------------------------------- launch ------------------------------------
extern "C" void kernel_launch(void* const* d_in, const int* in_sizes, int n_in,
                              void* d_out, int out_size) {
    (void)in_sizes; (void)n_in; (void)out_size;
    const float* x    = (const float*)d_in[0];
    const float* proj = (const float*)d_in[1];
    const float* ln1g = (const float*)d_in[2];
    const float* ln1b = (const float*)d_in[3];
    const float* Wqkv = (const float*)d_in[4];
    const float* bqkv = (const float*)d_in[5];
    const float* Wo   = (const float*)d_in[6];
    const float* bo   = (const float*)d_in[7];
    const float* ln2g = (const float*)d_in[8];
    const float* ln2b = (const float*)d_in[9];
    const float* Wff1 = (const float*)d_in[10];
    const float* bff1 = (const float*)d_in[11];
    const float* Wff2 = (const float*)d_in[12];
    const float* bff2 = (const float*)d_in[13];
    float* h = (float*)d_out;

    static float *p_qp = 0, *p_kp = 0, *p_ctxF = 0, *p_ksum = 0, *p_qdiag = 0,
                 *p_kdiag = 0, *p_hmax = 0, *p_dinv = 0;
    static __half *p_ln16 = 0, *p_qkv16 = 0, *p_ff16 = 0, *p_att16 = 0,
                  *p_qp16 = 0, *p_kpT = 0, *p_vT = 0, *p_ctxT = 0,
                  *p_wqkvT = 0, *p_woT = 0, *p_wff1T = 0, *p_wff2T = 0,
                  *p_projh = 0;
    if (!p_qp) {
        cudaGetSymbolAddress((void**)&p_qp, g_qp);
        cudaGetSymbolAddress((void**)&p_kp, g_kp);
        cudaGetSymbolAddress((void**)&p_ctxF, g_ctxF);
        cudaGetSymbolAddress((void**)&p_ksum, g_ksum);
        cudaGetSymbolAddress((void**)&p_qdiag, g_qdiag);
        cudaGetSymbolAddress((void**)&p_kdiag, g_kdiag);
        cudaGetSymbolAddress((void**)&p_hmax, g_hmax);
        cudaGetSymbolAddress((void**)&p_dinv, g_dinv);
        cudaGetSymbolAddress((void**)&p_ln16, g_ln16);
        cudaGetSymbolAddress((void**)&p_qkv16, g_qkv16);
        cudaGetSymbolAddress((void**)&p_ff16, g_ff16);
        cudaGetSymbolAddress((void**)&p_att16, g_att16);
        cudaGetSymbolAddress((void**)&p_qp16, g_qp16);
        cudaGetSymbolAddress((void**)&p_kpT, g_kpT);
        cudaGetSymbolAddress((void**)&p_vT, g_vT);
        cudaGetSymbolAddress((void**)&p_ctxT, g_ctxT);
        cudaGetSymbolAddress((void**)&p_wqkvT, g_wqkvT);
        cudaGetSymbolAddress((void**)&p_woT, g_woT);
        cudaGetSymbolAddress((void**)&p_wff1T, g_wff1T);
        cudaGetSymbolAddress((void**)&p_wff2T, g_wff2T);
        cudaGetSymbolAddress((void**)&p_projh, g_projh);
        cudaFuncSetAttribute(hgemm<EPI_NONE, 0, __half>,
                             cudaFuncAttributeMaxDynamicSharedMemorySize, HG_SMEM);
        cudaFuncSetAttribute(hgemm<EPI_NONE, 4, float>,
                             cudaFuncAttributeMaxDynamicSharedMemorySize, HG_SMEM);
        cudaFuncSetAttribute(hgemm<EPI_NONE, 2, float>,
                             cudaFuncAttributeMaxDynamicSharedMemorySize, HG_SMEM);
        cudaFuncSetAttribute(hgemm<EPI_DINV, 3, __half>,
                             cudaFuncAttributeMaxDynamicSharedMemorySize, HG_SMEM);
        cudaFuncSetAttribute(hgemm<EPI_ADD, 0, float>,
                             cudaFuncAttributeMaxDynamicSharedMemorySize, HG_SMEM);
        cudaFuncSetAttribute(hgemm<EPI_GELU, 0, __half>,
                             cudaFuncAttributeMaxDynamicSharedMemorySize, HG_SMEM);
    }

    // launch 0: weight transposes + fp16 conversion
    transpose_all<<<dim3(64, 64, 20), 256>>>(Wqkv, Wo, Wff1, Wff2, proj,
                                             p_wqkvT, p_woT, p_wff1T, p_wff2T,
                                             p_projh);
    // launch 1
    copy_kernel<<<(ROWSc * Dc) / 256, 256>>>(x, h);

    for (int l = 0; l < DEPTHc; l++) {
        const __half* pjh = p_projh + (size_t)l * Mc * DHc;

        ln_kernel<<<ROWSc / 8, 256>>>(h, ln1g + l * Dc, ln1b + l * Dc, p_ln16);

        // launch 3 (profiled): QKV
        hgemm<EPI_NONE, 0, __half><<<dim3(QKVW / 128, ROWSc / 128), 256, HG_SMEM>>>(
            p_ln16, Dc, p_wqkvT + (size_t)l * QKVW * Dc, Dc,
            bqkv + l * QKVW, (const float*)0, p_qkv16, QKVW, Dc, 1.0f, 128, 128,
            (float*)0, (float*)0);

        initbuf<<<(BHc * 128 * Mc) / 256, 256>>>(p_ctxF, p_hmax);

        // merged dd_q/dd_k (z<16: q -> qp, z>=16: k -> kp + fused hmax)
        hgemm<EPI_NONE, 4, float><<<dim3(Mc / 128, Nc / 128, 2 * BHc), 256, HG_SMEM>>>(
            p_qkv16, QKVW, pjh, DHc, (const float*)0, (const float*)0,
            p_qp, Mc, DHc, DN_CONST, 128, 128, p_kp, p_hmax);

        diag_kernel<<<ROWSc, 256>>>(p_qkv16, p_qdiag, p_kdiag);
        featq_finish<<<(BHc * Nc) / 8, 256>>>(p_qp, p_qdiag, p_qp16);
        featkT<<<dim3(Nc / 32, Mc / 32, BHc), 256>>>(p_kp, p_kdiag, p_hmax, p_kpT);
        vtrans<<<dim3(Nc / 32, 2, BHc), 256>>>(p_qkv16, p_vT);
        ksum_kernel<<<dim3(Mc / 8, BHc), 256>>>(p_kpT, p_ksum);

        // ctx^T = vT @ kpT^T, split-K=8, fp32 atomic accumulate
        hgemm<EPI_NONE, 2, float><<<dim3(Mc / 128, 8, BHc), 256, HG_SMEM>>>(
            p_vT, Nc, p_kpT, Nc, (const float*)0, (const float*)0,
            p_ctxF, Mc, Nc / 8, 1.0f, 64, 128, (float*)0, (float*)0);
        cvtctx<<<(BHc * 128 * Mc) / 256, 256>>>(p_ctxF, p_ctxT);

        dinv_kernel<<<(BHc * Nc) / 8, 256>>>(p_qp16, p_ksum, p_dinv);

        // attnout = (qp16 @ ctxT^T) * dinv, head-merged fp16
        hgemm<EPI_DINV, 3, __half><<<dim3(1, Nc / 128, BHc), 256, HG_SMEM>>>(
            p_qp16, Mc, p_ctxT, Mc, (const float*)0, p_dinv,
            p_att16, Dc, Mc, 1.0f, 128, 64, (float*)0, (float*)0);

        // Wo + residual
        hgemm<EPI_ADD, 0, float><<<dim3(Dc / 128, ROWSc / 128), 256, HG_SMEM>>>(
            p_att16, Dc, p_woT + (size_t)l * Dc * Dc, Dc,
            bo + l * Dc, h, h, Dc, Dc, 1.0f, 128, 128, (float*)0, (float*)0);

        ln_kernel<<<ROWSc / 8, 256>>>(h, ln2g + l * Dc, ln2b + l * Dc, p_ln16);

        // FF1 + gelu
        hgemm<EPI_GELU, 0, __half><<<dim3(FFc / 128, ROWSc / 128), 256, HG_SMEM>>>(
            p_ln16, Dc, p_wff1T + (size_t)l * FFc * Dc, Dc,
            bff1 + l * FFc, (const float*)0, p_ff16, FFc, Dc, 1.0f, 128, 128,
            (float*)0, (float*)0);

        // FF2 + residual
        hgemm<EPI_ADD, 0, float><<<dim3(Dc / 128, ROWSc / 128), 256, HG_SMEM>>>(
            p_ff16, FFc, p_wff2T + (size_t)l * Dc * FFc, FFc,
            bff2 + l * Dc, h, h, Dc, FFc, 1.0f, 128, 128, (float*)0, (float*)0);
    }
}

// round 13
// speedup vs baseline: 1.2465x; 1.0783x over previous
#include <cuda_runtime.h>
#include <cuda_fp16.h>
#include <math.h>
#include <stdint.h>

// ---------------------------------------------------------------------------
// SpatioTemporalPerformerEncoder — R13: shaped warp tiles (MT/NT), slab split-K
// (R12 resubmit — previous round was an infra failure, source never ran)
// ---------------------------------------------------------------------------

#define Bc     2
#define Hc     8
#define Nc     4096
#define Dc     512
#define DHc    64
#define Mc     256
#define FFc    2048
#define DEPTHc 4
#define ROWSc  8192
#define BHc    16
#define QKVW   1536

#define DN_CONST    0.35355339059327373f
#define DIAG_SCALE  0.0625f
#define RATIO_CONST 0.0625f
#define EPSK        1e-4f
#define LNEPS       1e-5f

#define HG_SMEM 61440   // 3 stages x (10240 A + 10240 B)
#define NSPLIT  8

// ------------------------- scratch (device globals) ------------------------
__device__ __half g_ln16 [(size_t)ROWSc * Dc];
__device__ __half g_qkv16[(size_t)ROWSc * QKVW];
__device__ __half g_ff16 [(size_t)ROWSc * FFc];
__device__ __half g_att16[(size_t)ROWSc * Dc];
__device__ float  g_qp   [(size_t)BHc * Nc * Mc];
__device__ float  g_kp   [(size_t)BHc * Nc * Mc];
__device__ __half g_qp16 [(size_t)BHc * Nc * Mc];
__device__ __half g_kpT  [(size_t)BHc * Mc * Nc];
__device__ __half g_vT   [(size_t)BHc * 64 * Nc];          // v^T, 64 rows
__device__ float  g_ctxF [(size_t)NSPLIT * BHc * 64 * Mc]; // split-K slabs
__device__ __half g_ctxT [(size_t)BHc * 64 * Mc];
__device__ float  g_ksum [BHc * Mc];
__device__ float  g_qdiag[BHc * Nc];
__device__ float  g_kdiag[BHc * Nc];
__device__ float  g_hmax [BHc];
__device__ float  g_dinv [BHc * Nc];
__device__ __half g_wqkvT[(size_t)DEPTHc * QKVW * Dc];
__device__ __half g_woT  [(size_t)DEPTHc * Dc * Dc];
__device__ __half g_wff1T[(size_t)DEPTHc * FFc * Dc];
__device__ __half g_wff2T[(size_t)DEPTHc * Dc * FFc];
__device__ __half g_projh[(size_t)DEPTHc * Mc * DHc];

// ------------------------------ helpers ------------------------------------
__device__ __forceinline__ uint32_t smem_to_u32(const void* p) {
    uint32_t a;
    asm("{ .reg .u64 t; cvta.to.shared.u64 t, %1; cvt.u32.u64 %0, t; }"
        : "=r"(a) : "l"(p));
    return a;
}
__device__ __forceinline__ uint32_t f2h2(float a, float b) {
    __half2 h = __floats2half2_rn(a, b);
    return *(uint32_t*)&h;
}
__device__ __forceinline__ void cp16(uint32_t dst, const void* src) {
    asm volatile("cp.async.cg.shared.global [%0], [%1], 16;"
                 :: "r"(dst), "l"(src));
}
#define CP_COMMIT() asm volatile("cp.async.commit_group;")
#define CP_WAIT(n)  asm volatile("cp.async.wait_group %0;" :: "n"(n))

__device__ __forceinline__ void ldsm4(uint32_t& r0, uint32_t& r1, uint32_t& r2,
                                      uint32_t& r3, uint32_t a) {
    asm volatile("ldmatrix.sync.aligned.m8n8.x4.shared.b16 {%0,%1,%2,%3}, [%4];"
                 : "=r"(r0), "=r"(r1), "=r"(r2), "=r"(r3) : "r"(a));
}
__device__ __forceinline__ void mma_f16(float c[4], const uint32_t a[4],
                                        const uint32_t b[2]) {
    asm volatile(
        "mma.sync.aligned.m16n8k16.row.col.f32.f16.f16.f32 "
        "{%0,%1,%2,%3}, {%4,%5,%6,%7}, {%8,%9}, {%0,%1,%2,%3};"
        : "+f"(c[0]), "+f"(c[1]), "+f"(c[2]), "+f"(c[3])
        : "r"(a[0]), "r"(a[1]), "r"(a[2]), "r"(a[3]), "r"(b[0]), "r"(b[1]));
}
__device__ __forceinline__ void atomicMaxF(float* a, float v) {
    if (v >= 0.0f) atomicMax((int*)a, __float_as_int(v));
    else atomicMin((unsigned int*)a, __float_as_uint(v));
}

// ------------------------- fp16 tensor-core GEMM ---------------------------
// C = scale*(A[M,K]h @ B[N,K]h^T) + epilogue. BK=32, 256 threads (8 warps 2x4),
// warp tile (MT*16)x(NT*16), BM=MT*32, BN=NT*64. 3-stage cp.async, 2 CTAs/SM.
// BHM 0: plain. 2: ctx (per-bh, split-K slab via blockIdx.y, fp32 slab out).
// 3: attnout (per-bh, dinv row scale via R, head-merged out).
// 4: merged dd q/k (z<16: q->C, z>=16: k->C2 + fused global-max into hmaxp).
#define EPI_NONE 0
#define EPI_GELU 1
#define EPI_ADD  2
#define EPI_DINV 3

template <int EPI, int BHM, typename OutT, int MT, int NT>
__global__ __launch_bounds__(256, 2)
void hgemm(const __half* __restrict__ A, int lda,
           const __half* __restrict__ Bh, int ldb,
           const float* __restrict__ bias, const float* __restrict__ R,
           OutT* __restrict__ C, int ldc, int K, float scale,
           int nvalid, float* __restrict__ C2, float* __restrict__ hmaxp) {
    extern __shared__ __align__(16) char smem_dyn[];
    uint32_t sBase = smem_to_u32(smem_dyn);

    const int BM = MT * 32, BN = NT * 64;
    int m0, n0;
    int isk = 0;
    if (BHM == 2) {
        int z = blockIdx.z, s = blockIdx.y;
        A += (size_t)z * BM * lda + (size_t)s * K;
        Bh += (size_t)z * Mc * ldb + (size_t)s * K;
        C += ((size_t)s * BHc + z) * BM * ldc;
        m0 = 0;
        n0 = blockIdx.x * BN;
    } else {
        if (BHM == 4) {
            int z = blockIdx.z;
            isk = z >> 4;
            int bh = z & 15;
            A += (size_t)(bh >> 3) * Nc * lda + (size_t)(bh & 7) * DHc +
                 (size_t)isk * Dc;
            float* Cb = isk ? C2 : (float*)C;
            C = (OutT*)(Cb + (size_t)bh * Nc * ldc);
        }
        if (BHM == 3) {
            int z = blockIdx.z;
            A += (size_t)z * Nc * lda;
            Bh += (size_t)z * 64 * ldb;
            C += (size_t)(z >> 3) * Nc * Dc + (size_t)(z & 7) * DHc;
            R += (size_t)z * Nc;
        }
        m0 = blockIdx.y * BM;
        n0 = blockIdx.x * BN;
    }

    int tid = threadIdx.x, lane = tid & 31, warp = tid >> 5;
    int wm = warp >> 2, wn = warp & 3;

    int rowC = tid >> 2, cA = (tid & 3) * 8;
    uint32_t sOff = ((uint32_t)rowC * 40 + cA) * 2;
    uint32_t fOff = (((lane & 15) * 40) + (lane >> 4) * 8) * 2;

    float c[MT][2 * NT][4];
#pragma unroll
    for (int i = 0; i < MT; i++)
#pragma unroll
        for (int j = 0; j < 2 * NT; j++)
#pragma unroll
            for (int l = 0; l < 4; l++) c[i][j][l] = 0.0f;

#define ISSUE(t, buf)                                                         \
    {                                                                         \
        int k0 = (t) * 32;                                                    \
        _Pragma("unroll")                                                     \
        for (int p = 0; p < MT / 2; p++)                                      \
            cp16(sBase + (buf) * 10240 + sOff + p * 5120,                     \
                 A + (size_t)(m0 + rowC + p * 64) * lda + k0 + cA);           \
        _Pragma("unroll")                                                     \
        for (int p = 0; p < NT; p++)                                          \
            cp16(sBase + 30720 + (buf) * 10240 + sOff + p * 5120,             \
                 Bh + (size_t)(n0 + rowC + p * 64) * ldb + k0 + cA);          \
        CP_COMMIT();                                                          \
    }

    int T = K >> 5;                 // all call sites have K >= 64 (T >= 2)
    ISSUE(0, 0)
    ISSUE(1, 1)
    int buf = 0;
    for (int t = 0; t < T; t++) {
        if (t == T - 1) { CP_WAIT(0); } else { CP_WAIT(1); }
        __syncthreads();

        uint32_t aTile = sBase + buf * 10240;
        uint32_t bTile = sBase + 30720 + buf * 10240;
#pragma unroll
        for (int kk = 0; kk < 2; kk++) {
            int k16 = kk * 16;
            uint32_t af[MT][4], bf[2 * NT][2];
#pragma unroll
            for (int mi = 0; mi < MT; mi++)
                ldsm4(af[mi][0], af[mi][1], af[mi][2], af[mi][3],
                      aTile + ((wm * MT * 16 + mi * 16) * 40 + k16) * 2 + fOff);
#pragma unroll
            for (int p = 0; p < NT; p++) {
                uint32_t r0, r1, r2, r3;
                ldsm4(r0, r1, r2, r3,
                      bTile + ((wn * NT * 16 + p * 16) * 40 + k16) * 2 + fOff);
                bf[2 * p][0] = r0; bf[2 * p][1] = r2;
                bf[2 * p + 1][0] = r1; bf[2 * p + 1][1] = r3;
            }
#pragma unroll
            for (int mi = 0; mi < MT; mi++)
#pragma unroll
                for (int ni = 0; ni < 2 * NT; ni++)
                    mma_f16(c[mi][ni], af[mi], bf[ni]);
        }
        if (t + 2 < T) {
            int nb = buf + 2; if (nb >= 3) nb -= 3;
            ISSUE(t + 2, nb)
        }
        buf = (buf + 1 == 3) ? 0 : buf + 1;
    }
#undef ISSUE

    // epilogue
    int g = lane >> 2, tig = lane & 3;
    float tm = -1e30f;
#pragma unroll
    for (int mi = 0; mi < MT; mi++) {
#pragma unroll
        for (int ni = 0; ni < 2 * NT; ni++) {
            int rl = wm * MT * 16 + mi * 16 + g;
            int cl = wn * NT * 16 + ni * 8 + 2 * tig;
            if (cl >= nvalid) continue;
            int col = n0 + cl;
#pragma unroll
            for (int half = 0; half < 2; half++) {
                int r = m0 + rl + half * 8;
                float v0 = c[mi][ni][half * 2 + 0] * scale;
                float v1 = c[mi][ni][half * 2 + 1] * scale;
                if (BHM == 4) tm = fmaxf(tm, fmaxf(v0, v1));
                if (bias) { v0 += bias[col]; v1 += bias[col + 1]; }
                if (EPI == EPI_GELU) {
                    v0 = 0.5f * v0 * (1.0f + erff(v0 * 0.70710678118654752f));
                    v1 = 0.5f * v1 * (1.0f + erff(v1 * 0.70710678118654752f));
                }
                if (EPI == EPI_ADD) {
                    v0 += R[(size_t)r * ldc + col];
                    v1 += R[(size_t)r * ldc + col + 1];
                }
                if (EPI == EPI_DINV) {
                    float di = R[r];
                    v0 *= di; v1 *= di;
                }
                if (sizeof(OutT) == 2) {
                    __half2 hv = __floats2half2_rn(v0, v1);
                    *(__half2*)&((__half*)C)[(size_t)r * ldc + col] = hv;
                } else {
                    float2 o = {v0, v1};
                    *(float2*)&((float*)C)[(size_t)r * ldc + col] = o;
                }
            }
        }
    }
    if (BHM == 4 && isk) {
#pragma unroll
        for (int o = 16; o > 0; o >>= 1)
            tm = fmaxf(tm, __shfl_xor_sync(0xffffffffu, tm, o));
        if (lane == 0) atomicMaxF(&hmaxp[blockIdx.z & 15], tm);
    }
}

// --------------- batched weight transpose + convert to fp16 ----------------
__global__ __launch_bounds__(256)
void transpose_all(const float* __restrict__ Wqkv, const float* __restrict__ Wo,
                   const float* __restrict__ Wff1, const float* __restrict__ Wff2,
                   const float* __restrict__ proj,
                   __half* __restrict__ qkvT, __half* __restrict__ woT,
                   __half* __restrict__ ff1T, __half* __restrict__ ff2T,
                   __half* __restrict__ projh) {
    __shared__ float tbuf[32][33];
    int z = blockIdx.z;
    if (z >= 16) {
        int l = z - 16;
        int idx = (blockIdx.y * gridDim.x + blockIdx.x) * 256 + threadIdx.x;
        if (idx < Mc * DHc)
            projh[(size_t)l * Mc * DHc + idx] =
                __float2half(proj[(size_t)l * Mc * DHc + idx]);
        return;
    }
    int type = z & 3, l = z >> 2;
    int K, N;
    const float* in;
    __half* out;
    if (type == 0)      { K = Dc;  N = QKVW; in = Wqkv + (size_t)l * Dc * QKVW; out = qkvT + (size_t)l * QKVW * Dc; }
    else if (type == 1) { K = Dc;  N = Dc;   in = Wo   + (size_t)l * Dc * Dc;   out = woT  + (size_t)l * Dc * Dc; }
    else if (type == 2) { K = Dc;  N = FFc;  in = Wff1 + (size_t)l * Dc * FFc;  out = ff1T + (size_t)l * FFc * Dc; }
    else                { K = FFc; N = Dc;   in = Wff2 + (size_t)l * FFc * Dc;  out = ff2T + (size_t)l * Dc * FFc; }

    int nx = blockIdx.x * 32, kx = blockIdx.y * 32;
    if (nx >= N || kx >= K) return;
    int tx = threadIdx.x & 31, ty = threadIdx.x >> 5;
#pragma unroll
    for (int i = 0; i < 4; i++)
        tbuf[ty + i * 8][tx] = in[(size_t)(kx + ty + i * 8) * N + nx + tx];
    __syncthreads();
#pragma unroll
    for (int i = 0; i < 4; i++)
        out[(size_t)(nx + ty + i * 8) * K + kx + tx] =
            __float2half(tbuf[tx][ty + i * 8]);
}

// ------------------------------ copy x -> h --------------------------------
__global__ void copy_kernel(const float* __restrict__ x, float* __restrict__ h) {
    size_t i = (size_t)blockIdx.x * 256 + threadIdx.x;
    h[i] = x[i];
}

// ------------------- layernorm: warp per row (fp16 out) --------------------
__global__ __launch_bounds__(256)
void ln_kernel(const float* __restrict__ x, const float* __restrict__ g,
               const float* __restrict__ b, __half* __restrict__ out) {
    int w = threadIdx.x >> 5, lane = threadIdx.x & 31;
    int row = blockIdx.x * 8 + w;
    const float4* xr = (const float4*)(x + (size_t)row * Dc);
    float4 v[4];
    float s = 0.0f;
#pragma unroll
    for (int i = 0; i < 4; i++) {
        v[i] = xr[lane + i * 32];
        s += (v[i].x + v[i].y) + (v[i].z + v[i].w);
    }
#pragma unroll
    for (int o = 16; o > 0; o >>= 1) s += __shfl_xor_sync(0xffffffffu, s, o);
    float mu = s * (1.0f / Dc);
    float var = 0.0f;
#pragma unroll
    for (int i = 0; i < 4; i++) {
        v[i].x -= mu; v[i].y -= mu; v[i].z -= mu; v[i].w -= mu;
        var += v[i].x * v[i].x + v[i].y * v[i].y +
               v[i].z * v[i].z + v[i].w * v[i].w;
    }
#pragma unroll
    for (int o = 16; o > 0; o >>= 1) var += __shfl_xor_sync(0xffffffffu, var, o);
    float rs = rsqrtf(var * (1.0f / Dc) + LNEPS);
    const float4* gp = (const float4*)g;
    const float4* bp = (const float4*)b;
    __half* orow = out + (size_t)row * Dc;
#pragma unroll
    for (int i = 0; i < 4; i++) {
        float4 gg = gp[lane + i * 32], bb = bp[lane + i * 32];
        uint2 o2;
        o2.x = f2h2(v[i].x * rs * gg.x + bb.x, v[i].y * rs * gg.y + bb.y);
        o2.y = f2h2(v[i].z * rs * gg.z + bb.z, v[i].w * rs * gg.w + bb.w);
        *(uint2*)&orow[(lane + i * 32) * 4] = o2;
    }
}

// ------------------- diag: per-(bh,row) 0.5*dn^2*|q|^2, |k|^2 --------------
__global__ __launch_bounds__(256)
void diag_kernel(const __half* __restrict__ qkv, float* __restrict__ qdiag,
                 float* __restrict__ kdiag) {
    int row = blockIdx.x;
    int w = threadIdx.x >> 5, lane = threadIdx.x & 31;
    const __half* base = qkv + (size_t)row * QKVW + w * DHc;
    float q0 = __half2float(base[lane]), q1 = __half2float(base[lane + 32]);
    float k0 = __half2float(base[Dc + lane]),
          k1 = __half2float(base[Dc + lane + 32]);
    float sq = q0 * q0 + q1 * q1;
    float sk = k0 * k0 + k1 * k1;
#pragma unroll
    for (int o = 16; o > 0; o >>= 1) {
        sq += __shfl_down_sync(0xffffffffu, sq, o);
        sk += __shfl_down_sync(0xffffffffu, sk, o);
    }
    if (lane == 0) {
        int bh = (row >> 12) * Hc + w;
        int n = row & (Nc - 1);
        qdiag[(size_t)bh * Nc + n] = sq * DIAG_SCALE;
        kdiag[(size_t)bh * Nc + n] = sk * DIAG_SCALE;
    }
}

// ---------- q features: per-row max + exp, fp32 dd -> fp16 features --------
__global__ __launch_bounds__(256)
void featq_finish(const float* __restrict__ qp, const float* __restrict__ qdiag,
                  __half* __restrict__ qp16) {
    int w = threadIdx.x >> 5, lane = threadIdx.x & 31;
    int rr = blockIdx.x * 8 + w;
    const float* p = qp + (size_t)rr * Mc + lane * 8;
    float4 v0 = *(const float4*)p;
    float4 v1 = *(const float4*)(p + 4);
    float mx = fmaxf(fmaxf(fmaxf(v0.x, v0.y), fmaxf(v0.z, v0.w)),
                     fmaxf(fmaxf(v1.x, v1.y), fmaxf(v1.z, v1.w)));
#pragma unroll
    for (int o = 16; o > 0; o >>= 1)
        mx = fmaxf(mx, __shfl_xor_sync(0xffffffffu, mx, o));
    float sub = qdiag[rr] + mx;
    uint4 o;
    o.x = f2h2(RATIO_CONST * (expf(v0.x - sub) + EPSK),
               RATIO_CONST * (expf(v0.y - sub) + EPSK));
    o.y = f2h2(RATIO_CONST * (expf(v0.z - sub) + EPSK),
               RATIO_CONST * (expf(v0.w - sub) + EPSK));
    o.z = f2h2(RATIO_CONST * (expf(v1.x - sub) + EPSK),
               RATIO_CONST * (expf(v1.y - sub) + EPSK));
    o.w = f2h2(RATIO_CONST * (expf(v1.z - sub) + EPSK),
               RATIO_CONST * (expf(v1.w - sub) + EPSK));
    *(uint4*)&qp16[(size_t)rr * Mc + lane * 8] = o;
}

// -------- k features: exp + transpose -> kpT16 [bh][m][n] ------------------
__global__ __launch_bounds__(256)
void featkT(const float* __restrict__ kp, const float* __restrict__ kdiag,
            const float* __restrict__ hmax, __half* __restrict__ kpT) {
    __shared__ __half tile[32][33];
    int bh = blockIdx.z;
    int n0 = blockIdx.x * 32, m0 = blockIdx.y * 32;
    float hm = hmax[bh];
    int tx = threadIdx.x & 31, ty = threadIdx.x >> 5;
#pragma unroll
    for (int i = 0; i < 4; i++) {
        int n = n0 + ty + i * 8;
        float sub = kdiag[(size_t)bh * Nc + n] + hm;
        float v = kp[((size_t)bh * Nc + n) * Mc + m0 + tx];
        tile[ty + i * 8][tx] = __float2half(RATIO_CONST * (expf(v - sub) + EPSK));
    }
    __syncthreads();
#pragma unroll
    for (int i = 0; i < 4; i++) {
        int m = m0 + ty + i * 8;
        kpT[((size_t)bh * Mc + m) * Nc + n0 + tx] = tile[tx][ty + i * 8];
    }
}

// -------------------- v transpose: vT16 [bh][d][n] (64 rows) ---------------
__global__ __launch_bounds__(256)
void vtrans(const __half* __restrict__ qkv, __half* __restrict__ vT) {
    __shared__ __half tile[32][33];
    int z = blockIdx.z;
    int b = z >> 3, h = z & 7;
    int n0 = blockIdx.x * 32, d0 = blockIdx.y * 32;
    int tx = threadIdx.x & 31, ty = threadIdx.x >> 5;
#pragma unroll
    for (int i = 0; i < 4; i++)
        tile[ty + i * 8][tx] =
            qkv[((size_t)(b * Nc + n0 + ty + i * 8)) * QKVW + 2 * Dc + h * DHc +
                d0 + tx];
    __syncthreads();
#pragma unroll
    for (int i = 0; i < 4; i++)
        vT[((size_t)z * 64 + d0 + ty + i * 8) * Nc + n0 + tx] =
            tile[tx][ty + i * 8];
}

// --------------------------- ksum from kpT ---------------------------------
__global__ __launch_bounds__(256)
void ksum_kernel(const __half* __restrict__ kpT, float* __restrict__ ksum) {
    int bh = blockIdx.y;
    int m = blockIdx.x * 8 + (threadIdx.x >> 5);
    int lane = threadIdx.x & 31;
    const uint4* row = (const uint4*)(kpT + ((size_t)bh * Mc + m) * Nc);
    float s = 0.0f;
    for (int i = lane; i < Nc / 8; i += 32) {
        uint4 u = row[i];
        __half2* hp = (__half2*)&u;
#pragma unroll
        for (int j = 0; j < 4; j++) {
            float2 f = __half22float2(hp[j]);
            s += f.x + f.y;
        }
    }
#pragma unroll
    for (int o = 16; o > 0; o >>= 1) s += __shfl_down_sync(0xffffffffu, s, o);
    if (lane == 0) ksum[bh * Mc + m] = s;
}

// ------------------------ init hmax (-inf), tiny ---------------------------
__global__ void initbuf(float* __restrict__ hmax) {
    if (threadIdx.x < BHc) hmax[threadIdx.x] = -1e30f;
}

// -------------- reduce ctx slabs + convert -> ctxT16 -----------------------
__global__ void cvtctx(const float* __restrict__ ctxF, __half* __restrict__ ctxT) {
    size_t i = (size_t)blockIdx.x * 256 + threadIdx.x;     // BHc*64*Mc elems
    float s = 0.0f;
#pragma unroll
    for (int sl = 0; sl < NSPLIT; sl++)
        s += ctxF[(size_t)sl * BHc * 64 * Mc + i];
    ctxT[i] = __float2half(s);
}

// ------------------------------- d_inv -------------------------------------
__global__ __launch_bounds__(256)
void dinv_kernel(const __half* __restrict__ qp16, const float* __restrict__ ksum,
                 float* __restrict__ dinv) {
    int w = threadIdx.x >> 5, lane = threadIdx.x & 31;
    int rr = blockIdx.x * 8 + w;
    int bh = rr >> 12;
    uint4 u = ((const uint4*)(qp16 + (size_t)rr * Mc))[lane];
    const float* ks = ksum + bh * Mc + lane * 8;
    __half2* hp = (__half2*)&u;
    float s = 0.0f;
#pragma unroll
    for (int j = 0; j < 4; j++) {
        float2 f = __half22float2(hp[j]);
        s += f.x * ks[2 * j] + f.y * ks[2 * j + 1];
    }
#pragma unroll
    for (int o = 16; o > 0; o >>= 1) s += __shfl_down_sync(0xffffffffu, s, o);
    if (lane == 0) dinv[rr] = 1.0f / s;
}

// ------------------------------- launch ------------------------------------
extern "C" void kernel_launch(void* const* d_in, const int* in_sizes, int n_in,
                              void* d_out, int out_size) {
    (void)in_sizes; (void)n_in; (void)out_size;
    const float* x    = (const float*)d_in[0];
    const float* proj = (const float*)d_in[1];
    const float* ln1g = (const float*)d_in[2];
    const float* ln1b = (const float*)d_in[3];
    const float* Wqkv = (const float*)d_in[4];
    const float* bqkv = (const float*)d_in[5];
    const float* Wo   = (const float*)d_in[6];
    const float* bo   = (const float*)d_in[7];
    const float* ln2g = (const float*)d_in[8];
    const float* ln2b = (const float*)d_in[9];
    const float* Wff1 = (const float*)d_in[10];
    const float* bff1 = (const float*)d_in[11];
    const float* Wff2 = (const float*)d_in[12];
    const float* bff2 = (const float*)d_in[13];
    float* h = (float*)d_out;

    static float *p_qp = 0, *p_kp = 0, *p_ctxF = 0, *p_ksum = 0, *p_qdiag = 0,
                 *p_kdiag = 0, *p_hmax = 0, *p_dinv = 0;
    static __half *p_ln16 = 0, *p_qkv16 = 0, *p_ff16 = 0, *p_att16 = 0,
                  *p_qp16 = 0, *p_kpT = 0, *p_vT = 0, *p_ctxT = 0,
                  *p_wqkvT = 0, *p_woT = 0, *p_wff1T = 0, *p_wff2T = 0,
                  *p_projh = 0;
    if (!p_qp) {
        cudaGetSymbolAddress((void**)&p_qp, g_qp);
        cudaGetSymbolAddress((void**)&p_kp, g_kp);
        cudaGetSymbolAddress((void**)&p_ctxF, g_ctxF);
        cudaGetSymbolAddress((void**)&p_ksum, g_ksum);
        cudaGetSymbolAddress((void**)&p_qdiag, g_qdiag);
        cudaGetSymbolAddress((void**)&p_kdiag, g_kdiag);
        cudaGetSymbolAddress((void**)&p_hmax, g_hmax);
        cudaGetSymbolAddress((void**)&p_dinv, g_dinv);
        cudaGetSymbolAddress((void**)&p_ln16, g_ln16);
        cudaGetSymbolAddress((void**)&p_qkv16, g_qkv16);
        cudaGetSymbolAddress((void**)&p_ff16, g_ff16);
        cudaGetSymbolAddress((void**)&p_att16, g_att16);
        cudaGetSymbolAddress((void**)&p_qp16, g_qp16);
        cudaGetSymbolAddress((void**)&p_kpT, g_kpT);
        cudaGetSymbolAddress((void**)&p_vT, g_vT);
        cudaGetSymbolAddress((void**)&p_ctxT, g_ctxT);
        cudaGetSymbolAddress((void**)&p_wqkvT, g_wqkvT);
        cudaGetSymbolAddress((void**)&p_woT, g_woT);
        cudaGetSymbolAddress((void**)&p_wff1T, g_wff1T);
        cudaGetSymbolAddress((void**)&p_wff2T, g_wff2T);
        cudaGetSymbolAddress((void**)&p_projh, g_projh);
        cudaFuncSetAttribute(hgemm<EPI_NONE, 0, __half, 4, 2>,
                             cudaFuncAttributeMaxDynamicSharedMemorySize, HG_SMEM);
        cudaFuncSetAttribute(hgemm<EPI_NONE, 4, float, 4, 2>,
                             cudaFuncAttributeMaxDynamicSharedMemorySize, HG_SMEM);
        cudaFuncSetAttribute(hgemm<EPI_NONE, 2, float, 2, 2>,
                             cudaFuncAttributeMaxDynamicSharedMemorySize, HG_SMEM);
        cudaFuncSetAttribute(hgemm<EPI_DINV, 3, __half, 4, 1>,
                             cudaFuncAttributeMaxDynamicSharedMemorySize, HG_SMEM);
        cudaFuncSetAttribute(hgemm<EPI_ADD, 0, float, 4, 2>,
                             cudaFuncAttributeMaxDynamicSharedMemorySize, HG_SMEM);
        cudaFuncSetAttribute(hgemm<EPI_GELU, 0, __half, 4, 2>,
                             cudaFuncAttributeMaxDynamicSharedMemorySize, HG_SMEM);
    }

    // launch 0: weight transposes + fp16 conversion
    transpose_all<<<dim3(64, 64, 20), 256>>>(Wqkv, Wo, Wff1, Wff2, proj,
                                             p_wqkvT, p_woT, p_wff1T, p_wff2T,
                                             p_projh);
    // launch 1
    copy_kernel<<<(ROWSc * Dc) / 256, 256>>>(x, h);

    for (int l = 0; l < DEPTHc; l++) {
        const __half* pjh = p_projh + (size_t)l * Mc * DHc;

        ln_kernel<<<ROWSc / 8, 256>>>(h, ln1g + l * Dc, ln1b + l * Dc, p_ln16);

        // launch 3 (profiled): QKV
        hgemm<EPI_NONE, 0, __half, 4, 2>
            <<<dim3(QKVW / 128, ROWSc / 128), 256, HG_SMEM>>>(
            p_ln16, Dc, p_wqkvT + (size_t)l * QKVW * Dc, Dc,
            bqkv + l * QKVW, (const float*)0, p_qkv16, QKVW, Dc, 1.0f, 128,
            (float*)0, (float*)0);

        initbuf<<<1, 32>>>(p_hmax);

        // merged dd_q/dd_k (z<16: q -> qp, z>=16: k -> kp + fused hmax)
        hgemm<EPI_NONE, 4, float, 4, 2>
            <<<dim3(Mc / 128, Nc / 128, 2 * BHc), 256, HG_SMEM>>>(
            p_qkv16, QKVW, pjh, DHc, (const float*)0, (const float*)0,
            p_qp, Mc, DHc, DN_CONST, 128, p_kp, p_hmax);

        diag_kernel<<<ROWSc, 256>>>(p_qkv16, p_qdiag, p_kdiag);
        featq_finish<<<(BHc * Nc) / 8, 256>>>(p_qp, p_qdiag, p_qp16);
        featkT<<<dim3(Nc / 32, Mc / 32, BHc), 256>>>(p_kp, p_kdiag, p_hmax, p_kpT);
        vtrans<<<dim3(Nc / 32, 2, BHc), 256>>>(p_qkv16, p_vT);
        ksum_kernel<<<dim3(Mc / 8, BHc), 256>>>(p_kpT, p_ksum);

        // ctx^T = vT @ kpT^T, split-K=8 disjoint slabs (BM=64)
        hgemm<EPI_NONE, 2, float, 2, 2>
            <<<dim3(Mc / 128, NSPLIT, BHc), 256, HG_SMEM>>>(
            p_vT, Nc, p_kpT, Nc, (const float*)0, (const float*)0,
            p_ctxF, Mc, Nc / NSPLIT, 1.0f, 128, (float*)0, (float*)0);
        cvtctx<<<(BHc * 64 * Mc) / 256, 256>>>(p_ctxF, p_ctxT);

        dinv_kernel<<<(BHc * Nc) / 8, 256>>>(p_qp16, p_ksum, p_dinv);

        // attnout = (qp16 @ ctxT^T) * dinv, BN=64, head-merged fp16
        hgemm<EPI_DINV, 3, __half, 4, 1>
            <<<dim3(1, Nc / 128, BHc), 256, HG_SMEM>>>(
            p_qp16, Mc, p_ctxT, Mc, (const float*)0, p_dinv,
            p_att16, Dc, Mc, 1.0f, 64, (float*)0, (float*)0);

        // Wo + residual
        hgemm<EPI_ADD, 0, float, 4, 2>
            <<<dim3(Dc / 128, ROWSc / 128), 256, HG_SMEM>>>(
            p_att16, Dc, p_woT + (size_t)l * Dc * Dc, Dc,
            bo + l * Dc, h, h, Dc, Dc, 1.0f, 128, (float*)0, (float*)0);

        ln_kernel<<<ROWSc / 8, 256>>>(h, ln2g + l * Dc, ln2b + l * Dc, p_ln16);

        // FF1 + gelu
        hgemm<EPI_GELU, 0, __half, 4, 2>
            <<<dim3(FFc / 128, ROWSc / 128), 256, HG_SMEM>>>(
            p_ln16, Dc, p_wff1T + (size_t)l * FFc * Dc, Dc,
            bff1 + l * FFc, (const float*)0, p_ff16, FFc, Dc, 1.0f, 128,
            (float*)0, (float*)0);

        // FF2 + residual
        hgemm<EPI_ADD, 0, float, 4, 2>
            <<<dim3(Dc / 128, ROWSc / 128), 256, HG_SMEM>>>(
            p_ff16, FFc, p_wff2T + (size_t)l * Dc * FFc, FFc,
            bff2 + l * Dc, h, h, Dc, FFc, 1.0f, 128, (float*)0, (float*)0);
    }
}

// round 14
// speedup vs baseline: 1.2778x; 1.0251x over previous
#include <cuda_runtime.h>
#include <cuda_fp16.h>
#include <math.h>
#include <stdint.h>

// ---------------------------------------------------------------------------
// SpatioTemporalPerformerEncoder — R14: fused featq epilogue, sized smem stages
// ---------------------------------------------------------------------------

#define Bc     2
#define Hc     8
#define Nc     4096
#define Dc     512
#define DHc    64
#define Mc     256
#define FFc    2048
#define DEPTHc 4
#define ROWSc  8192
#define BHc    16
#define QKVW   1536

#define DN_CONST    0.35355339059327373f
#define DIAG_SCALE  0.0625f
#define RATIO_CONST 0.0625f
#define EPSK        1e-4f
#define LNEPS       1e-5f

#define NSPLIT  8

// ------------------------- scratch (device globals) ------------------------
__device__ __half g_ln16 [(size_t)ROWSc * Dc];
__device__ __half g_qkv16[(size_t)ROWSc * QKVW];
__device__ __half g_ff16 [(size_t)ROWSc * FFc];
__device__ __half g_att16[(size_t)ROWSc * Dc];
__device__ float  g_kp   [(size_t)BHc * Nc * Mc];
__device__ __half g_qp16 [(size_t)BHc * Nc * Mc];
__device__ __half g_kpT  [(size_t)BHc * Mc * Nc];
__device__ __half g_vT   [(size_t)BHc * 64 * Nc];          // v^T, 64 rows
__device__ float  g_ctxF [(size_t)NSPLIT * BHc * 64 * Mc]; // split-K slabs
__device__ __half g_ctxT [(size_t)BHc * 64 * Mc];
__device__ float  g_ksum [BHc * Mc];
__device__ float  g_qdiag[BHc * Nc];
__device__ float  g_kdiag[BHc * Nc];
__device__ float  g_hmax [BHc];
__device__ float  g_dinv [BHc * Nc];
__device__ __half g_wqkvT[(size_t)DEPTHc * QKVW * Dc];
__device__ __half g_woT  [(size_t)DEPTHc * Dc * Dc];
__device__ __half g_wff1T[(size_t)DEPTHc * FFc * Dc];
__device__ __half g_wff2T[(size_t)DEPTHc * Dc * FFc];
__device__ __half g_projh[(size_t)DEPTHc * Mc * DHc];

// ------------------------------ helpers ------------------------------------
__device__ __forceinline__ uint32_t smem_to_u32(const void* p) {
    uint32_t a;
    asm("{ .reg .u64 t; cvta.to.shared.u64 t, %1; cvt.u32.u64 %0, t; }"
        : "=r"(a) : "l"(p));
    return a;
}
__device__ __forceinline__ uint32_t f2h2(float a, float b) {
    __half2 h = __floats2half2_rn(a, b);
    return *(uint32_t*)&h;
}
__device__ __forceinline__ void cp16(uint32_t dst, const void* src) {
    asm volatile("cp.async.cg.shared.global [%0], [%1], 16;"
                 :: "r"(dst), "l"(src));
}
#define CP_COMMIT() asm volatile("cp.async.commit_group;")
#define CP_WAIT(n)  asm volatile("cp.async.wait_group %0;" :: "n"(n))

__device__ __forceinline__ void ldsm4(uint32_t& r0, uint32_t& r1, uint32_t& r2,
                                      uint32_t& r3, uint32_t a) {
    asm volatile("ldmatrix.sync.aligned.m8n8.x4.shared.b16 {%0,%1,%2,%3}, [%4];"
                 : "=r"(r0), "=r"(r1), "=r"(r2), "=r"(r3) : "r"(a));
}
__device__ __forceinline__ void mma_f16(float c[4], const uint32_t a[4],
                                        const uint32_t b[2]) {
    asm volatile(
        "mma.sync.aligned.m16n8k16.row.col.f32.f16.f16.f32 "
        "{%0,%1,%2,%3}, {%4,%5,%6,%7}, {%8,%9}, {%0,%1,%2,%3};"
        : "+f"(c[0]), "+f"(c[1]), "+f"(c[2]), "+f"(c[3])
        : "r"(a[0]), "r"(a[1]), "r"(a[2]), "r"(a[3]), "r"(b[0]), "r"(b[1]));
}
__device__ __forceinline__ void atomicMaxF(float* a, float v) {
    if (v >= 0.0f) atomicMax((int*)a, __float_as_int(v));
    else atomicMin((unsigned int*)a, __float_as_uint(v));
}

// ------------------------- fp16 tensor-core GEMM ---------------------------
// C = scale*(A[M,K]h @ B[N,K]h^T) + epilogue. BK=32, 256 threads (8 warps 2x4),
// warp tile (MT*16)x(NT*16), BM=MT*32, BN=NT*64. 3-stage cp.async.
// Stage layout: A at buf*STG, B at buf*STG + BM*80 (STG=(BM+BN)*80 bytes).
// BHM 0: plain. 2: ctx (per-bh, split-K slab via blockIdx.y, fp32 slab out).
// 3: attnout (per-bh, dinv row scale via R, head-merged out).
// 4: dd_k (per-bh, fp32 out + fused global-max into hmaxp).
// 5: dd_q fused featq (per-bh, qdiag via R, row-max+exp epilogue, fp16 out).
#define EPI_NONE 0
#define EPI_GELU 1
#define EPI_ADD  2
#define EPI_DINV 3

template <int EPI, int BHM, typename OutT, int MT, int NT>
__global__ __launch_bounds__(256, 2)
void hgemm(const __half* __restrict__ A, int lda,
           const __half* __restrict__ Bh, int ldb,
           const float* __restrict__ bias, const float* __restrict__ R,
           OutT* __restrict__ C, int ldc, int K, float scale,
           int nvalid, float* __restrict__ hmaxp) {
    extern __shared__ __align__(16) char smem_dyn[];
    uint32_t sBase = smem_to_u32(smem_dyn);

    const int BM = MT * 32, BN = NT * 64;
    const uint32_t ASZ = (uint32_t)BM * 80;
    const uint32_t STG = (uint32_t)(BM + BN) * 80;

    int m0, n0;
    if (BHM == 2) {
        int z = blockIdx.z, s = blockIdx.y;
        A += (size_t)z * BM * lda + (size_t)s * K;
        Bh += (size_t)z * Mc * ldb + (size_t)s * K;
        C += ((size_t)s * BHc + z) * BM * ldc;
        m0 = 0;
        n0 = blockIdx.x * BN;
    } else {
        if (BHM == 4) {
            int z = blockIdx.z;
            A += (size_t)(z >> 3) * Nc * lda + (size_t)(z & 7) * DHc + Dc;
            C += (size_t)z * Nc * ldc;
        }
        if (BHM == 5) {
            int z = blockIdx.z;
            A += (size_t)(z >> 3) * Nc * lda + (size_t)(z & 7) * DHc;
            C += (size_t)z * Nc * ldc;
            R += (size_t)z * Nc;
        }
        if (BHM == 3) {
            int z = blockIdx.z;
            A += (size_t)z * Nc * lda;
            Bh += (size_t)z * 64 * ldb;
            C += (size_t)(z >> 3) * Nc * Dc + (size_t)(z & 7) * DHc;
            R += (size_t)z * Nc;
        }
        m0 = blockIdx.y * BM;
        n0 = blockIdx.x * BN;
    }

    int tid = threadIdx.x, lane = tid & 31, warp = tid >> 5;
    int wm = warp >> 2, wn = warp & 3;

    int rowC = tid >> 2, cA = (tid & 3) * 8;
    uint32_t sOff = ((uint32_t)rowC * 40 + cA) * 2;
    uint32_t fOff = (((lane & 15) * 40) + (lane >> 4) * 8) * 2;

    float c[MT][2 * NT][4];
#pragma unroll
    for (int i = 0; i < MT; i++)
#pragma unroll
        for (int j = 0; j < 2 * NT; j++)
#pragma unroll
            for (int l = 0; l < 4; l++) c[i][j][l] = 0.0f;

#define ISSUE(t, buf)                                                         \
    {                                                                         \
        int k0 = (t) * 32;                                                    \
        _Pragma("unroll")                                                     \
        for (int p = 0; p < MT / 2; p++)                                      \
            cp16(sBase + (buf) * STG + sOff + p * 5120,                       \
                 A + (size_t)(m0 + rowC + p * 64) * lda + k0 + cA);           \
        _Pragma("unroll")                                                     \
        for (int p = 0; p < NT; p++)                                          \
            cp16(sBase + (buf) * STG + ASZ + sOff + p * 5120,                 \
                 Bh + (size_t)(n0 + rowC + p * 64) * ldb + k0 + cA);          \
        CP_COMMIT();                                                          \
    }

    int T = K >> 5;                 // all call sites have K >= 64 (T >= 2)
    ISSUE(0, 0)
    ISSUE(1, 1)
    int buf = 0;
    for (int t = 0; t < T; t++) {
        if (t == T - 1) { CP_WAIT(0); } else { CP_WAIT(1); }
        __syncthreads();

        uint32_t aTile = sBase + buf * STG;
        uint32_t bTile = aTile + ASZ;
#pragma unroll
        for (int kk = 0; kk < 2; kk++) {
            int k16 = kk * 16;
            uint32_t af[MT][4], bf[2 * NT][2];
#pragma unroll
            for (int mi = 0; mi < MT; mi++)
                ldsm4(af[mi][0], af[mi][1], af[mi][2], af[mi][3],
                      aTile + ((wm * MT * 16 + mi * 16) * 40 + k16) * 2 + fOff);
#pragma unroll
            for (int p = 0; p < NT; p++) {
                uint32_t r0, r1, r2, r3;
                ldsm4(r0, r1, r2, r3,
                      bTile + ((wn * NT * 16 + p * 16) * 40 + k16) * 2 + fOff);
                bf[2 * p][0] = r0; bf[2 * p][1] = r2;
                bf[2 * p + 1][0] = r1; bf[2 * p + 1][1] = r3;
            }
#pragma unroll
            for (int mi = 0; mi < MT; mi++)
#pragma unroll
                for (int ni = 0; ni < 2 * NT; ni++)
                    mma_f16(c[mi][ni], af[mi], bf[ni]);
        }
        if (t + 2 < T) {
            int nb = buf + 2; if (nb >= 3) nb -= 3;
            ISSUE(t + 2, nb)
        }
        buf = (buf + 1 == 3) ? 0 : buf + 1;
    }
#undef ISSUE

    int g = lane >> 2, tig = lane & 3;

    if (BHM == 5) {
        // fused FAVOR+ q-feature epilogue: row max + exp, fp16 out
        float* rowred = (float*)smem_dyn;
        __syncthreads();
        if (tid < BM) rowred[tid] = -1e30f;
        __syncthreads();
        float lm[MT][2];
#pragma unroll
        for (int mi = 0; mi < MT; mi++) { lm[mi][0] = -1e30f; lm[mi][1] = -1e30f; }
#pragma unroll
        for (int mi = 0; mi < MT; mi++)
#pragma unroll
            for (int ni = 0; ni < 2 * NT; ni++) {
                lm[mi][0] = fmaxf(lm[mi][0], fmaxf(c[mi][ni][0], c[mi][ni][1]));
                lm[mi][1] = fmaxf(lm[mi][1], fmaxf(c[mi][ni][2], c[mi][ni][3]));
            }
#pragma unroll
        for (int mi = 0; mi < MT; mi++)
#pragma unroll
            for (int half = 0; half < 2; half++) {
                int rl = wm * MT * 16 + mi * 16 + g + half * 8;
                atomicMaxF(&rowred[rl], lm[mi][half] * scale);
            }
        __syncthreads();
        float sub[MT][2];
#pragma unroll
        for (int mi = 0; mi < MT; mi++)
#pragma unroll
            for (int half = 0; half < 2; half++) {
                int rl = wm * MT * 16 + mi * 16 + g + half * 8;
                sub[mi][half] = R[m0 + rl] + rowred[rl];
            }
#pragma unroll
        for (int mi = 0; mi < MT; mi++)
#pragma unroll
            for (int ni = 0; ni < 2 * NT; ni++) {
                int col = wn * NT * 16 + ni * 8 + 2 * tig;
#pragma unroll
                for (int half = 0; half < 2; half++) {
                    int r = m0 + wm * MT * 16 + mi * 16 + g + half * 8;
                    float s_ = sub[mi][half];
                    float v0 = RATIO_CONST *
                               (expf(c[mi][ni][half * 2 + 0] * scale - s_) + EPSK);
                    float v1 = RATIO_CONST *
                               (expf(c[mi][ni][half * 2 + 1] * scale - s_) + EPSK);
                    __half2 hv = __floats2half2_rn(v0, v1);
                    *(__half2*)&((__half*)C)[(size_t)r * ldc + col] = hv;
                }
            }
        return;
    }

    // generic epilogue
    float tm = -1e30f;
#pragma unroll
    for (int mi = 0; mi < MT; mi++) {
#pragma unroll
        for (int ni = 0; ni < 2 * NT; ni++) {
            int rl = wm * MT * 16 + mi * 16 + g;
            int cl = wn * NT * 16 + ni * 8 + 2 * tig;
            if (cl >= nvalid) continue;
            int col = n0 + cl;
#pragma unroll
            for (int half = 0; half < 2; half++) {
                int r = m0 + rl + half * 8;
                float v0 = c[mi][ni][half * 2 + 0] * scale;
                float v1 = c[mi][ni][half * 2 + 1] * scale;
                if (BHM == 4) tm = fmaxf(tm, fmaxf(v0, v1));
                if (bias) { v0 += bias[col]; v1 += bias[col + 1]; }
                if (EPI == EPI_GELU) {
                    v0 = 0.5f * v0 * (1.0f + erff(v0 * 0.70710678118654752f));
                    v1 = 0.5f * v1 * (1.0f + erff(v1 * 0.70710678118654752f));
                }
                if (EPI == EPI_ADD) {
                    v0 += R[(size_t)r * ldc + col];
                    v1 += R[(size_t)r * ldc + col + 1];
                }
                if (EPI == EPI_DINV) {
                    float di = R[r];
                    v0 *= di; v1 *= di;
                }
                if (sizeof(OutT) == 2) {
                    __half2 hv = __floats2half2_rn(v0, v1);
                    *(__half2*)&((__half*)C)[(size_t)r * ldc + col] = hv;
                } else {
                    float2 o = {v0, v1};
                    *(float2*)&((float*)C)[(size_t)r * ldc + col] = o;
                }
            }
        }
    }
    if (BHM == 4) {
#pragma unroll
        for (int o = 16; o > 0; o >>= 1)
            tm = fmaxf(tm, __shfl_xor_sync(0xffffffffu, tm, o));
        if (lane == 0) atomicMaxF(&hmaxp[blockIdx.z], tm);
    }
}

// --------------- batched weight transpose + convert to fp16 ----------------
__global__ __launch_bounds__(256)
void transpose_all(const float* __restrict__ Wqkv, const float* __restrict__ Wo,
                   const float* __restrict__ Wff1, const float* __restrict__ Wff2,
                   const float* __restrict__ proj,
                   __half* __restrict__ qkvT, __half* __restrict__ woT,
                   __half* __restrict__ ff1T, __half* __restrict__ ff2T,
                   __half* __restrict__ projh) {
    __shared__ float tbuf[32][33];
    int z = blockIdx.z;
    if (z >= 16) {
        int l = z - 16;
        int idx = (blockIdx.y * gridDim.x + blockIdx.x) * 256 + threadIdx.x;
        if (idx < Mc * DHc)
            projh[(size_t)l * Mc * DHc + idx] =
                __float2half(proj[(size_t)l * Mc * DHc + idx]);
        return;
    }
    int type = z & 3, l = z >> 2;
    int K, N;
    const float* in;
    __half* out;
    if (type == 0)      { K = Dc;  N = QKVW; in = Wqkv + (size_t)l * Dc * QKVW; out = qkvT + (size_t)l * QKVW * Dc; }
    else if (type == 1) { K = Dc;  N = Dc;   in = Wo   + (size_t)l * Dc * Dc;   out = woT  + (size_t)l * Dc * Dc; }
    else if (type == 2) { K = Dc;  N = FFc;  in = Wff1 + (size_t)l * Dc * FFc;  out = ff1T + (size_t)l * FFc * Dc; }
    else                { K = FFc; N = Dc;   in = Wff2 + (size_t)l * FFc * Dc;  out = ff2T + (size_t)l * Dc * FFc; }

    int nx = blockIdx.x * 32, kx = blockIdx.y * 32;
    if (nx >= N || kx >= K) return;
    int tx = threadIdx.x & 31, ty = threadIdx.x >> 5;
#pragma unroll
    for (int i = 0; i < 4; i++)
        tbuf[ty + i * 8][tx] = in[(size_t)(kx + ty + i * 8) * N + nx + tx];
    __syncthreads();
#pragma unroll
    for (int i = 0; i < 4; i++)
        out[(size_t)(nx + ty + i * 8) * K + kx + tx] =
            __float2half(tbuf[tx][ty + i * 8]);
}

// ------------------------------ copy x -> h --------------------------------
__global__ void copy_kernel(const float* __restrict__ x, float* __restrict__ h) {
    size_t i = (size_t)blockIdx.x * 256 + threadIdx.x;
    h[i] = x[i];
}

// ------------------- layernorm: warp per row (fp16 out) --------------------
__global__ __launch_bounds__(256)
void ln_kernel(const float* __restrict__ x, const float* __restrict__ g,
               const float* __restrict__ b, __half* __restrict__ out) {
    int w = threadIdx.x >> 5, lane = threadIdx.x & 31;
    int row = blockIdx.x * 8 + w;
    const float4* xr = (const float4*)(x + (size_t)row * Dc);
    float4 v[4];
    float s = 0.0f;
#pragma unroll
    for (int i = 0; i < 4; i++) {
        v[i] = xr[lane + i * 32];
        s += (v[i].x + v[i].y) + (v[i].z + v[i].w);
    }
#pragma unroll
    for (int o = 16; o > 0; o >>= 1) s += __shfl_xor_sync(0xffffffffu, s, o);
    float mu = s * (1.0f / Dc);
    float var = 0.0f;
#pragma unroll
    for (int i = 0; i < 4; i++) {
        v[i].x -= mu; v[i].y -= mu; v[i].z -= mu; v[i].w -= mu;
        var += v[i].x * v[i].x + v[i].y * v[i].y +
               v[i].z * v[i].z + v[i].w * v[i].w;
    }
#pragma unroll
    for (int o = 16; o > 0; o >>= 1) var += __shfl_xor_sync(0xffffffffu, var, o);
    float rs = rsqrtf(var * (1.0f / Dc) + LNEPS);
    const float4* gp = (const float4*)g;
    const float4* bp = (const float4*)b;
    __half* orow = out + (size_t)row * Dc;
#pragma unroll
    for (int i = 0; i < 4; i++) {
        float4 gg = gp[lane + i * 32], bb = bp[lane + i * 32];
        uint2 o2;
        o2.x = f2h2(v[i].x * rs * gg.x + bb.x, v[i].y * rs * gg.y + bb.y);
        o2.y = f2h2(v[i].z * rs * gg.z + bb.z, v[i].w * rs * gg.w + bb.w);
        *(uint2*)&orow[(lane + i * 32) * 4] = o2;
    }
}

// ------------------- diag: per-(bh,row) 0.5*dn^2*|q|^2, |k|^2 --------------
__global__ __launch_bounds__(256)
void diag_kernel(const __half* __restrict__ qkv, float* __restrict__ qdiag,
                 float* __restrict__ kdiag) {
    int row = blockIdx.x;
    int w = threadIdx.x >> 5, lane = threadIdx.x & 31;
    const __half* base = qkv + (size_t)row * QKVW + w * DHc;
    float q0 = __half2float(base[lane]), q1 = __half2float(base[lane + 32]);
    float k0 = __half2float(base[Dc + lane]),
          k1 = __half2float(base[Dc + lane + 32]);
    float sq = q0 * q0 + q1 * q1;
    float sk = k0 * k0 + k1 * k1;
#pragma unroll
    for (int o = 16; o > 0; o >>= 1) {
        sq += __shfl_down_sync(0xffffffffu, sq, o);
        sk += __shfl_down_sync(0xffffffffu, sk, o);
    }
    if (lane == 0) {
        int bh = (row >> 12) * Hc + w;
        int n = row & (Nc - 1);
        qdiag[(size_t)bh * Nc + n] = sq * DIAG_SCALE;
        kdiag[(size_t)bh * Nc + n] = sk * DIAG_SCALE;
    }
}

// -------- k features: exp + transpose -> kpT16 [bh][m][n] ------------------
__global__ __launch_bounds__(256)
void featkT(const float* __restrict__ kp, const float* __restrict__ kdiag,
            const float* __restrict__ hmax, __half* __restrict__ kpT) {
    __shared__ __half tile[32][33];
    int bh = blockIdx.z;
    int n0 = blockIdx.x * 32, m0 = blockIdx.y * 32;
    float hm = hmax[bh];
    int tx = threadIdx.x & 31, ty = threadIdx.x >> 5;
#pragma unroll
    for (int i = 0; i < 4; i++) {
        int n = n0 + ty + i * 8;
        float sub = kdiag[(size_t)bh * Nc + n] + hm;
        float v = kp[((size_t)bh * Nc + n) * Mc + m0 + tx];
        tile[ty + i * 8][tx] = __float2half(RATIO_CONST * (expf(v - sub) + EPSK));
    }
    __syncthreads();
#pragma unroll
    for (int i = 0; i < 4; i++) {
        int m = m0 + ty + i * 8;
        kpT[((size_t)bh * Mc + m) * Nc + n0 + tx] = tile[tx][ty + i * 8];
    }
}

// -------------------- v transpose: vT16 [bh][d][n] (64 rows) ---------------
__global__ __launch_bounds__(256)
void vtrans(const __half* __restrict__ qkv, __half* __restrict__ vT) {
    __shared__ __half tile[32][33];
    int z = blockIdx.z;
    int b = z >> 3, h = z & 7;
    int n0 = blockIdx.x * 32, d0 = blockIdx.y * 32;
    int tx = threadIdx.x & 31, ty = threadIdx.x >> 5;
#pragma unroll
    for (int i = 0; i < 4; i++)
        tile[ty + i * 8][tx] =
            qkv[((size_t)(b * Nc + n0 + ty + i * 8)) * QKVW + 2 * Dc + h * DHc +
                d0 + tx];
    __syncthreads();
#pragma unroll
    for (int i = 0; i < 4; i++)
        vT[((size_t)z * 64 + d0 + ty + i * 8) * Nc + n0 + tx] =
            tile[tx][ty + i * 8];
}

// --------------------------- ksum from kpT ---------------------------------
__global__ __launch_bounds__(256)
void ksum_kernel(const __half* __restrict__ kpT, float* __restrict__ ksum) {
    int bh = blockIdx.y;
    int m = blockIdx.x * 8 + (threadIdx.x >> 5);
    int lane = threadIdx.x & 31;
    const uint4* row = (const uint4*)(kpT + ((size_t)bh * Mc + m) * Nc);
    float s = 0.0f;
    for (int i = lane; i < Nc / 8; i += 32) {
        uint4 u = row[i];
        __half2* hp = (__half2*)&u;
#pragma unroll
        for (int j = 0; j < 4; j++) {
            float2 f = __half22float2(hp[j]);
            s += f.x + f.y;
        }
    }
#pragma unroll
    for (int o = 16; o > 0; o >>= 1) s += __shfl_down_sync(0xffffffffu, s, o);
    if (lane == 0) ksum[bh * Mc + m] = s;
}

// ------------------------ init hmax (-inf), tiny ---------------------------
__global__ void initbuf(float* __restrict__ hmax) {
    if (threadIdx.x < BHc) hmax[threadIdx.x] = -1e30f;
}

// -------------- reduce ctx slabs + convert -> ctxT16 -----------------------
__global__ void cvtctx(const float* __restrict__ ctxF, __half* __restrict__ ctxT) {
    size_t i = (size_t)blockIdx.x * 256 + threadIdx.x;     // BHc*64*Mc elems
    float s = 0.0f;
#pragma unroll
    for (int sl = 0; sl < NSPLIT; sl++)
        s += ctxF[(size_t)sl * BHc * 64 * Mc + i];
    ctxT[i] = __float2half(s);
}

// ------------------------------- d_inv -------------------------------------
__global__ __launch_bounds__(256)
void dinv_kernel(const __half* __restrict__ qp16, const float* __restrict__ ksum,
                 float* __restrict__ dinv) {
    int w = threadIdx.x >> 5, lane = threadIdx.x & 31;
    int rr = blockIdx.x * 8 + w;
    int bh = rr >> 12;
    uint4 u = ((const uint4*)(qp16 + (size_t)rr * Mc))[lane];
    const float* ks = ksum + bh * Mc + lane * 8;
    __half2* hp = (__half2*)&u;
    float s = 0.0f;
#pragma unroll
    for (int j = 0; j < 4; j++) {
        float2 f = __half22float2(hp[j]);
        s += f.x * ks[2 * j] + f.y * ks[2 * j + 1];
    }
#pragma unroll
    for (int o = 16; o > 0; o >>= 1) s += __shfl_down_sync(0xffffffffu, s, o);
    if (lane == 0) dinv[rr] = 1.0f / s;
}

// ------------------------------- launch ------------------------------------
#define SM_44 61440   // 3*(128+128)*80
#define SM_24 76800   // 3*(64+256)*80
#define SM_22 46080   // 3*(64+128)*80
#define SM_41 46080   // 3*(128+64)*80

extern "C" void kernel_launch(void* const* d_in, const int* in_sizes, int n_in,
                              void* d_out, int out_size) {
    (void)in_sizes; (void)n_in; (void)out_size;
    const float* x    = (const float*)d_in[0];
    const float* proj = (const float*)d_in[1];
    const float* ln1g = (const float*)d_in[2];
    const float* ln1b = (const float*)d_in[3];
    const float* Wqkv = (const float*)d_in[4];
    const float* bqkv = (const float*)d_in[5];
    const float* Wo   = (const float*)d_in[6];
    const float* bo   = (const float*)d_in[7];
    const float* ln2g = (const float*)d_in[8];
    const float* ln2b = (const float*)d_in[9];
    const float* Wff1 = (const float*)d_in[10];
    const float* bff1 = (const float*)d_in[11];
    const float* Wff2 = (const float*)d_in[12];
    const float* bff2 = (const float*)d_in[13];
    float* h = (float*)d_out;

    static float *p_kp = 0, *p_ctxF = 0, *p_ksum = 0, *p_qdiag = 0,
                 *p_kdiag = 0, *p_hmax = 0, *p_dinv = 0;
    static __half *p_ln16 = 0, *p_qkv16 = 0, *p_ff16 = 0, *p_att16 = 0,
                  *p_qp16 = 0, *p_kpT = 0, *p_vT = 0, *p_ctxT = 0,
                  *p_wqkvT = 0, *p_woT = 0, *p_wff1T = 0, *p_wff2T = 0,
                  *p_projh = 0;
    if (!p_kp) {
        cudaGetSymbolAddress((void**)&p_kp, g_kp);
        cudaGetSymbolAddress((void**)&p_ctxF, g_ctxF);
        cudaGetSymbolAddress((void**)&p_ksum, g_ksum);
        cudaGetSymbolAddress((void**)&p_qdiag, g_qdiag);
        cudaGetSymbolAddress((void**)&p_kdiag, g_kdiag);
        cudaGetSymbolAddress((void**)&p_hmax, g_hmax);
        cudaGetSymbolAddress((void**)&p_dinv, g_dinv);
        cudaGetSymbolAddress((void**)&p_ln16, g_ln16);
        cudaGetSymbolAddress((void**)&p_qkv16, g_qkv16);
        cudaGetSymbolAddress((void**)&p_ff16, g_ff16);
        cudaGetSymbolAddress((void**)&p_att16, g_att16);
        cudaGetSymbolAddress((void**)&p_qp16, g_qp16);
        cudaGetSymbolAddress((void**)&p_kpT, g_kpT);
        cudaGetSymbolAddress((void**)&p_vT, g_vT);
        cudaGetSymbolAddress((void**)&p_ctxT, g_ctxT);
        cudaGetSymbolAddress((void**)&p_wqkvT, g_wqkvT);
        cudaGetSymbolAddress((void**)&p_woT, g_woT);
        cudaGetSymbolAddress((void**)&p_wff1T, g_wff1T);
        cudaGetSymbolAddress((void**)&p_wff2T, g_wff2T);
        cudaGetSymbolAddress((void**)&p_projh, g_projh);
        cudaFuncSetAttribute(hgemm<EPI_NONE, 0, __half, 4, 2>,
                             cudaFuncAttributeMaxDynamicSharedMemorySize, SM_44);
        cudaFuncSetAttribute(hgemm<EPI_NONE, 5, __half, 2, 4>,
                             cudaFuncAttributeMaxDynamicSharedMemorySize, SM_24);
        cudaFuncSetAttribute(hgemm<EPI_NONE, 4, float, 4, 2>,
                             cudaFuncAttributeMaxDynamicSharedMemorySize, SM_44);
        cudaFuncSetAttribute(hgemm<EPI_NONE, 2, float, 2, 2>,
                             cudaFuncAttributeMaxDynamicSharedMemorySize, SM_22);
        cudaFuncSetAttribute(hgemm<EPI_DINV, 3, __half, 4, 1>,
                             cudaFuncAttributeMaxDynamicSharedMemorySize, SM_41);
        cudaFuncSetAttribute(hgemm<EPI_ADD, 0, float, 4, 2>,
                             cudaFuncAttributeMaxDynamicSharedMemorySize, SM_44);
        cudaFuncSetAttribute(hgemm<EPI_GELU, 0, __half, 4, 2>,
                             cudaFuncAttributeMaxDynamicSharedMemorySize, SM_44);
    }

    // launch 0: weight transposes + fp16 conversion
    transpose_all<<<dim3(64, 64, 20), 256>>>(Wqkv, Wo, Wff1, Wff2, proj,
                                             p_wqkvT, p_woT, p_wff1T, p_wff2T,
                                             p_projh);
    // launch 1
    copy_kernel<<<(ROWSc * Dc) / 256, 256>>>(x, h);

    for (int l = 0; l < DEPTHc; l++) {
        const __half* pjh = p_projh + (size_t)l * Mc * DHc;

        ln_kernel<<<ROWSc / 8, 256>>>(h, ln1g + l * Dc, ln1b + l * Dc, p_ln16);

        // launch 3 (profiled): QKV
        hgemm<EPI_NONE, 0, __half, 4, 2>
            <<<dim3(QKVW / 128, ROWSc / 128), 256, SM_44>>>(
            p_ln16, Dc, p_wqkvT + (size_t)l * QKVW * Dc, Dc,
            bqkv + l * QKVW, (const float*)0, p_qkv16, QKVW, Dc, 1.0f, 128,
            (float*)0);

        initbuf<<<1, 32>>>(p_hmax);
        diag_kernel<<<ROWSc, 256>>>(p_qkv16, p_qdiag, p_kdiag);

        // dd_q with fused featq epilogue (BM=64, BN=256)
        hgemm<EPI_NONE, 5, __half, 2, 4>
            <<<dim3(1, Nc / 64, BHc), 256, SM_24>>>(
            p_qkv16, QKVW, pjh, DHc, (const float*)0, p_qdiag,
            p_qp16, Mc, DHc, DN_CONST, 256, (float*)0);

        // dd_k (fp32 out + fused global max)
        hgemm<EPI_NONE, 4, float, 4, 2>
            <<<dim3(Mc / 128, Nc / 128, BHc), 256, SM_44>>>(
            p_qkv16, QKVW, pjh, DHc, (const float*)0, (const float*)0,
            p_kp, Mc, DHc, DN_CONST, 128, p_hmax);

        featkT<<<dim3(Nc / 32, Mc / 32, BHc), 256>>>(p_kp, p_kdiag, p_hmax, p_kpT);
        vtrans<<<dim3(Nc / 32, 2, BHc), 256>>>(p_qkv16, p_vT);
        ksum_kernel<<<dim3(Mc / 8, BHc), 256>>>(p_kpT, p_ksum);

        // ctx^T = vT @ kpT^T, split-K=8 disjoint slabs (BM=64)
        hgemm<EPI_NONE, 2, float, 2, 2>
            <<<dim3(Mc / 128, NSPLIT, BHc), 256, SM_22>>>(
            p_vT, Nc, p_kpT, Nc, (const float*)0, (const float*)0,
            p_ctxF, Mc, Nc / NSPLIT, 1.0f, 128, (float*)0);
        cvtctx<<<(BHc * 64 * Mc) / 256, 256>>>(p_ctxF, p_ctxT);

        dinv_kernel<<<(BHc * Nc) / 8, 256>>>(p_qp16, p_ksum, p_dinv);

        // attnout = (qp16 @ ctxT^T) * dinv, BN=64, head-merged fp16
        hgemm<EPI_DINV, 3, __half, 4, 1>
            <<<dim3(1, Nc / 128, BHc), 256, SM_41>>>(
            p_qp16, Mc, p_ctxT, Mc, (const float*)0, p_dinv,
            p_att16, Dc, Mc, 1.0f, 64, (float*)0);

        // Wo + residual
        hgemm<EPI_ADD, 0, float, 4, 2>
            <<<dim3(Dc / 128, ROWSc / 128), 256, SM_44>>>(
            p_att16, Dc, p_woT + (size_t)l * Dc * Dc, Dc,
            bo + l * Dc, h, h, Dc, Dc, 1.0f, 128, (float*)0);

        ln_kernel<<<ROWSc / 8, 256>>>(h, ln2g + l * Dc, ln2b + l * Dc, p_ln16);

        // FF1 + gelu
        hgemm<EPI_GELU, 0, __half, 4, 2>
            <<<dim3(FFc / 128, ROWSc / 128), 256, SM_44>>>(
            p_ln16, Dc, p_wff1T + (size_t)l * FFc * Dc, Dc,
            bff1 + l * FFc, (const float*)0, p_ff16, FFc, Dc, 1.0f, 128,
            (float*)0);

        // FF2 + residual
        hgemm<EPI_ADD, 0, float, 4, 2>
            <<<dim3(Dc / 128, ROWSc / 128), 256, SM_44>>>(
            p_ff16, FFc, p_wff2T + (size_t)l * Dc * FFc, FFc,
            bff2 + l * Dc, h, h, Dc, FFc, 1.0f, 128, (float*)0);
    }
}

// round 15
// speedup vs baseline: 1.3001x; 1.0174x over previous
#include <cuda_runtime.h>
#include <cuda_fp16.h>
#include <math.h>
#include <stdint.h>

// ---------------------------------------------------------------------------
// SpatioTemporalPerformerEncoder — R15: direct-ddT k path (no transpose),
// fused exp+ksum
// ---------------------------------------------------------------------------

#define Bc     2
#define Hc     8
#define Nc     4096
#define Dc     512
#define DHc    64
#define Mc     256
#define FFc    2048
#define DEPTHc 4
#define ROWSc  8192
#define BHc    16
#define QKVW   1536

#define DN_CONST    0.35355339059327373f
#define DIAG_SCALE  0.0625f
#define RATIO_CONST 0.0625f
#define EPSK        1e-4f
#define LNEPS       1e-5f

#define NSPLIT  8

// ------------------------- scratch (device globals) ------------------------
__device__ __half g_ln16 [(size_t)ROWSc * Dc];
__device__ __half g_qkv16[(size_t)ROWSc * QKVW];
__device__ __half g_ff16 [(size_t)ROWSc * FFc];
__device__ __half g_att16[(size_t)ROWSc * Dc];
__device__ float  g_ddT  [(size_t)BHc * Mc * Nc];          // raw dd_k^T
__device__ __half g_qp16 [(size_t)BHc * Nc * Mc];
__device__ __half g_kpT  [(size_t)BHc * Mc * Nc];
__device__ __half g_vT   [(size_t)BHc * 64 * Nc];          // v^T, 64 rows
__device__ float  g_ctxF [(size_t)NSPLIT * BHc * 64 * Mc]; // split-K slabs
__device__ __half g_ctxT [(size_t)BHc * 64 * Mc];
__device__ float  g_ksum [BHc * Mc];
__device__ float  g_qdiag[BHc * Nc];
__device__ float  g_kdiag[BHc * Nc];
__device__ float  g_hmax [BHc];
__device__ float  g_dinv [BHc * Nc];
__device__ __half g_wqkvT[(size_t)DEPTHc * QKVW * Dc];
__device__ __half g_woT  [(size_t)DEPTHc * Dc * Dc];
__device__ __half g_wff1T[(size_t)DEPTHc * FFc * Dc];
__device__ __half g_wff2T[(size_t)DEPTHc * Dc * FFc];
__device__ __half g_projh[(size_t)DEPTHc * Mc * DHc];

// ------------------------------ helpers ------------------------------------
__device__ __forceinline__ uint32_t smem_to_u32(const void* p) {
    uint32_t a;
    asm("{ .reg .u64 t; cvta.to.shared.u64 t, %1; cvt.u32.u64 %0, t; }"
        : "=r"(a) : "l"(p));
    return a;
}
__device__ __forceinline__ uint32_t f2h2(float a, float b) {
    __half2 h = __floats2half2_rn(a, b);
    return *(uint32_t*)&h;
}
__device__ __forceinline__ void cp16(uint32_t dst, const void* src) {
    asm volatile("cp.async.cg.shared.global [%0], [%1], 16;"
                 :: "r"(dst), "l"(src));
}
#define CP_COMMIT() asm volatile("cp.async.commit_group;")
#define CP_WAIT(n)  asm volatile("cp.async.wait_group %0;" :: "n"(n))

__device__ __forceinline__ void ldsm4(uint32_t& r0, uint32_t& r1, uint32_t& r2,
                                      uint32_t& r3, uint32_t a) {
    asm volatile("ldmatrix.sync.aligned.m8n8.x4.shared.b16 {%0,%1,%2,%3}, [%4];"
                 : "=r"(r0), "=r"(r1), "=r"(r2), "=r"(r3) : "r"(a));
}
__device__ __forceinline__ void mma_f16(float c[4], const uint32_t a[4],
                                        const uint32_t b[2]) {
    asm volatile(
        "mma.sync.aligned.m16n8k16.row.col.f32.f16.f16.f32 "
        "{%0,%1,%2,%3}, {%4,%5,%6,%7}, {%8,%9}, {%0,%1,%2,%3};"
        : "+f"(c[0]), "+f"(c[1]), "+f"(c[2]), "+f"(c[3])
        : "r"(a[0]), "r"(a[1]), "r"(a[2]), "r"(a[3]), "r"(b[0]), "r"(b[1]));
}
__device__ __forceinline__ void atomicMaxF(float* a, float v) {
    if (v >= 0.0f) atomicMax((int*)a, __float_as_int(v));
    else atomicMin((unsigned int*)a, __float_as_uint(v));
}

// ------------------------- fp16 tensor-core GEMM ---------------------------
// C = scale*(A[M,K]h @ B[N,K]h^T) + epilogue. BK=32, 256 threads (8 warps 2x4),
// warp tile (MT*16)x(NT*16), BM=MT*32, BN=NT*64. 3-stage cp.async.
// BHM 0: plain. 2: ctx (per-bh, split-K slab via blockIdx.y, fp32 slab out).
// 3: attnout (per-bh, dinv row scale via R, head-merged out).
// 5: dd_q fused featq (per-bh, qdiag via R, row-max+exp epilogue, fp16 out).
// 6: dd_k^T direct (A=proj, B=k rows; fp32 out [m][n] + fused global max).
#define EPI_NONE 0
#define EPI_GELU 1
#define EPI_ADD  2
#define EPI_DINV 3

template <int EPI, int BHM, typename OutT, int MT, int NT>
__global__ __launch_bounds__(256, 2)
void hgemm(const __half* __restrict__ A, int lda,
           const __half* __restrict__ Bh, int ldb,
           const float* __restrict__ bias, const float* __restrict__ R,
           OutT* __restrict__ C, int ldc, int K, float scale,
           int nvalid, float* __restrict__ hmaxp) {
    extern __shared__ __align__(16) char smem_dyn[];
    uint32_t sBase = smem_to_u32(smem_dyn);

    const int BM = MT * 32, BN = NT * 64;
    const uint32_t ASZ = (uint32_t)BM * 80;
    const uint32_t STG = (uint32_t)(BM + BN) * 80;

    int m0, n0;
    if (BHM == 2) {
        int z = blockIdx.z, s = blockIdx.y;
        A += (size_t)z * BM * lda + (size_t)s * K;
        Bh += (size_t)z * Mc * ldb + (size_t)s * K;
        C += ((size_t)s * BHc + z) * BM * ldc;
        m0 = 0;
        n0 = blockIdx.x * BN;
    } else {
        if (BHM == 5) {
            int z = blockIdx.z;
            A += (size_t)(z >> 3) * Nc * lda + (size_t)(z & 7) * DHc;
            C += (size_t)z * Nc * ldc;
            R += (size_t)z * Nc;
        }
        if (BHM == 6) {
            int z = blockIdx.z;
            Bh += (size_t)(z >> 3) * Nc * ldb + (size_t)(z & 7) * DHc + Dc;
            C += (size_t)z * Mc * ldc;
        }
        if (BHM == 3) {
            int z = blockIdx.z;
            A += (size_t)z * Nc * lda;
            Bh += (size_t)z * 64 * ldb;
            C += (size_t)(z >> 3) * Nc * Dc + (size_t)(z & 7) * DHc;
            R += (size_t)z * Nc;
        }
        m0 = blockIdx.y * BM;
        n0 = blockIdx.x * BN;
    }

    int tid = threadIdx.x, lane = tid & 31, warp = tid >> 5;
    int wm = warp >> 2, wn = warp & 3;

    int rowC = tid >> 2, cA = (tid & 3) * 8;
    uint32_t sOff = ((uint32_t)rowC * 40 + cA) * 2;
    uint32_t fOff = (((lane & 15) * 40) + (lane >> 4) * 8) * 2;

    float c[MT][2 * NT][4];
#pragma unroll
    for (int i = 0; i < MT; i++)
#pragma unroll
        for (int j = 0; j < 2 * NT; j++)
#pragma unroll
            for (int l = 0; l < 4; l++) c[i][j][l] = 0.0f;

#define ISSUE(t, buf)                                                         \
    {                                                                         \
        int k0 = (t) * 32;                                                    \
        _Pragma("unroll")                                                     \
        for (int p = 0; p < MT / 2; p++)                                      \
            cp16(sBase + (buf) * STG + sOff + p * 5120,                       \
                 A + (size_t)(m0 + rowC + p * 64) * lda + k0 + cA);           \
        _Pragma("unroll")                                                     \
        for (int p = 0; p < NT; p++)                                          \
            cp16(sBase + (buf) * STG + ASZ + sOff + p * 5120,                 \
                 Bh + (size_t)(n0 + rowC + p * 64) * ldb + k0 + cA);          \
        CP_COMMIT();                                                          \
    }

    int T = K >> 5;                 // all call sites have K >= 64 (T >= 2)
    ISSUE(0, 0)
    ISSUE(1, 1)
    int buf = 0;
    for (int t = 0; t < T; t++) {
        if (t == T - 1) { CP_WAIT(0); } else { CP_WAIT(1); }
        __syncthreads();

        uint32_t aTile = sBase + buf * STG;
        uint32_t bTile = aTile + ASZ;
#pragma unroll
        for (int kk = 0; kk < 2; kk++) {
            int k16 = kk * 16;
            uint32_t af[MT][4], bf[2 * NT][2];
#pragma unroll
            for (int mi = 0; mi < MT; mi++)
                ldsm4(af[mi][0], af[mi][1], af[mi][2], af[mi][3],
                      aTile + ((wm * MT * 16 + mi * 16) * 40 + k16) * 2 + fOff);
#pragma unroll
            for (int p = 0; p < NT; p++) {
                uint32_t r0, r1, r2, r3;
                ldsm4(r0, r1, r2, r3,
                      bTile + ((wn * NT * 16 + p * 16) * 40 + k16) * 2 + fOff);
                bf[2 * p][0] = r0; bf[2 * p][1] = r2;
                bf[2 * p + 1][0] = r1; bf[2 * p + 1][1] = r3;
            }
#pragma unroll
            for (int mi = 0; mi < MT; mi++)
#pragma unroll
                for (int ni = 0; ni < 2 * NT; ni++)
                    mma_f16(c[mi][ni], af[mi], bf[ni]);
        }
        if (t + 2 < T) {
            int nb = buf + 2; if (nb >= 3) nb -= 3;
            ISSUE(t + 2, nb)
        }
        buf = (buf + 1 == 3) ? 0 : buf + 1;
    }
#undef ISSUE

    int g = lane >> 2, tig = lane & 3;

    if (BHM == 5) {
        // fused FAVOR+ q-feature epilogue: row max + exp, fp16 out
        float* rowred = (float*)smem_dyn;
        __syncthreads();
        if (tid < BM) rowred[tid] = -1e30f;
        __syncthreads();
        float lm[MT][2];
#pragma unroll
        for (int mi = 0; mi < MT; mi++) { lm[mi][0] = -1e30f; lm[mi][1] = -1e30f; }
#pragma unroll
        for (int mi = 0; mi < MT; mi++)
#pragma unroll
            for (int ni = 0; ni < 2 * NT; ni++) {
                lm[mi][0] = fmaxf(lm[mi][0], fmaxf(c[mi][ni][0], c[mi][ni][1]));
                lm[mi][1] = fmaxf(lm[mi][1], fmaxf(c[mi][ni][2], c[mi][ni][3]));
            }
#pragma unroll
        for (int mi = 0; mi < MT; mi++)
#pragma unroll
            for (int half = 0; half < 2; half++) {
                int rl = wm * MT * 16 + mi * 16 + g + half * 8;
                atomicMaxF(&rowred[rl], lm[mi][half] * scale);
            }
        __syncthreads();
        float sub[MT][2];
#pragma unroll
        for (int mi = 0; mi < MT; mi++)
#pragma unroll
            for (int half = 0; half < 2; half++) {
                int rl = wm * MT * 16 + mi * 16 + g + half * 8;
                sub[mi][half] = R[m0 + rl] + rowred[rl];
            }
#pragma unroll
        for (int mi = 0; mi < MT; mi++)
#pragma unroll
            for (int ni = 0; ni < 2 * NT; ni++) {
                int col = wn * NT * 16 + ni * 8 + 2 * tig;
#pragma unroll
                for (int half = 0; half < 2; half++) {
                    int r = m0 + wm * MT * 16 + mi * 16 + g + half * 8;
                    float s_ = sub[mi][half];
                    float v0 = RATIO_CONST *
                               (expf(c[mi][ni][half * 2 + 0] * scale - s_) + EPSK);
                    float v1 = RATIO_CONST *
                               (expf(c[mi][ni][half * 2 + 1] * scale - s_) + EPSK);
                    __half2 hv = __floats2half2_rn(v0, v1);
                    *(__half2*)&((__half*)C)[(size_t)r * ldc + col] = hv;
                }
            }
        return;
    }

    // generic epilogue
    float tm = -1e30f;
#pragma unroll
    for (int mi = 0; mi < MT; mi++) {
#pragma unroll
        for (int ni = 0; ni < 2 * NT; ni++) {
            int rl = wm * MT * 16 + mi * 16 + g;
            int cl = wn * NT * 16 + ni * 8 + 2 * tig;
            if (cl >= nvalid) continue;
            int col = n0 + cl;
#pragma unroll
            for (int half = 0; half < 2; half++) {
                int r = m0 + rl + half * 8;
                float v0 = c[mi][ni][half * 2 + 0] * scale;
                float v1 = c[mi][ni][half * 2 + 1] * scale;
                if (BHM == 6) tm = fmaxf(tm, fmaxf(v0, v1));
                if (bias) { v0 += bias[col]; v1 += bias[col + 1]; }
                if (EPI == EPI_GELU) {
                    v0 = 0.5f * v0 * (1.0f + erff(v0 * 0.70710678118654752f));
                    v1 = 0.5f * v1 * (1.0f + erff(v1 * 0.70710678118654752f));
                }
                if (EPI == EPI_ADD) {
                    v0 += R[(size_t)r * ldc + col];
                    v1 += R[(size_t)r * ldc + col + 1];
                }
                if (EPI == EPI_DINV) {
                    float di = R[r];
                    v0 *= di; v1 *= di;
                }
                if (sizeof(OutT) == 2) {
                    __half2 hv = __floats2half2_rn(v0, v1);
                    *(__half2*)&((__half*)C)[(size_t)r * ldc + col] = hv;
                } else {
                    float2 o = {v0, v1};
                    *(float2*)&((float*)C)[(size_t)r * ldc + col] = o;
                }
            }
        }
    }
    if (BHM == 6) {
#pragma unroll
        for (int o = 16; o > 0; o >>= 1)
            tm = fmaxf(tm, __shfl_xor_sync(0xffffffffu, tm, o));
        if (lane == 0) atomicMaxF(&hmaxp[blockIdx.z], tm);
    }
}

// --------------- batched weight transpose + convert to fp16 ----------------
__global__ __launch_bounds__(256)
void transpose_all(const float* __restrict__ Wqkv, const float* __restrict__ Wo,
                   const float* __restrict__ Wff1, const float* __restrict__ Wff2,
                   const float* __restrict__ proj,
                   __half* __restrict__ qkvT, __half* __restrict__ woT,
                   __half* __restrict__ ff1T, __half* __restrict__ ff2T,
                   __half* __restrict__ projh) {
    __shared__ float tbuf[32][33];
    int z = blockIdx.z;
    if (z >= 16) {
        int l = z - 16;
        int idx = (blockIdx.y * gridDim.x + blockIdx.x) * 256 + threadIdx.x;
        if (idx < Mc * DHc)
            projh[(size_t)l * Mc * DHc + idx] =
                __float2half(proj[(size_t)l * Mc * DHc + idx]);
        return;
    }
    int type = z & 3, l = z >> 2;
    int K, N;
    const float* in;
    __half* out;
    if (type == 0)      { K = Dc;  N = QKVW; in = Wqkv + (size_t)l * Dc * QKVW; out = qkvT + (size_t)l * QKVW * Dc; }
    else if (type == 1) { K = Dc;  N = Dc;   in = Wo   + (size_t)l * Dc * Dc;   out = woT  + (size_t)l * Dc * Dc; }
    else if (type == 2) { K = Dc;  N = FFc;  in = Wff1 + (size_t)l * Dc * FFc;  out = ff1T + (size_t)l * FFc * Dc; }
    else                { K = FFc; N = Dc;   in = Wff2 + (size_t)l * FFc * Dc;  out = ff2T + (size_t)l * Dc * FFc; }

    int nx = blockIdx.x * 32, kx = blockIdx.y * 32;
    if (nx >= N || kx >= K) return;
    int tx = threadIdx.x & 31, ty = threadIdx.x >> 5;
#pragma unroll
    for (int i = 0; i < 4; i++)
        tbuf[ty + i * 8][tx] = in[(size_t)(kx + ty + i * 8) * N + nx + tx];
    __syncthreads();
#pragma unroll
    for (int i = 0; i < 4; i++)
        out[(size_t)(nx + ty + i * 8) * K + kx + tx] =
            __float2half(tbuf[tx][ty + i * 8]);
}

// ------------------------------ copy x -> h --------------------------------
__global__ void copy_kernel(const float* __restrict__ x, float* __restrict__ h) {
    size_t i = (size_t)blockIdx.x * 256 + threadIdx.x;
    h[i] = x[i];
}

// ------------------- layernorm: warp per row (fp16 out) --------------------
__global__ __launch_bounds__(256)
void ln_kernel(const float* __restrict__ x, const float* __restrict__ g,
               const float* __restrict__ b, __half* __restrict__ out) {
    int w = threadIdx.x >> 5, lane = threadIdx.x & 31;
    int row = blockIdx.x * 8 + w;
    const float4* xr = (const float4*)(x + (size_t)row * Dc);
    float4 v[4];
    float s = 0.0f;
#pragma unroll
    for (int i = 0; i < 4; i++) {
        v[i] = xr[lane + i * 32];
        s += (v[i].x + v[i].y) + (v[i].z + v[i].w);
    }
#pragma unroll
    for (int o = 16; o > 0; o >>= 1) s += __shfl_xor_sync(0xffffffffu, s, o);
    float mu = s * (1.0f / Dc);
    float var = 0.0f;
#pragma unroll
    for (int i = 0; i < 4; i++) {
        v[i].x -= mu; v[i].y -= mu; v[i].z -= mu; v[i].w -= mu;
        var += v[i].x * v[i].x + v[i].y * v[i].y +
               v[i].z * v[i].z + v[i].w * v[i].w;
    }
#pragma unroll
    for (int o = 16; o > 0; o >>= 1) var += __shfl_xor_sync(0xffffffffu, var, o);
    float rs = rsqrtf(var * (1.0f / Dc) + LNEPS);
    const float4* gp = (const float4*)g;
    const float4* bp = (const float4*)b;
    __half* orow = out + (size_t)row * Dc;
#pragma unroll
    for (int i = 0; i < 4; i++) {
        float4 gg = gp[lane + i * 32], bb = bp[lane + i * 32];
        uint2 o2;
        o2.x = f2h2(v[i].x * rs * gg.x + bb.x, v[i].y * rs * gg.y + bb.y);
        o2.y = f2h2(v[i].z * rs * gg.z + bb.z, v[i].w * rs * gg.w + bb.w);
        *(uint2*)&orow[(lane + i * 32) * 4] = o2;
    }
}

// ------------------- diag: per-(bh,row) 0.5*dn^2*|q|^2, |k|^2 --------------
__global__ __launch_bounds__(256)
void diag_kernel(const __half* __restrict__ qkv, float* __restrict__ qdiag,
                 float* __restrict__ kdiag) {
    int row = blockIdx.x;
    int w = threadIdx.x >> 5, lane = threadIdx.x & 31;
    const __half* base = qkv + (size_t)row * QKVW + w * DHc;
    float q0 = __half2float(base[lane]), q1 = __half2float(base[lane + 32]);
    float k0 = __half2float(base[Dc + lane]),
          k1 = __half2float(base[Dc + lane + 32]);
    float sq = q0 * q0 + q1 * q1;
    float sk = k0 * k0 + k1 * k1;
#pragma unroll
    for (int o = 16; o > 0; o >>= 1) {
        sq += __shfl_down_sync(0xffffffffu, sq, o);
        sk += __shfl_down_sync(0xffffffffu, sk, o);
    }
    if (lane == 0) {
        int bh = (row >> 12) * Hc + w;
        int n = row & (Nc - 1);
        qdiag[(size_t)bh * Nc + n] = sq * DIAG_SCALE;
        kdiag[(size_t)bh * Nc + n] = sk * DIAG_SCALE;
    }
}

// ------- k features: exp over ddT rows + fused ksum (warp per row) ---------
__global__ __launch_bounds__(256)
void featk_exp(const float* __restrict__ ddT, const float* __restrict__ kdiag,
               const float* __restrict__ hmax, __half* __restrict__ kpT,
               float* __restrict__ ksum) {
    int bh = blockIdx.y;
    int m = blockIdx.x * 8 + (threadIdx.x >> 5);
    int lane = threadIdx.x & 31;
    float hm = hmax[bh];
    const float4* src = (const float4*)(ddT + ((size_t)bh * Mc + m) * Nc);
    const float4* kd4 = (const float4*)(kdiag + (size_t)bh * Nc);
    __half2* dst = (__half2*)(kpT + ((size_t)bh * Mc + m) * Nc);
    float s = 0.0f;
    for (int i = lane; i < Nc / 4; i += 32) {
        float4 v = src[i];
        float4 kd = kd4[i];
        float e0 = RATIO_CONST * (expf(v.x - kd.x - hm) + EPSK);
        float e1 = RATIO_CONST * (expf(v.y - kd.y - hm) + EPSK);
        float e2 = RATIO_CONST * (expf(v.z - kd.z - hm) + EPSK);
        float e3 = RATIO_CONST * (expf(v.w - kd.w - hm) + EPSK);
        s += (e0 + e1) + (e2 + e3);
        dst[2 * i]     = __floats2half2_rn(e0, e1);
        dst[2 * i + 1] = __floats2half2_rn(e2, e3);
    }
#pragma unroll
    for (int o = 16; o > 0; o >>= 1) s += __shfl_down_sync(0xffffffffu, s, o);
    if (lane == 0) ksum[bh * Mc + m] = s;
}

// -------------------- v transpose: vT16 [bh][d][n] (64 rows) ---------------
__global__ __launch_bounds__(256)
void vtrans(const __half* __restrict__ qkv, __half* __restrict__ vT) {
    __shared__ __half tile[32][33];
    int z = blockIdx.z;
    int b = z >> 3, h = z & 7;
    int n0 = blockIdx.x * 32, d0 = blockIdx.y * 32;
    int tx = threadIdx.x & 31, ty = threadIdx.x >> 5;
#pragma unroll
    for (int i = 0; i < 4; i++)
        tile[ty + i * 8][tx] =
            qkv[((size_t)(b * Nc + n0 + ty + i * 8)) * QKVW + 2 * Dc + h * DHc +
                d0 + tx];
    __syncthreads();
#pragma unroll
    for (int i = 0; i < 4; i++)
        vT[((size_t)z * 64 + d0 + ty + i * 8) * Nc + n0 + tx] =
            tile[tx][ty + i * 8];
}

// ------------------------ init hmax (-inf), tiny ---------------------------
__global__ void initbuf(float* __restrict__ hmax) {
    if (threadIdx.x < BHc) hmax[threadIdx.x] = -1e30f;
}

// -------------- reduce ctx slabs + convert -> ctxT16 -----------------------
__global__ void cvtctx(const float* __restrict__ ctxF, __half* __restrict__ ctxT) {
    size_t i = (size_t)blockIdx.x * 256 + threadIdx.x;     // BHc*64*Mc elems
    float s = 0.0f;
#pragma unroll
    for (int sl = 0; sl < NSPLIT; sl++)
        s += ctxF[(size_t)sl * BHc * 64 * Mc + i];
    ctxT[i] = __float2half(s);
}

// ------------------------------- d_inv -------------------------------------
__global__ __launch_bounds__(256)
void dinv_kernel(const __half* __restrict__ qp16, const float* __restrict__ ksum,
                 float* __restrict__ dinv) {
    int w = threadIdx.x >> 5, lane = threadIdx.x & 31;
    int rr = blockIdx.x * 8 + w;
    int bh = rr >> 12;
    uint4 u = ((const uint4*)(qp16 + (size_t)rr * Mc))[lane];
    const float* ks = ksum + bh * Mc + lane * 8;
    __half2* hp = (__half2*)&u;
    float s = 0.0f;
#pragma unroll
    for (int j = 0; j < 4; j++) {
        float2 f = __half22float2(hp[j]);
        s += f.x * ks[2 * j] + f.y * ks[2 * j + 1];
    }
#pragma unroll
    for (int o = 16; o > 0; o >>= 1) s += __shfl_down_sync(0xffffffffu, s, o);
    if (lane == 0) dinv[rr] = 1.0f / s;
}

// ------------------------------- launch ------------------------------------
#define SM_44 61440   // 3*(128+128)*80
#define SM_24 76800   // 3*(64+256)*80
#define SM_22 46080   // 3*(64+128)*80
#define SM_41 46080   // 3*(128+64)*80

extern "C" void kernel_launch(void* const* d_in, const int* in_sizes, int n_in,
                              void* d_out, int out_size) {
    (void)in_sizes; (void)n_in; (void)out_size;
    const float* x    = (const float*)d_in[0];
    const float* proj = (const float*)d_in[1];
    const float* ln1g = (const float*)d_in[2];
    const float* ln1b = (const float*)d_in[3];
    const float* Wqkv = (const float*)d_in[4];
    const float* bqkv = (const float*)d_in[5];
    const float* Wo   = (const float*)d_in[6];
    const float* bo   = (const float*)d_in[7];
    const float* ln2g = (const float*)d_in[8];
    const float* ln2b = (const float*)d_in[9];
    const float* Wff1 = (const float*)d_in[10];
    const float* bff1 = (const float*)d_in[11];
    const float* Wff2 = (const float*)d_in[12];
    const float* bff2 = (const float*)d_in[13];
    float* h = (float*)d_out;

    static float *p_ddT = 0, *p_ctxF = 0, *p_ksum = 0, *p_qdiag = 0,
                 *p_kdiag = 0, *p_hmax = 0, *p_dinv = 0;
    static __half *p_ln16 = 0, *p_qkv16 = 0, *p_ff16 = 0, *p_att16 = 0,
                  *p_qp16 = 0, *p_kpT = 0, *p_vT = 0, *p_ctxT = 0,
                  *p_wqkvT = 0, *p_woT = 0, *p_wff1T = 0, *p_wff2T = 0,
                  *p_projh = 0;
    if (!p_ddT) {
        cudaGetSymbolAddress((void**)&p_ddT, g_ddT);
        cudaGetSymbolAddress((void**)&p_ctxF, g_ctxF);
        cudaGetSymbolAddress((void**)&p_ksum, g_ksum);
        cudaGetSymbolAddress((void**)&p_qdiag, g_qdiag);
        cudaGetSymbolAddress((void**)&p_kdiag, g_kdiag);
        cudaGetSymbolAddress((void**)&p_hmax, g_hmax);
        cudaGetSymbolAddress((void**)&p_dinv, g_dinv);
        cudaGetSymbolAddress((void**)&p_ln16, g_ln16);
        cudaGetSymbolAddress((void**)&p_qkv16, g_qkv16);
        cudaGetSymbolAddress((void**)&p_ff16, g_ff16);
        cudaGetSymbolAddress((void**)&p_att16, g_att16);
        cudaGetSymbolAddress((void**)&p_qp16, g_qp16);
        cudaGetSymbolAddress((void**)&p_kpT, g_kpT);
        cudaGetSymbolAddress((void**)&p_vT, g_vT);
        cudaGetSymbolAddress((void**)&p_ctxT, g_ctxT);
        cudaGetSymbolAddress((void**)&p_wqkvT, g_wqkvT);
        cudaGetSymbolAddress((void**)&p_woT, g_woT);
        cudaGetSymbolAddress((void**)&p_wff1T, g_wff1T);
        cudaGetSymbolAddress((void**)&p_wff2T, g_wff2T);
        cudaGetSymbolAddress((void**)&p_projh, g_projh);
        cudaFuncSetAttribute(hgemm<EPI_NONE, 0, __half, 4, 2>,
                             cudaFuncAttributeMaxDynamicSharedMemorySize, SM_44);
        cudaFuncSetAttribute(hgemm<EPI_NONE, 5, __half, 2, 4>,
                             cudaFuncAttributeMaxDynamicSharedMemorySize, SM_24);
        cudaFuncSetAttribute(hgemm<EPI_NONE, 6, float, 4, 2>,
                             cudaFuncAttributeMaxDynamicSharedMemorySize, SM_44);
        cudaFuncSetAttribute(hgemm<EPI_NONE, 2, float, 2, 2>,
                             cudaFuncAttributeMaxDynamicSharedMemorySize, SM_22);
        cudaFuncSetAttribute(hgemm<EPI_DINV, 3, __half, 4, 1>,
                             cudaFuncAttributeMaxDynamicSharedMemorySize, SM_41);
        cudaFuncSetAttribute(hgemm<EPI_ADD, 0, float, 4, 2>,
                             cudaFuncAttributeMaxDynamicSharedMemorySize, SM_44);
        cudaFuncSetAttribute(hgemm<EPI_GELU, 0, __half, 4, 2>,
                             cudaFuncAttributeMaxDynamicSharedMemorySize, SM_44);
    }

    // launch 0: weight transposes + fp16 conversion
    transpose_all<<<dim3(64, 64, 20), 256>>>(Wqkv, Wo, Wff1, Wff2, proj,
                                             p_wqkvT, p_woT, p_wff1T, p_wff2T,
                                             p_projh);
    // launch 1
    copy_kernel<<<(ROWSc * Dc) / 256, 256>>>(x, h);

    for (int l = 0; l < DEPTHc; l++) {
        const __half* pjh = p_projh + (size_t)l * Mc * DHc;

        ln_kernel<<<ROWSc / 8, 256>>>(h, ln1g + l * Dc, ln1b + l * Dc, p_ln16);

        // launch 3 (profiled): QKV
        hgemm<EPI_NONE, 0, __half, 4, 2>
            <<<dim3(QKVW / 128, ROWSc / 128), 256, SM_44>>>(
            p_ln16, Dc, p_wqkvT + (size_t)l * QKVW * Dc, Dc,
            bqkv + l * QKVW, (const float*)0, p_qkv16, QKVW, Dc, 1.0f, 128,
            (float*)0);

        initbuf<<<1, 32>>>(p_hmax);
        diag_kernel<<<ROWSc, 256>>>(p_qkv16, p_qdiag, p_kdiag);

        // dd_q with fused featq epilogue (BM=64, BN=256)
        hgemm<EPI_NONE, 5, __half, 2, 4>
            <<<dim3(1, Nc / 64, BHc), 256, SM_24>>>(
            p_qkv16, QKVW, pjh, DHc, (const float*)0, p_qdiag,
            p_qp16, Mc, DHc, DN_CONST, 256, (float*)0);

        // dd_k^T direct: A=proj [256x64], B=k rows -> ddT [bh][m][n] + hmax
        hgemm<EPI_NONE, 6, float, 4, 2>
            <<<dim3(Nc / 128, Mc / 128, BHc), 256, SM_44>>>(
            pjh, DHc, p_qkv16, QKVW, (const float*)0, (const float*)0,
            p_ddT, Nc, DHc, DN_CONST, 128, p_hmax);

        // exp + fused ksum (warp per m row)
        featk_exp<<<dim3(Mc / 8, BHc), 256>>>(p_ddT, p_kdiag, p_hmax,
                                              p_kpT, p_ksum);

        vtrans<<<dim3(Nc / 32, 2, BHc), 256>>>(p_qkv16, p_vT);

        // ctx^T = vT @ kpT^T, split-K=8 disjoint slabs (BM=64)
        hgemm<EPI_NONE, 2, float, 2, 2>
            <<<dim3(Mc / 128, NSPLIT, BHc), 256, SM_22>>>(
            p_vT, Nc, p_kpT, Nc, (const float*)0, (const float*)0,
            p_ctxF, Mc, Nc / NSPLIT, 1.0f, 128, (float*)0);
        cvtctx<<<(BHc * 64 * Mc) / 256, 256>>>(p_ctxF, p_ctxT);

        dinv_kernel<<<(BHc * Nc) / 8, 256>>>(p_qp16, p_ksum, p_dinv);

        // attnout = (qp16 @ ctxT^T) * dinv, BN=64, head-merged fp16
        hgemm<EPI_DINV, 3, __half, 4, 1>
            <<<dim3(1, Nc / 128, BHc), 256, SM_41>>>(
            p_qp16, Mc, p_ctxT, Mc, (const float*)0, p_dinv,
            p_att16, Dc, Mc, 1.0f, 64, (float*)0);

        // Wo + residual
        hgemm<EPI_ADD, 0, float, 4, 2>
            <<<dim3(Dc / 128, ROWSc / 128), 256, SM_44>>>(
            p_att16, Dc, p_woT + (size_t)l * Dc * Dc, Dc,
            bo + l * Dc, h, h, Dc, Dc, 1.0f, 128, (float*)0);

        ln_kernel<<<ROWSc / 8, 256>>>(h, ln2g + l * Dc, ln2b + l * Dc, p_ln16);

        // FF1 + gelu
        hgemm<EPI_GELU, 0, __half, 4, 2>
            <<<dim3(FFc / 128, ROWSc / 128), 256, SM_44>>>(
            p_ln16, Dc, p_wff1T + (size_t)l * FFc * Dc, Dc,
            bff1 + l * FFc, (const float*)0, p_ff16, FFc, Dc, 1.0f, 128,
            (float*)0);

        // FF2 + residual
        hgemm<EPI_ADD, 0, float, 4, 2>
            <<<dim3(Dc / 128, ROWSc / 128), 256, SM_44>>>(
            p_ff16, FFc, p_wff2T + (size_t)l * Dc * FFc, FFc,
            bff2 + l * Dc, h, h, Dc, FFc, 1.0f, 128, (float*)0);
    }
}

// round 16
// speedup vs baseline: 1.3090x; 1.0069x over previous
#include <cuda_runtime.h>
#include <cuda_fp16.h>
#include <math.h>
#include <stdint.h>

// ---------------------------------------------------------------------------
// SpatioTemporalPerformerEncoder — R16: launch consolidation (merged small
// kernels; GEMM paths identical to R15)
// ---------------------------------------------------------------------------

#define Bc     2
#define Hc     8
#define Nc     4096
#define Dc     512
#define DHc    64
#define Mc     256
#define FFc    2048
#define DEPTHc 4
#define ROWSc  8192
#define BHc    16
#define QKVW   1536

#define DN_CONST    0.35355339059327373f
#define DIAG_SCALE  0.0625f
#define RATIO_CONST 0.0625f
#define EPSK        1e-4f
#define LNEPS       1e-5f

#define NSPLIT  8

// ------------------------- scratch (device globals) ------------------------
__device__ __half g_ln16 [(size_t)ROWSc * Dc];
__device__ __half g_qkv16[(size_t)ROWSc * QKVW];
__device__ __half g_ff16 [(size_t)ROWSc * FFc];
__device__ __half g_att16[(size_t)ROWSc * Dc];
__device__ float  g_ddT  [(size_t)BHc * Mc * Nc];          // raw dd_k^T
__device__ __half g_qp16 [(size_t)BHc * Nc * Mc];
__device__ __half g_kpT  [(size_t)BHc * Mc * Nc];
__device__ __half g_vT   [(size_t)BHc * 64 * Nc];          // v^T, 64 rows
__device__ float  g_ctxF [(size_t)NSPLIT * BHc * 64 * Mc]; // split-K slabs
__device__ __half g_ctxT [(size_t)BHc * 64 * Mc];
__device__ float  g_ksum [BHc * Mc];
__device__ float  g_qdiag[BHc * Nc];
__device__ float  g_kdiag[BHc * Nc];
__device__ float  g_hmax [BHc];
__device__ float  g_dinv [BHc * Nc];
__device__ __half g_wqkvT[(size_t)DEPTHc * QKVW * Dc];
__device__ __half g_woT  [(size_t)DEPTHc * Dc * Dc];
__device__ __half g_wff1T[(size_t)DEPTHc * FFc * Dc];
__device__ __half g_wff2T[(size_t)DEPTHc * Dc * FFc];
__device__ __half g_projh[(size_t)DEPTHc * Mc * DHc];

// ------------------------------ helpers ------------------------------------
__device__ __forceinline__ uint32_t smem_to_u32(const void* p) {
    uint32_t a;
    asm("{ .reg .u64 t; cvta.to.shared.u64 t, %1; cvt.u32.u64 %0, t; }"
        : "=r"(a) : "l"(p));
    return a;
}
__device__ __forceinline__ uint32_t f2h2(float a, float b) {
    __half2 h = __floats2half2_rn(a, b);
    return *(uint32_t*)&h;
}
__device__ __forceinline__ void cp16(uint32_t dst, const void* src) {
    asm volatile("cp.async.cg.shared.global [%0], [%1], 16;"
                 :: "r"(dst), "l"(src));
}
#define CP_COMMIT() asm volatile("cp.async.commit_group;")
#define CP_WAIT(n)  asm volatile("cp.async.wait_group %0;" :: "n"(n))

__device__ __forceinline__ void ldsm4(uint32_t& r0, uint32_t& r1, uint32_t& r2,
                                      uint32_t& r3, uint32_t a) {
    asm volatile("ldmatrix.sync.aligned.m8n8.x4.shared.b16 {%0,%1,%2,%3}, [%4];"
                 : "=r"(r0), "=r"(r1), "=r"(r2), "=r"(r3) : "r"(a));
}
__device__ __forceinline__ void mma_f16(float c[4], const uint32_t a[4],
                                        const uint32_t b[2]) {
    asm volatile(
        "mma.sync.aligned.m16n8k16.row.col.f32.f16.f16.f32 "
        "{%0,%1,%2,%3}, {%4,%5,%6,%7}, {%8,%9}, {%0,%1,%2,%3};"
        : "+f"(c[0]), "+f"(c[1]), "+f"(c[2]), "+f"(c[3])
        : "r"(a[0]), "r"(a[1]), "r"(a[2]), "r"(a[3]), "r"(b[0]), "r"(b[1]));
}
__device__ __forceinline__ void atomicMaxF(float* a, float v) {
    if (v >= 0.0f) atomicMax((int*)a, __float_as_int(v));
    else atomicMin((unsigned int*)a, __float_as_uint(v));
}

// ------------------------- fp16 tensor-core GEMM ---------------------------
// C = scale*(A[M,K]h @ B[N,K]h^T) + epilogue. BK=32, 256 threads (8 warps 2x4),
// warp tile (MT*16)x(NT*16), BM=MT*32, BN=NT*64. 3-stage cp.async.
// BHM 0: plain. 2: ctx (per-bh, split-K slab via blockIdx.y, fp32 slab out).
// 3: attnout (per-bh, dinv row scale via R, head-merged out).
// 5: dd_q fused featq (per-bh, qdiag via R, row-max+exp epilogue, fp16 out).
// 6: dd_k^T direct (A=proj, B=k rows; fp32 out [m][n] + fused global max).
#define EPI_NONE 0
#define EPI_GELU 1
#define EPI_ADD  2
#define EPI_DINV 3

template <int EPI, int BHM, typename OutT, int MT, int NT>
__global__ __launch_bounds__(256, 2)
void hgemm(const __half* __restrict__ A, int lda,
           const __half* __restrict__ Bh, int ldb,
           const float* __restrict__ bias, const float* __restrict__ R,
           OutT* __restrict__ C, int ldc, int K, float scale,
           int nvalid, float* __restrict__ hmaxp) {
    extern __shared__ __align__(16) char smem_dyn[];
    uint32_t sBase = smem_to_u32(smem_dyn);

    const int BM = MT * 32, BN = NT * 64;
    const uint32_t ASZ = (uint32_t)BM * 80;
    const uint32_t STG = (uint32_t)(BM + BN) * 80;

    int m0, n0;
    if (BHM == 2) {
        int z = blockIdx.z, s = blockIdx.y;
        A += (size_t)z * BM * lda + (size_t)s * K;
        Bh += (size_t)z * Mc * ldb + (size_t)s * K;
        C += ((size_t)s * BHc + z) * BM * ldc;
        m0 = 0;
        n0 = blockIdx.x * BN;
    } else {
        if (BHM == 5) {
            int z = blockIdx.z;
            A += (size_t)(z >> 3) * Nc * lda + (size_t)(z & 7) * DHc;
            C += (size_t)z * Nc * ldc;
            R += (size_t)z * Nc;
        }
        if (BHM == 6) {
            int z = blockIdx.z;
            Bh += (size_t)(z >> 3) * Nc * ldb + (size_t)(z & 7) * DHc + Dc;
            C += (size_t)z * Mc * ldc;
        }
        if (BHM == 3) {
            int z = blockIdx.z;
            A += (size_t)z * Nc * lda;
            Bh += (size_t)z * 64 * ldb;
            C += (size_t)(z >> 3) * Nc * Dc + (size_t)(z & 7) * DHc;
            R += (size_t)z * Nc;
        }
        m0 = blockIdx.y * BM;
        n0 = blockIdx.x * BN;
    }

    int tid = threadIdx.x, lane = tid & 31, warp = tid >> 5;
    int wm = warp >> 2, wn = warp & 3;

    int rowC = tid >> 2, cA = (tid & 3) * 8;
    uint32_t sOff = ((uint32_t)rowC * 40 + cA) * 2;
    uint32_t fOff = (((lane & 15) * 40) + (lane >> 4) * 8) * 2;

    float c[MT][2 * NT][4];
#pragma unroll
    for (int i = 0; i < MT; i++)
#pragma unroll
        for (int j = 0; j < 2 * NT; j++)
#pragma unroll
            for (int l = 0; l < 4; l++) c[i][j][l] = 0.0f;

#define ISSUE(t, buf)                                                         \
    {                                                                         \
        int k0 = (t) * 32;                                                    \
        _Pragma("unroll")                                                     \
        for (int p = 0; p < MT / 2; p++)                                      \
            cp16(sBase + (buf) * STG + sOff + p * 5120,                       \
                 A + (size_t)(m0 + rowC + p * 64) * lda + k0 + cA);           \
        _Pragma("unroll")                                                     \
        for (int p = 0; p < NT; p++)                                          \
            cp16(sBase + (buf) * STG + ASZ + sOff + p * 5120,                 \
                 Bh + (size_t)(n0 + rowC + p * 64) * ldb + k0 + cA);          \
        CP_COMMIT();                                                          \
    }

    int T = K >> 5;                 // all call sites have K >= 64 (T >= 2)
    ISSUE(0, 0)
    ISSUE(1, 1)
    int buf = 0;
    for (int t = 0; t < T; t++) {
        if (t == T - 1) { CP_WAIT(0); } else { CP_WAIT(1); }
        __syncthreads();

        uint32_t aTile = sBase + buf * STG;
        uint32_t bTile = aTile + ASZ;
#pragma unroll
        for (int kk = 0; kk < 2; kk++) {
            int k16 = kk * 16;
            uint32_t af[MT][4], bf[2 * NT][2];
#pragma unroll
            for (int mi = 0; mi < MT; mi++)
                ldsm4(af[mi][0], af[mi][1], af[mi][2], af[mi][3],
                      aTile + ((wm * MT * 16 + mi * 16) * 40 + k16) * 2 + fOff);
#pragma unroll
            for (int p = 0; p < NT; p++) {
                uint32_t r0, r1, r2, r3;
                ldsm4(r0, r1, r2, r3,
                      bTile + ((wn * NT * 16 + p * 16) * 40 + k16) * 2 + fOff);
                bf[2 * p][0] = r0; bf[2 * p][1] = r2;
                bf[2 * p + 1][0] = r1; bf[2 * p + 1][1] = r3;
            }
#pragma unroll
            for (int mi = 0; mi < MT; mi++)
#pragma unroll
                for (int ni = 0; ni < 2 * NT; ni++)
                    mma_f16(c[mi][ni], af[mi], bf[ni]);
        }
        if (t + 2 < T) {
            int nb = buf + 2; if (nb >= 3) nb -= 3;
            ISSUE(t + 2, nb)
        }
        buf = (buf + 1 == 3) ? 0 : buf + 1;
    }
#undef ISSUE

    int g = lane >> 2, tig = lane & 3;

    if (BHM == 5) {
        // fused FAVOR+ q-feature epilogue: row max + exp, fp16 out
        float* rowred = (float*)smem_dyn;
        __syncthreads();
        if (tid < BM) rowred[tid] = -1e30f;
        __syncthreads();
        float lm[MT][2];
#pragma unroll
        for (int mi = 0; mi < MT; mi++) { lm[mi][0] = -1e30f; lm[mi][1] = -1e30f; }
#pragma unroll
        for (int mi = 0; mi < MT; mi++)
#pragma unroll
            for (int ni = 0; ni < 2 * NT; ni++) {
                lm[mi][0] = fmaxf(lm[mi][0], fmaxf(c[mi][ni][0], c[mi][ni][1]));
                lm[mi][1] = fmaxf(lm[mi][1], fmaxf(c[mi][ni][2], c[mi][ni][3]));
            }
#pragma unroll
        for (int mi = 0; mi < MT; mi++)
#pragma unroll
            for (int half = 0; half < 2; half++) {
                int rl = wm * MT * 16 + mi * 16 + g + half * 8;
                atomicMaxF(&rowred[rl], lm[mi][half] * scale);
            }
        __syncthreads();
        float sub[MT][2];
#pragma unroll
        for (int mi = 0; mi < MT; mi++)
#pragma unroll
            for (int half = 0; half < 2; half++) {
                int rl = wm * MT * 16 + mi * 16 + g + half * 8;
                sub[mi][half] = R[m0 + rl] + rowred[rl];
            }
#pragma unroll
        for (int mi = 0; mi < MT; mi++)
#pragma unroll
            for (int ni = 0; ni < 2 * NT; ni++) {
                int col = wn * NT * 16 + ni * 8 + 2 * tig;
#pragma unroll
                for (int half = 0; half < 2; half++) {
                    int r = m0 + wm * MT * 16 + mi * 16 + g + half * 8;
                    float s_ = sub[mi][half];
                    float v0 = RATIO_CONST *
                               (expf(c[mi][ni][half * 2 + 0] * scale - s_) + EPSK);
                    float v1 = RATIO_CONST *
                               (expf(c[mi][ni][half * 2 + 1] * scale - s_) + EPSK);
                    __half2 hv = __floats2half2_rn(v0, v1);
                    *(__half2*)&((__half*)C)[(size_t)r * ldc + col] = hv;
                }
            }
        return;
    }

    // generic epilogue
    float tm = -1e30f;
#pragma unroll
    for (int mi = 0; mi < MT; mi++) {
#pragma unroll
        for (int ni = 0; ni < 2 * NT; ni++) {
            int rl = wm * MT * 16 + mi * 16 + g;
            int cl = wn * NT * 16 + ni * 8 + 2 * tig;
            if (cl >= nvalid) continue;
            int col = n0 + cl;
#pragma unroll
            for (int half = 0; half < 2; half++) {
                int r = m0 + rl + half * 8;
                float v0 = c[mi][ni][half * 2 + 0] * scale;
                float v1 = c[mi][ni][half * 2 + 1] * scale;
                if (BHM == 6) tm = fmaxf(tm, fmaxf(v0, v1));
                if (bias) { v0 += bias[col]; v1 += bias[col + 1]; }
                if (EPI == EPI_GELU) {
                    v0 = 0.5f * v0 * (1.0f + erff(v0 * 0.70710678118654752f));
                    v1 = 0.5f * v1 * (1.0f + erff(v1 * 0.70710678118654752f));
                }
                if (EPI == EPI_ADD) {
                    v0 += R[(size_t)r * ldc + col];
                    v1 += R[(size_t)r * ldc + col + 1];
                }
                if (EPI == EPI_DINV) {
                    float di = R[r];
                    v0 *= di; v1 *= di;
                }
                if (sizeof(OutT) == 2) {
                    __half2 hv = __floats2half2_rn(v0, v1);
                    *(__half2*)&((__half*)C)[(size_t)r * ldc + col] = hv;
                } else {
                    float2 o = {v0, v1};
                    *(float2*)&((float*)C)[(size_t)r * ldc + col] = o;
                }
            }
        }
    }
    if (BHM == 6) {
#pragma unroll
        for (int o = 16; o > 0; o >>= 1)
            tm = fmaxf(tm, __shfl_xor_sync(0xffffffffu, tm, o));
        if (lane == 0) atomicMaxF(&hmaxp[blockIdx.z], tm);
    }
}

// --------------- batched weight transpose + convert to fp16 ----------------
__global__ __launch_bounds__(256)
void transpose_all(const float* __restrict__ Wqkv, const float* __restrict__ Wo,
                   const float* __restrict__ Wff1, const float* __restrict__ Wff2,
                   const float* __restrict__ proj,
                   __half* __restrict__ qkvT, __half* __restrict__ woT,
                   __half* __restrict__ ff1T, __half* __restrict__ ff2T,
                   __half* __restrict__ projh) {
    __shared__ float tbuf[32][33];
    int z = blockIdx.z;
    if (z >= 16) {
        int l = z - 16;
        int idx = (blockIdx.y * gridDim.x + blockIdx.x) * 256 + threadIdx.x;
        if (idx < Mc * DHc)
            projh[(size_t)l * Mc * DHc + idx] =
                __float2half(proj[(size_t)l * Mc * DHc + idx]);
        return;
    }
    int type = z & 3, l = z >> 2;
    int K, N;
    const float* in;
    __half* out;
    if (type == 0)      { K = Dc;  N = QKVW; in = Wqkv + (size_t)l * Dc * QKVW; out = qkvT + (size_t)l * QKVW * Dc; }
    else if (type == 1) { K = Dc;  N = Dc;   in = Wo   + (size_t)l * Dc * Dc;   out = woT  + (size_t)l * Dc * Dc; }
    else if (type == 2) { K = Dc;  N = FFc;  in = Wff1 + (size_t)l * Dc * FFc;  out = ff1T + (size_t)l * FFc * Dc; }
    else                { K = FFc; N = Dc;   in = Wff2 + (size_t)l * FFc * Dc;  out = ff2T + (size_t)l * Dc * FFc; }

    int nx = blockIdx.x * 32, kx = blockIdx.y * 32;
    if (nx >= N || kx >= K) return;
    int tx = threadIdx.x & 31, ty = threadIdx.x >> 5;
#pragma unroll
    for (int i = 0; i < 4; i++)
        tbuf[ty + i * 8][tx] = in[(size_t)(kx + ty + i * 8) * N + nx + tx];
    __syncthreads();
#pragma unroll
    for (int i = 0; i < 4; i++)
        out[(size_t)(nx + ty + i * 8) * K + kx + tx] =
            __float2half(tbuf[tx][ty + i * 8]);
}

// ------------------------------ copy x -> h --------------------------------
__global__ void copy_kernel(const float* __restrict__ x, float* __restrict__ h) {
    size_t i = (size_t)blockIdx.x * 256 + threadIdx.x;
    h[i] = x[i];
}

// ------------------- layernorm: warp per row (fp16 out) --------------------
__global__ __launch_bounds__(256)
void ln_kernel(const float* __restrict__ x, const float* __restrict__ g,
               const float* __restrict__ b, __half* __restrict__ out) {
    int w = threadIdx.x >> 5, lane = threadIdx.x & 31;
    int row = blockIdx.x * 8 + w;
    const float4* xr = (const float4*)(x + (size_t)row * Dc);
    float4 v[4];
    float s = 0.0f;
#pragma unroll
    for (int i = 0; i < 4; i++) {
        v[i] = xr[lane + i * 32];
        s += (v[i].x + v[i].y) + (v[i].z + v[i].w);
    }
#pragma unroll
    for (int o = 16; o > 0; o >>= 1) s += __shfl_xor_sync(0xffffffffu, s, o);
    float mu = s * (1.0f / Dc);
    float var = 0.0f;
#pragma unroll
    for (int i = 0; i < 4; i++) {
        v[i].x -= mu; v[i].y -= mu; v[i].z -= mu; v[i].w -= mu;
        var += v[i].x * v[i].x + v[i].y * v[i].y +
               v[i].z * v[i].z + v[i].w * v[i].w;
    }
#pragma unroll
    for (int o = 16; o > 0; o >>= 1) var += __shfl_xor_sync(0xffffffffu, var, o);
    float rs = rsqrtf(var * (1.0f / Dc) + LNEPS);
    const float4* gp = (const float4*)g;
    const float4* bp = (const float4*)b;
    __half* orow = out + (size_t)row * Dc;
#pragma unroll
    for (int i = 0; i < 4; i++) {
        float4 gg = gp[lane + i * 32], bb = bp[lane + i * 32];
        uint2 o2;
        o2.x = f2h2(v[i].x * rs * gg.x + bb.x, v[i].y * rs * gg.y + bb.y);
        o2.y = f2h2(v[i].z * rs * gg.z + bb.z, v[i].w * rs * gg.w + bb.w);
        *(uint2*)&orow[(lane + i * 32) * 4] = o2;
    }
}

// ------- diag (+ hmax init): per-(bh,row) 0.5*dn^2*|q|^2, |k|^2 ------------
__global__ __launch_bounds__(256)
void diag_kernel(const __half* __restrict__ qkv, float* __restrict__ qdiag,
                 float* __restrict__ kdiag, float* __restrict__ hmax) {
    if (blockIdx.x == 0 && threadIdx.x < BHc) hmax[threadIdx.x] = -1e30f;
    int row = blockIdx.x;
    int w = threadIdx.x >> 5, lane = threadIdx.x & 31;
    const __half* base = qkv + (size_t)row * QKVW + w * DHc;
    float q0 = __half2float(base[lane]), q1 = __half2float(base[lane + 32]);
    float k0 = __half2float(base[Dc + lane]),
          k1 = __half2float(base[Dc + lane + 32]);
    float sq = q0 * q0 + q1 * q1;
    float sk = k0 * k0 + k1 * k1;
#pragma unroll
    for (int o = 16; o > 0; o >>= 1) {
        sq += __shfl_down_sync(0xffffffffu, sq, o);
        sk += __shfl_down_sync(0xffffffffu, sk, o);
    }
    if (lane == 0) {
        int bh = (row >> 12) * Hc + w;
        int n = row & (Nc - 1);
        qdiag[(size_t)bh * Nc + n] = sq * DIAG_SCALE;
        kdiag[(size_t)bh * Nc + n] = sk * DIAG_SCALE;
    }
}

// ---- merged: featk exp+ksum (x<32) | v transpose (x>=32) ------------------
__global__ __launch_bounds__(256)
void featk_vtrans(const float* __restrict__ ddT, const float* __restrict__ kdiag,
                  const float* __restrict__ hmax, __half* __restrict__ kpT,
                  float* __restrict__ ksum, const __half* __restrict__ qkv,
                  __half* __restrict__ vT) {
    int bh = blockIdx.y;
    if (blockIdx.x < 32) {
        // featk: exp over ddT rows + fused ksum (warp per m row)
        int m = blockIdx.x * 8 + (threadIdx.x >> 5);
        int lane = threadIdx.x & 31;
        float hm = hmax[bh];
        const float4* src = (const float4*)(ddT + ((size_t)bh * Mc + m) * Nc);
        const float4* kd4 = (const float4*)(kdiag + (size_t)bh * Nc);
        __half2* dst = (__half2*)(kpT + ((size_t)bh * Mc + m) * Nc);
        float s = 0.0f;
        for (int i = lane; i < Nc / 4; i += 32) {
            float4 v = src[i];
            float4 kd = kd4[i];
            float e0 = RATIO_CONST * (expf(v.x - kd.x - hm) + EPSK);
            float e1 = RATIO_CONST * (expf(v.y - kd.y - hm) + EPSK);
            float e2 = RATIO_CONST * (expf(v.z - kd.z - hm) + EPSK);
            float e3 = RATIO_CONST * (expf(v.w - kd.w - hm) + EPSK);
            s += (e0 + e1) + (e2 + e3);
            dst[2 * i]     = __floats2half2_rn(e0, e1);
            dst[2 * i + 1] = __floats2half2_rn(e2, e3);
        }
#pragma unroll
        for (int o = 16; o > 0; o >>= 1) s += __shfl_down_sync(0xffffffffu, s, o);
        if (lane == 0) ksum[bh * Mc + m] = s;
    } else {
        // v transpose tile
        __shared__ __half tile[32][33];
        int xx = blockIdx.x - 32;        // 0..255
        int n0 = (xx & 127) * 32, d0 = (xx >> 7) * 32;
        int b = bh >> 3, h = bh & 7;
        int tx = threadIdx.x & 31, ty = threadIdx.x >> 5;
#pragma unroll
        for (int i = 0; i < 4; i++)
            tile[ty + i * 8][tx] =
                qkv[((size_t)(b * Nc + n0 + ty + i * 8)) * QKVW + 2 * Dc +
                    h * DHc + d0 + tx];
        __syncthreads();
#pragma unroll
        for (int i = 0; i < 4; i++)
            vT[((size_t)bh * 64 + d0 + ty + i * 8) * Nc + n0 + tx] =
                tile[tx][ty + i * 8];
    }
}

// ---- merged: ctx slab reduce->fp16 (x<1024) | dinv (x>=1024) --------------
__global__ __launch_bounds__(256)
void cvt_dinv(const float* __restrict__ ctxF, __half* __restrict__ ctxT,
              const __half* __restrict__ qp16, const float* __restrict__ ksum,
              float* __restrict__ dinv) {
    if (blockIdx.x < 1024) {
        size_t i = (size_t)blockIdx.x * 256 + threadIdx.x;   // BHc*64*Mc elems
        float s = 0.0f;
#pragma unroll
        for (int sl = 0; sl < NSPLIT; sl++)
            s += ctxF[(size_t)sl * BHc * 64 * Mc + i];
        ctxT[i] = __float2half(s);
    } else {
        int w = threadIdx.x >> 5, lane = threadIdx.x & 31;
        int rr = (blockIdx.x - 1024) * 8 + w;
        int bh = rr >> 12;
        uint4 u = ((const uint4*)(qp16 + (size_t)rr * Mc))[lane];
        const float* ks = ksum + bh * Mc + lane * 8;
        __half2* hp = (__half2*)&u;
        float s = 0.0f;
#pragma unroll
        for (int j = 0; j < 4; j++) {
            float2 f = __half22float2(hp[j]);
            s += f.x * ks[2 * j] + f.y * ks[2 * j + 1];
        }
#pragma unroll
        for (int o = 16; o > 0; o >>= 1)
            s += __shfl_down_sync(0xffffffffu, s, o);
        if (lane == 0) dinv[rr] = 1.0f / s;
    }
}

// ------------------------------- launch ------------------------------------
#define SM_44 61440   // 3*(128+128)*80
#define SM_24 76800   // 3*(64+256)*80
#define SM_22 46080   // 3*(64+128)*80
#define SM_41 46080   // 3*(128+64)*80

extern "C" void kernel_launch(void* const* d_in, const int* in_sizes, int n_in,
                              void* d_out, int out_size) {
    (void)in_sizes; (void)n_in; (void)out_size;
    const float* x    = (const float*)d_in[0];
    const float* proj = (const float*)d_in[1];
    const float* ln1g = (const float*)d_in[2];
    const float* ln1b = (const float*)d_in[3];
    const float* Wqkv = (const float*)d_in[4];
    const float* bqkv = (const float*)d_in[5];
    const float* Wo   = (const float*)d_in[6];
    const float* bo   = (const float*)d_in[7];
    const float* ln2g = (const float*)d_in[8];
    const float* ln2b = (const float*)d_in[9];
    const float* Wff1 = (const float*)d_in[10];
    const float* bff1 = (const float*)d_in[11];
    const float* Wff2 = (const float*)d_in[12];
    const float* bff2 = (const float*)d_in[13];
    float* h = (float*)d_out;

    static float *p_ddT = 0, *p_ctxF = 0, *p_ksum = 0, *p_qdiag = 0,
                 *p_kdiag = 0, *p_hmax = 0, *p_dinv = 0;
    static __half *p_ln16 = 0, *p_qkv16 = 0, *p_ff16 = 0, *p_att16 = 0,
                  *p_qp16 = 0, *p_kpT = 0, *p_vT = 0, *p_ctxT = 0,
                  *p_wqkvT = 0, *p_woT = 0, *p_wff1T = 0, *p_wff2T = 0,
                  *p_projh = 0;
    if (!p_ddT) {
        cudaGetSymbolAddress((void**)&p_ddT, g_ddT);
        cudaGetSymbolAddress((void**)&p_ctxF, g_ctxF);
        cudaGetSymbolAddress((void**)&p_ksum, g_ksum);
        cudaGetSymbolAddress((void**)&p_qdiag, g_qdiag);
        cudaGetSymbolAddress((void**)&p_kdiag, g_kdiag);
        cudaGetSymbolAddress((void**)&p_hmax, g_hmax);
        cudaGetSymbolAddress((void**)&p_dinv, g_dinv);
        cudaGetSymbolAddress((void**)&p_ln16, g_ln16);
        cudaGetSymbolAddress((void**)&p_qkv16, g_qkv16);
        cudaGetSymbolAddress((void**)&p_ff16, g_ff16);
        cudaGetSymbolAddress((void**)&p_att16, g_att16);
        cudaGetSymbolAddress((void**)&p_qp16, g_qp16);
        cudaGetSymbolAddress((void**)&p_kpT, g_kpT);
        cudaGetSymbolAddress((void**)&p_vT, g_vT);
        cudaGetSymbolAddress((void**)&p_ctxT, g_ctxT);
        cudaGetSymbolAddress((void**)&p_wqkvT, g_wqkvT);
        cudaGetSymbolAddress((void**)&p_woT, g_woT);
        cudaGetSymbolAddress((void**)&p_wff1T, g_wff1T);
        cudaGetSymbolAddress((void**)&p_wff2T, g_wff2T);
        cudaGetSymbolAddress((void**)&p_projh, g_projh);
        cudaFuncSetAttribute(hgemm<EPI_NONE, 0, __half, 4, 2>,
                             cudaFuncAttributeMaxDynamicSharedMemorySize, SM_44);
        cudaFuncSetAttribute(hgemm<EPI_NONE, 5, __half, 2, 4>,
                             cudaFuncAttributeMaxDynamicSharedMemorySize, SM_24);
        cudaFuncSetAttribute(hgemm<EPI_NONE, 6, float, 4, 2>,
                             cudaFuncAttributeMaxDynamicSharedMemorySize, SM_44);
        cudaFuncSetAttribute(hgemm<EPI_NONE, 2, float, 2, 2>,
                             cudaFuncAttributeMaxDynamicSharedMemorySize, SM_22);
        cudaFuncSetAttribute(hgemm<EPI_DINV, 3, __half, 4, 1>,
                             cudaFuncAttributeMaxDynamicSharedMemorySize, SM_41);
        cudaFuncSetAttribute(hgemm<EPI_ADD, 0, float, 4, 2>,
                             cudaFuncAttributeMaxDynamicSharedMemorySize, SM_44);
        cudaFuncSetAttribute(hgemm<EPI_GELU, 0, __half, 4, 2>,
                             cudaFuncAttributeMaxDynamicSharedMemorySize, SM_44);
    }

    // launch 0: weight transposes + fp16 conversion
    transpose_all<<<dim3(64, 64, 20), 256>>>(Wqkv, Wo, Wff1, Wff2, proj,
                                             p_wqkvT, p_woT, p_wff1T, p_wff2T,
                                             p_projh);
    // launch 1
    copy_kernel<<<(ROWSc * Dc) / 256, 256>>>(x, h);

    for (int l = 0; l < DEPTHc; l++) {
        const __half* pjh = p_projh + (size_t)l * Mc * DHc;

        ln_kernel<<<ROWSc / 8, 256>>>(h, ln1g + l * Dc, ln1b + l * Dc, p_ln16);

        // launch 3 (profiled): QKV
        hgemm<EPI_NONE, 0, __half, 4, 2>
            <<<dim3(QKVW / 128, ROWSc / 128), 256, SM_44>>>(
            p_ln16, Dc, p_wqkvT + (size_t)l * QKVW * Dc, Dc,
            bqkv + l * QKVW, (const float*)0, p_qkv16, QKVW, Dc, 1.0f, 128,
            (float*)0);

        // diag (+ hmax init)
        diag_kernel<<<ROWSc, 256>>>(p_qkv16, p_qdiag, p_kdiag, p_hmax);

        // dd_q with fused featq epilogue (BM=64, BN=256)
        hgemm<EPI_NONE, 5, __half, 2, 4>
            <<<dim3(1, Nc / 64, BHc), 256, SM_24>>>(
            p_qkv16, QKVW, pjh, DHc, (const float*)0, p_qdiag,
            p_qp16, Mc, DHc, DN_CONST, 256, (float*)0);

        // dd_k^T direct: A=proj [256x64], B=k rows -> ddT [bh][m][n] + hmax
        hgemm<EPI_NONE, 6, float, 4, 2>
            <<<dim3(Nc / 128, Mc / 128, BHc), 256, SM_44>>>(
            pjh, DHc, p_qkv16, QKVW, (const float*)0, (const float*)0,
            p_ddT, Nc, DHc, DN_CONST, 128, p_hmax);

        // merged: featk exp+ksum | v transpose
        featk_vtrans<<<dim3(288, BHc), 256>>>(p_ddT, p_kdiag, p_hmax,
                                              p_kpT, p_ksum, p_qkv16, p_vT);

        // ctx^T = vT @ kpT^T, split-K=8 disjoint slabs (BM=64)
        hgemm<EPI_NONE, 2, float, 2, 2>
            <<<dim3(Mc / 128, NSPLIT, BHc), 256, SM_22>>>(
            p_vT, Nc, p_kpT, Nc, (const float*)0, (const float*)0,
            p_ctxF, Mc, Nc / NSPLIT, 1.0f, 128, (float*)0);

        // merged: ctx slab-reduce + dinv
        cvt_dinv<<<1024 + (BHc * Nc) / 8, 256>>>(p_ctxF, p_ctxT,
                                                 p_qp16, p_ksum, p_dinv);

        // attnout = (qp16 @ ctxT^T) * dinv, BN=64, head-merged fp16
        hgemm<EPI_DINV, 3, __half, 4, 1>
            <<<dim3(1, Nc / 128, BHc), 256, SM_41>>>(
            p_qp16, Mc, p_ctxT, Mc, (const float*)0, p_dinv,
            p_att16, Dc, Mc, 1.0f, 64, (float*)0);

        // Wo + residual
        hgemm<EPI_ADD, 0, float, 4, 2>
            <<<dim3(Dc / 128, ROWSc / 128), 256, SM_44>>>(
            p_att16, Dc, p_woT + (size_t)l * Dc * Dc, Dc,
            bo + l * Dc, h, h, Dc, Dc, 1.0f, 128, (float*)0);

        ln_kernel<<<ROWSc / 8, 256>>>(h, ln2g + l * Dc, ln2b + l * Dc, p_ln16);

        // FF1 + gelu
        hgemm<EPI_GELU, 0, __half, 4, 2>
            <<<dim3(FFc / 128, ROWSc / 128), 256, SM_44>>>(
            p_ln16, Dc, p_wff1T + (size_t)l * FFc * Dc, Dc,
            bff1 + l * FFc, (const float*)0, p_ff16, FFc, Dc, 1.0f, 128,
            (float*)0);

        // FF2 + residual
        hgemm<EPI_ADD, 0, float, 4, 2>
            <<<dim3(Dc / 128, ROWSc / 128), 256, SM_44>>>(
            p_ff16, FFc, p_wff2T + (size_t)l * Dc * FFc, FFc,
            bff2 + l * Dc, h, h, Dc, FFc, 1.0f, 128, (float*)0);
    }
}

// round 17
// speedup vs baseline: 1.3589x; 1.0381x over previous
#include <cuda_runtime.h>
#include <cuda_fp16.h>
#include <math.h>
#include <stdint.h>

// ---------------------------------------------------------------------------
// SpatioTemporalPerformerEncoder — R17: compile-time K, fully unrolled mainloop
// (R16 structure; KT template folds smem addressing to immediates)
// ---------------------------------------------------------------------------

#define Bc     2
#define Hc     8
#define Nc     4096
#define Dc     512
#define DHc    64
#define Mc     256
#define FFc    2048
#define DEPTHc 4
#define ROWSc  8192
#define BHc    16
#define QKVW   1536

#define DN_CONST    0.35355339059327373f
#define DIAG_SCALE  0.0625f
#define RATIO_CONST 0.0625f
#define EPSK        1e-4f
#define LNEPS       1e-5f

#define NSPLIT  8

// ------------------------- scratch (device globals) ------------------------
__device__ __half g_ln16 [(size_t)ROWSc * Dc];
__device__ __half g_qkv16[(size_t)ROWSc * QKVW];
__device__ __half g_ff16 [(size_t)ROWSc * FFc];
__device__ __half g_att16[(size_t)ROWSc * Dc];
__device__ float  g_ddT  [(size_t)BHc * Mc * Nc];          // raw dd_k^T
__device__ __half g_qp16 [(size_t)BHc * Nc * Mc];
__device__ __half g_kpT  [(size_t)BHc * Mc * Nc];
__device__ __half g_vT   [(size_t)BHc * 64 * Nc];          // v^T, 64 rows
__device__ float  g_ctxF [(size_t)NSPLIT * BHc * 64 * Mc]; // split-K slabs
__device__ __half g_ctxT [(size_t)BHc * 64 * Mc];
__device__ float  g_ksum [BHc * Mc];
__device__ float  g_qdiag[BHc * Nc];
__device__ float  g_kdiag[BHc * Nc];
__device__ float  g_hmax [BHc];
__device__ float  g_dinv [BHc * Nc];
__device__ __half g_wqkvT[(size_t)DEPTHc * QKVW * Dc];
__device__ __half g_woT  [(size_t)DEPTHc * Dc * Dc];
__device__ __half g_wff1T[(size_t)DEPTHc * FFc * Dc];
__device__ __half g_wff2T[(size_t)DEPTHc * Dc * FFc];
__device__ __half g_projh[(size_t)DEPTHc * Mc * DHc];

// ------------------------------ helpers ------------------------------------
__device__ __forceinline__ uint32_t smem_to_u32(const void* p) {
    uint32_t a;
    asm("{ .reg .u64 t; cvta.to.shared.u64 t, %1; cvt.u32.u64 %0, t; }"
        : "=r"(a) : "l"(p));
    return a;
}
__device__ __forceinline__ uint32_t f2h2(float a, float b) {
    __half2 h = __floats2half2_rn(a, b);
    return *(uint32_t*)&h;
}
__device__ __forceinline__ void cp16(uint32_t dst, const void* src) {
    asm volatile("cp.async.cg.shared.global [%0], [%1], 16;"
                 :: "r"(dst), "l"(src));
}
#define CP_COMMIT() asm volatile("cp.async.commit_group;")
#define CP_WAIT(n)  asm volatile("cp.async.wait_group %0;" :: "n"(n))

__device__ __forceinline__ void ldsm4(uint32_t& r0, uint32_t& r1, uint32_t& r2,
                                      uint32_t& r3, uint32_t a) {
    asm volatile("ldmatrix.sync.aligned.m8n8.x4.shared.b16 {%0,%1,%2,%3}, [%4];"
                 : "=r"(r0), "=r"(r1), "=r"(r2), "=r"(r3) : "r"(a));
}
__device__ __forceinline__ void mma_f16(float c[4], const uint32_t a[4],
                                        const uint32_t b[2]) {
    asm volatile(
        "mma.sync.aligned.m16n8k16.row.col.f32.f16.f16.f32 "
        "{%0,%1,%2,%3}, {%4,%5,%6,%7}, {%8,%9}, {%0,%1,%2,%3};"
        : "+f"(c[0]), "+f"(c[1]), "+f"(c[2]), "+f"(c[3])
        : "r"(a[0]), "r"(a[1]), "r"(a[2]), "r"(a[3]), "r"(b[0]), "r"(b[1]));
}
__device__ __forceinline__ void atomicMaxF(float* a, float v) {
    if (v >= 0.0f) atomicMax((int*)a, __float_as_int(v));
    else atomicMin((unsigned int*)a, __float_as_uint(v));
}

// ------------------------- fp16 tensor-core GEMM ---------------------------
// C = scale*(A[M,K]h @ B[N,K]h^T) + epilogue. BK=32, 256 threads (8 warps 2x4),
// warp tile (MT*16)x(NT*16), BM=MT*32, BN=NT*64. 3-stage cp.async.
// KT > 0: compile-time K, fully unrolled mainloop. KT == 0: runtime K.
// BHM 0: plain. 2: ctx (per-bh, split-K slab via blockIdx.y, fp32 slab out).
// 3: attnout (per-bh, dinv row scale via R, head-merged out).
// 5: dd_q fused featq (per-bh, qdiag via R, row-max+exp epilogue, fp16 out).
// 6: dd_k^T direct (A=proj, B=k rows; fp32 out [m][n] + fused global max).
#define EPI_NONE 0
#define EPI_GELU 1
#define EPI_ADD  2
#define EPI_DINV 3

template <int EPI, int BHM, typename OutT, int MT, int NT, int KT>
__global__ __launch_bounds__(256, 2)
void hgemm(const __half* __restrict__ A, int lda,
           const __half* __restrict__ Bh, int ldb,
           const float* __restrict__ bias, const float* __restrict__ R,
           OutT* __restrict__ C, int ldc, int K, float scale,
           int nvalid, float* __restrict__ hmaxp) {
    extern __shared__ __align__(16) char smem_dyn[];
    uint32_t sBase = smem_to_u32(smem_dyn);

    const int BM = MT * 32, BN = NT * 64;
    const uint32_t ASZ = (uint32_t)BM * 80;
    const uint32_t STG = (uint32_t)(BM + BN) * 80;

    int m0, n0;
    if (BHM == 2) {
        int z = blockIdx.z, s = blockIdx.y;
        A += (size_t)z * BM * lda + (size_t)s * K;
        Bh += (size_t)z * Mc * ldb + (size_t)s * K;
        C += ((size_t)s * BHc + z) * BM * ldc;
        m0 = 0;
        n0 = blockIdx.x * BN;
    } else {
        if (BHM == 5) {
            int z = blockIdx.z;
            A += (size_t)(z >> 3) * Nc * lda + (size_t)(z & 7) * DHc;
            C += (size_t)z * Nc * ldc;
            R += (size_t)z * Nc;
        }
        if (BHM == 6) {
            int z = blockIdx.z;
            Bh += (size_t)(z >> 3) * Nc * ldb + (size_t)(z & 7) * DHc + Dc;
            C += (size_t)z * Mc * ldc;
        }
        if (BHM == 3) {
            int z = blockIdx.z;
            A += (size_t)z * Nc * lda;
            Bh += (size_t)z * 64 * ldb;
            C += (size_t)(z >> 3) * Nc * Dc + (size_t)(z & 7) * DHc;
            R += (size_t)z * Nc;
        }
        m0 = blockIdx.y * BM;
        n0 = blockIdx.x * BN;
    }

    int tid = threadIdx.x, lane = tid & 31, warp = tid >> 5;
    int wm = warp >> 2, wn = warp & 3;

    int rowC = tid >> 2, cA = (tid & 3) * 8;
    uint32_t sOff = ((uint32_t)rowC * 40 + cA) * 2;
    uint32_t fOff = (((lane & 15) * 40) + (lane >> 4) * 8) * 2;

    float c[MT][2 * NT][4];
#pragma unroll
    for (int i = 0; i < MT; i++)
#pragma unroll
        for (int j = 0; j < 2 * NT; j++)
#pragma unroll
            for (int l = 0; l < 4; l++) c[i][j][l] = 0.0f;

#define ISSUE(t, buf)                                                         \
    {                                                                         \
        int k0 = (t) * 32;                                                    \
        _Pragma("unroll")                                                     \
        for (int p = 0; p < MT / 2; p++)                                      \
            cp16(sBase + (buf) * STG + sOff + p * 5120,                       \
                 A + (size_t)(m0 + rowC + p * 64) * lda + k0 + cA);           \
        _Pragma("unroll")                                                     \
        for (int p = 0; p < NT; p++)                                          \
            cp16(sBase + (buf) * STG + ASZ + sOff + p * 5120,                 \
                 Bh + (size_t)(n0 + rowC + p * 64) * ldb + k0 + cA);          \
        CP_COMMIT();                                                          \
    }

    const int T = (KT > 0) ? (KT / 32) : (K >> 5);   // all call sites T >= 2
    ISSUE(0, 0)
    ISSUE(1, 1)
#pragma unroll
    for (int t = 0; t < T; t++) {
        int buf = t % 3;                              // folds when KT > 0
        if (t == T - 1) { CP_WAIT(0); } else { CP_WAIT(1); }
        __syncthreads();

        uint32_t aTile = sBase + buf * STG;
        uint32_t bTile = aTile + ASZ;
#pragma unroll
        for (int kk = 0; kk < 2; kk++) {
            int k16 = kk * 16;
            uint32_t af[MT][4], bf[2 * NT][2];
#pragma unroll
            for (int mi = 0; mi < MT; mi++)
                ldsm4(af[mi][0], af[mi][1], af[mi][2], af[mi][3],
                      aTile + ((wm * MT * 16 + mi * 16) * 40 + k16) * 2 + fOff);
#pragma unroll
            for (int p = 0; p < NT; p++) {
                uint32_t r0, r1, r2, r3;
                ldsm4(r0, r1, r2, r3,
                      bTile + ((wn * NT * 16 + p * 16) * 40 + k16) * 2 + fOff);
                bf[2 * p][0] = r0; bf[2 * p][1] = r2;
                bf[2 * p + 1][0] = r1; bf[2 * p + 1][1] = r3;
            }
#pragma unroll
            for (int mi = 0; mi < MT; mi++)
#pragma unroll
                for (int ni = 0; ni < 2 * NT; ni++)
                    mma_f16(c[mi][ni], af[mi], bf[ni]);
        }
        if (t + 2 < T) {
            ISSUE(t + 2, (t + 2) % 3)
        }
    }
#undef ISSUE

    int g = lane >> 2, tig = lane & 3;

    if (BHM == 5) {
        // fused FAVOR+ q-feature epilogue: row max + exp, fp16 out
        float* rowred = (float*)smem_dyn;
        __syncthreads();
        if (tid < BM) rowred[tid] = -1e30f;
        __syncthreads();
        float lm[MT][2];
#pragma unroll
        for (int mi = 0; mi < MT; mi++) { lm[mi][0] = -1e30f; lm[mi][1] = -1e30f; }
#pragma unroll
        for (int mi = 0; mi < MT; mi++)
#pragma unroll
            for (int ni = 0; ni < 2 * NT; ni++) {
                lm[mi][0] = fmaxf(lm[mi][0], fmaxf(c[mi][ni][0], c[mi][ni][1]));
                lm[mi][1] = fmaxf(lm[mi][1], fmaxf(c[mi][ni][2], c[mi][ni][3]));
            }
#pragma unroll
        for (int mi = 0; mi < MT; mi++)
#pragma unroll
            for (int half = 0; half < 2; half++) {
                int rl = wm * MT * 16 + mi * 16 + g + half * 8;
                atomicMaxF(&rowred[rl], lm[mi][half] * scale);
            }
        __syncthreads();
        float sub[MT][2];
#pragma unroll
        for (int mi = 0; mi < MT; mi++)
#pragma unroll
            for (int half = 0; half < 2; half++) {
                int rl = wm * MT * 16 + mi * 16 + g + half * 8;
                sub[mi][half] = R[m0 + rl] + rowred[rl];
            }
#pragma unroll
        for (int mi = 0; mi < MT; mi++)
#pragma unroll
            for (int ni = 0; ni < 2 * NT; ni++) {
                int col = wn * NT * 16 + ni * 8 + 2 * tig;
#pragma unroll
                for (int half = 0; half < 2; half++) {
                    int r = m0 + wm * MT * 16 + mi * 16 + g + half * 8;
                    float s_ = sub[mi][half];
                    float v0 = RATIO_CONST *
                               (expf(c[mi][ni][half * 2 + 0] * scale - s_) + EPSK);
                    float v1 = RATIO_CONST *
                               (expf(c[mi][ni][half * 2 + 1] * scale - s_) + EPSK);
                    __half2 hv = __floats2half2_rn(v0, v1);
                    *(__half2*)&((__half*)C)[(size_t)r * ldc + col] = hv;
                }
            }
        return;
    }

    // generic epilogue
    float tm = -1e30f;
#pragma unroll
    for (int mi = 0; mi < MT; mi++) {
#pragma unroll
        for (int ni = 0; ni < 2 * NT; ni++) {
            int rl = wm * MT * 16 + mi * 16 + g;
            int cl = wn * NT * 16 + ni * 8 + 2 * tig;
            if (cl >= nvalid) continue;
            int col = n0 + cl;
#pragma unroll
            for (int half = 0; half < 2; half++) {
                int r = m0 + rl + half * 8;
                float v0 = c[mi][ni][half * 2 + 0] * scale;
                float v1 = c[mi][ni][half * 2 + 1] * scale;
                if (BHM == 6) tm = fmaxf(tm, fmaxf(v0, v1));
                if (bias) { v0 += bias[col]; v1 += bias[col + 1]; }
                if (EPI == EPI_GELU) {
                    v0 = 0.5f * v0 * (1.0f + erff(v0 * 0.70710678118654752f));
                    v1 = 0.5f * v1 * (1.0f + erff(v1 * 0.70710678118654752f));
                }
                if (EPI == EPI_ADD) {
                    v0 += R[(size_t)r * ldc + col];
                    v1 += R[(size_t)r * ldc + col + 1];
                }
                if (EPI == EPI_DINV) {
                    float di = R[r];
                    v0 *= di; v1 *= di;
                }
                if (sizeof(OutT) == 2) {
                    __half2 hv = __floats2half2_rn(v0, v1);
                    *(__half2*)&((__half*)C)[(size_t)r * ldc + col] = hv;
                } else {
                    float2 o = {v0, v1};
                    *(float2*)&((float*)C)[(size_t)r * ldc + col] = o;
                }
            }
        }
    }
    if (BHM == 6) {
#pragma unroll
        for (int o = 16; o > 0; o >>= 1)
            tm = fmaxf(tm, __shfl_xor_sync(0xffffffffu, tm, o));
        if (lane == 0) atomicMaxF(&hmaxp[blockIdx.z], tm);
    }
}

// --------------- batched weight transpose + convert to fp16 ----------------
__global__ __launch_bounds__(256)
void transpose_all(const float* __restrict__ Wqkv, const float* __restrict__ Wo,
                   const float* __restrict__ Wff1, const float* __restrict__ Wff2,
                   const float* __restrict__ proj,
                   __half* __restrict__ qkvT, __half* __restrict__ woT,
                   __half* __restrict__ ff1T, __half* __restrict__ ff2T,
                   __half* __restrict__ projh) {
    __shared__ float tbuf[32][33];
    int z = blockIdx.z;
    if (z >= 16) {
        int l = z - 16;
        int idx = (blockIdx.y * gridDim.x + blockIdx.x) * 256 + threadIdx.x;
        if (idx < Mc * DHc)
            projh[(size_t)l * Mc * DHc + idx] =
                __float2half(proj[(size_t)l * Mc * DHc + idx]);
        return;
    }
    int type = z & 3, l = z >> 2;
    int K, N;
    const float* in;
    __half* out;
    if (type == 0)      { K = Dc;  N = QKVW; in = Wqkv + (size_t)l * Dc * QKVW; out = qkvT + (size_t)l * QKVW * Dc; }
    else if (type == 1) { K = Dc;  N = Dc;   in = Wo   + (size_t)l * Dc * Dc;   out = woT  + (size_t)l * Dc * Dc; }
    else if (type == 2) { K = Dc;  N = FFc;  in = Wff1 + (size_t)l * Dc * FFc;  out = ff1T + (size_t)l * FFc * Dc; }
    else                { K = FFc; N = Dc;   in = Wff2 + (size_t)l * FFc * Dc;  out = ff2T + (size_t)l * Dc * FFc; }

    int nx = blockIdx.x * 32, kx = blockIdx.y * 32;
    if (nx >= N || kx >= K) return;
    int tx = threadIdx.x & 31, ty = threadIdx.x >> 5;
#pragma unroll
    for (int i = 0; i < 4; i++)
        tbuf[ty + i * 8][tx] = in[(size_t)(kx + ty + i * 8) * N + nx + tx];
    __syncthreads();
#pragma unroll
    for (int i = 0; i < 4; i++)
        out[(size_t)(nx + ty + i * 8) * K + kx + tx] =
            __float2half(tbuf[tx][ty + i * 8]);
}

// ------------------------------ copy x -> h --------------------------------
__global__ void copy_kernel(const float* __restrict__ x, float* __restrict__ h) {
    size_t i = (size_t)blockIdx.x * 256 + threadIdx.x;
    h[i] = x[i];
}

// ------------------- layernorm: warp per row (fp16 out) --------------------
__global__ __launch_bounds__(256)
void ln_kernel(const float* __restrict__ x, const float* __restrict__ g,
               const float* __restrict__ b, __half* __restrict__ out) {
    int w = threadIdx.x >> 5, lane = threadIdx.x & 31;
    int row = blockIdx.x * 8 + w;
    const float4* xr = (const float4*)(x + (size_t)row * Dc);
    float4 v[4];
    float s = 0.0f;
#pragma unroll
    for (int i = 0; i < 4; i++) {
        v[i] = xr[lane + i * 32];
        s += (v[i].x + v[i].y) + (v[i].z + v[i].w);
    }
#pragma unroll
    for (int o = 16; o > 0; o >>= 1) s += __shfl_xor_sync(0xffffffffu, s, o);
    float mu = s * (1.0f / Dc);
    float var = 0.0f;
#pragma unroll
    for (int i = 0; i < 4; i++) {
        v[i].x -= mu; v[i].y -= mu; v[i].z -= mu; v[i].w -= mu;
        var += v[i].x * v[i].x + v[i].y * v[i].y +
               v[i].z * v[i].z + v[i].w * v[i].w;
    }
#pragma unroll
    for (int o = 16; o > 0; o >>= 1) var += __shfl_xor_sync(0xffffffffu, var, o);
    float rs = rsqrtf(var * (1.0f / Dc) + LNEPS);
    const float4* gp = (const float4*)g;
    const float4* bp = (const float4*)b;
    __half* orow = out + (size_t)row * Dc;
#pragma unroll
    for (int i = 0; i < 4; i++) {
        float4 gg = gp[lane + i * 32], bb = bp[lane + i * 32];
        uint2 o2;
        o2.x = f2h2(v[i].x * rs * gg.x + bb.x, v[i].y * rs * gg.y + bb.y);
        o2.y = f2h2(v[i].z * rs * gg.z + bb.z, v[i].w * rs * gg.w + bb.w);
        *(uint2*)&orow[(lane + i * 32) * 4] = o2;
    }
}

// ------- diag (+ hmax init): per-(bh,row) 0.5*dn^2*|q|^2, |k|^2 ------------
__global__ __launch_bounds__(256)
void diag_kernel(const __half* __restrict__ qkv, float* __restrict__ qdiag,
                 float* __restrict__ kdiag, float* __restrict__ hmax) {
    if (blockIdx.x == 0 && threadIdx.x < BHc) hmax[threadIdx.x] = -1e30f;
    int row = blockIdx.x;
    int w = threadIdx.x >> 5, lane = threadIdx.x & 31;
    const __half* base = qkv + (size_t)row * QKVW + w * DHc;
    float q0 = __half2float(base[lane]), q1 = __half2float(base[lane + 32]);
    float k0 = __half2float(base[Dc + lane]),
          k1 = __half2float(base[Dc + lane + 32]);
    float sq = q0 * q0 + q1 * q1;
    float sk = k0 * k0 + k1 * k1;
#pragma unroll
    for (int o = 16; o > 0; o >>= 1) {
        sq += __shfl_down_sync(0xffffffffu, sq, o);
        sk += __shfl_down_sync(0xffffffffu, sk, o);
    }
    if (lane == 0) {
        int bh = (row >> 12) * Hc + w;
        int n = row & (Nc - 1);
        qdiag[(size_t)bh * Nc + n] = sq * DIAG_SCALE;
        kdiag[(size_t)bh * Nc + n] = sk * DIAG_SCALE;
    }
}

// ---- merged: featk exp+ksum (x<32) | v transpose (x>=32) ------------------
__global__ __launch_bounds__(256)
void featk_vtrans(const float* __restrict__ ddT, const float* __restrict__ kdiag,
                  const float* __restrict__ hmax, __half* __restrict__ kpT,
                  float* __restrict__ ksum, const __half* __restrict__ qkv,
                  __half* __restrict__ vT) {
    int bh = blockIdx.y;
    if (blockIdx.x < 32) {
        int m = blockIdx.x * 8 + (threadIdx.x >> 5);
        int lane = threadIdx.x & 31;
        float hm = hmax[bh];
        const float4* src = (const float4*)(ddT + ((size_t)bh * Mc + m) * Nc);
        const float4* kd4 = (const float4*)(kdiag + (size_t)bh * Nc);
        __half2* dst = (__half2*)(kpT + ((size_t)bh * Mc + m) * Nc);
        float s = 0.0f;
        for (int i = lane; i < Nc / 4; i += 32) {
            float4 v = src[i];
            float4 kd = kd4[i];
            float e0 = RATIO_CONST * (expf(v.x - kd.x - hm) + EPSK);
            float e1 = RATIO_CONST * (expf(v.y - kd.y - hm) + EPSK);
            float e2 = RATIO_CONST * (expf(v.z - kd.z - hm) + EPSK);
            float e3 = RATIO_CONST * (expf(v.w - kd.w - hm) + EPSK);
            s += (e0 + e1) + (e2 + e3);
            dst[2 * i]     = __floats2half2_rn(e0, e1);
            dst[2 * i + 1] = __floats2half2_rn(e2, e3);
        }
#pragma unroll
        for (int o = 16; o > 0; o >>= 1) s += __shfl_down_sync(0xffffffffu, s, o);
        if (lane == 0) ksum[bh * Mc + m] = s;
    } else {
        __shared__ __half tile[32][33];
        int xx = blockIdx.x - 32;        // 0..255
        int n0 = (xx & 127) * 32, d0 = (xx >> 7) * 32;
        int b = bh >> 3, h = bh & 7;
        int tx = threadIdx.x & 31, ty = threadIdx.x >> 5;
#pragma unroll
        for (int i = 0; i < 4; i++)
            tile[ty + i * 8][tx] =
                qkv[((size_t)(b * Nc + n0 + ty + i * 8)) * QKVW + 2 * Dc +
                    h * DHc + d0 + tx];
        __syncthreads();
#pragma unroll
        for (int i = 0; i < 4; i++)
            vT[((size_t)bh * 64 + d0 + ty + i * 8) * Nc + n0 + tx] =
                tile[tx][ty + i * 8];
    }
}

// ---- merged: ctx slab reduce->fp16 (x<1024) | dinv (x>=1024) --------------
__global__ __launch_bounds__(256)
void cvt_dinv(const float* __restrict__ ctxF, __half* __restrict__ ctxT,
              const __half* __restrict__ qp16, const float* __restrict__ ksum,
              float* __restrict__ dinv) {
    if (blockIdx.x < 1024) {
        size_t i = (size_t)blockIdx.x * 256 + threadIdx.x;   // BHc*64*Mc elems
        float s = 0.0f;
#pragma unroll
        for (int sl = 0; sl < NSPLIT; sl++)
            s += ctxF[(size_t)sl * BHc * 64 * Mc + i];
        ctxT[i] = __float2half(s);
    } else {
        int w = threadIdx.x >> 5, lane = threadIdx.x & 31;
        int rr = (blockIdx.x - 1024) * 8 + w;
        int bh = rr >> 12;
        uint4 u = ((const uint4*)(qp16 + (size_t)rr * Mc))[lane];
        const float* ks = ksum + bh * Mc + lane * 8;
        __half2* hp = (__half2*)&u;
        float s = 0.0f;
#pragma unroll
        for (int j = 0; j < 4; j++) {
            float2 f = __half22float2(hp[j]);
            s += f.x * ks[2 * j] + f.y * ks[2 * j + 1];
        }
#pragma unroll
        for (int o = 16; o > 0; o >>= 1)
            s += __shfl_down_sync(0xffffffffu, s, o);
        if (lane == 0) dinv[rr] = 1.0f / s;
    }
}

// ------------------------------- launch ------------------------------------
#define SM_44 61440   // 3*(128+128)*80
#define SM_24 76800   // 3*(64+256)*80
#define SM_22 46080   // 3*(64+128)*80
#define SM_41 46080   // 3*(128+64)*80

extern "C" void kernel_launch(void* const* d_in, const int* in_sizes, int n_in,
                              void* d_out, int out_size) {
    (void)in_sizes; (void)n_in; (void)out_size;
    const float* x    = (const float*)d_in[0];
    const float* proj = (const float*)d_in[1];
    const float* ln1g = (const float*)d_in[2];
    const float* ln1b = (const float*)d_in[3];
    const float* Wqkv = (const float*)d_in[4];
    const float* bqkv = (const float*)d_in[5];
    const float* Wo   = (const float*)d_in[6];
    const float* bo   = (const float*)d_in[7];
    const float* ln2g = (const float*)d_in[8];
    const float* ln2b = (const float*)d_in[9];
    const float* Wff1 = (const float*)d_in[10];
    const float* bff1 = (const float*)d_in[11];
    const float* Wff2 = (const float*)d_in[12];
    const float* bff2 = (const float*)d_in[13];
    float* h = (float*)d_out;

    static float *p_ddT = 0, *p_ctxF = 0, *p_ksum = 0, *p_qdiag = 0,
                 *p_kdiag = 0, *p_hmax = 0, *p_dinv = 0;
    static __half *p_ln16 = 0, *p_qkv16 = 0, *p_ff16 = 0, *p_att16 = 0,
                  *p_qp16 = 0, *p_kpT = 0, *p_vT = 0, *p_ctxT = 0,
                  *p_wqkvT = 0, *p_woT = 0, *p_wff1T = 0, *p_wff2T = 0,
                  *p_projh = 0;
    if (!p_ddT) {
        cudaGetSymbolAddress((void**)&p_ddT, g_ddT);
        cudaGetSymbolAddress((void**)&p_ctxF, g_ctxF);
        cudaGetSymbolAddress((void**)&p_ksum, g_ksum);
        cudaGetSymbolAddress((void**)&p_qdiag, g_qdiag);
        cudaGetSymbolAddress((void**)&p_kdiag, g_kdiag);
        cudaGetSymbolAddress((void**)&p_hmax, g_hmax);
        cudaGetSymbolAddress((void**)&p_dinv, g_dinv);
        cudaGetSymbolAddress((void**)&p_ln16, g_ln16);
        cudaGetSymbolAddress((void**)&p_qkv16, g_qkv16);
        cudaGetSymbolAddress((void**)&p_ff16, g_ff16);
        cudaGetSymbolAddress((void**)&p_att16, g_att16);
        cudaGetSymbolAddress((void**)&p_qp16, g_qp16);
        cudaGetSymbolAddress((void**)&p_kpT, g_kpT);
        cudaGetSymbolAddress((void**)&p_vT, g_vT);
        cudaGetSymbolAddress((void**)&p_ctxT, g_ctxT);
        cudaGetSymbolAddress((void**)&p_wqkvT, g_wqkvT);
        cudaGetSymbolAddress((void**)&p_woT, g_woT);
        cudaGetSymbolAddress((void**)&p_wff1T, g_wff1T);
        cudaGetSymbolAddress((void**)&p_wff2T, g_wff2T);
        cudaGetSymbolAddress((void**)&p_projh, g_projh);
        cudaFuncSetAttribute(hgemm<EPI_NONE, 0, __half, 4, 2, 512>,
                             cudaFuncAttributeMaxDynamicSharedMemorySize, SM_44);
        cudaFuncSetAttribute(hgemm<EPI_NONE, 5, __half, 2, 4, 64>,
                             cudaFuncAttributeMaxDynamicSharedMemorySize, SM_24);
        cudaFuncSetAttribute(hgemm<EPI_NONE, 6, float, 4, 2, 64>,
                             cudaFuncAttributeMaxDynamicSharedMemorySize, SM_44);
        cudaFuncSetAttribute(hgemm<EPI_NONE, 2, float, 2, 2, 512>,
                             cudaFuncAttributeMaxDynamicSharedMemorySize, SM_22);
        cudaFuncSetAttribute(hgemm<EPI_DINV, 3, __half, 4, 1, 256>,
                             cudaFuncAttributeMaxDynamicSharedMemorySize, SM_41);
        cudaFuncSetAttribute(hgemm<EPI_ADD, 0, float, 4, 2, 512>,
                             cudaFuncAttributeMaxDynamicSharedMemorySize, SM_44);
        cudaFuncSetAttribute(hgemm<EPI_ADD, 0, float, 4, 2, 0>,
                             cudaFuncAttributeMaxDynamicSharedMemorySize, SM_44);
        cudaFuncSetAttribute(hgemm<EPI_GELU, 0, __half, 4, 2, 512>,
                             cudaFuncAttributeMaxDynamicSharedMemorySize, SM_44);
    }

    // launch 0: weight transposes + fp16 conversion
    transpose_all<<<dim3(64, 64, 20), 256>>>(Wqkv, Wo, Wff1, Wff2, proj,
                                             p_wqkvT, p_woT, p_wff1T, p_wff2T,
                                             p_projh);
    // launch 1
    copy_kernel<<<(ROWSc * Dc) / 256, 256>>>(x, h);

    for (int l = 0; l < DEPTHc; l++) {
        const __half* pjh = p_projh + (size_t)l * Mc * DHc;

        ln_kernel<<<ROWSc / 8, 256>>>(h, ln1g + l * Dc, ln1b + l * Dc, p_ln16);

        // launch 3 (profiled): QKV, compile-time K=512
        hgemm<EPI_NONE, 0, __half, 4, 2, 512>
            <<<dim3(QKVW / 128, ROWSc / 128), 256, SM_44>>>(
            p_ln16, Dc, p_wqkvT + (size_t)l * QKVW * Dc, Dc,
            bqkv + l * QKVW, (const float*)0, p_qkv16, QKVW, Dc, 1.0f, 128,
            (float*)0);

        // diag (+ hmax init)
        diag_kernel<<<ROWSc, 256>>>(p_qkv16, p_qdiag, p_kdiag, p_hmax);

        // dd_q with fused featq epilogue (BM=64, BN=256), K=64
        hgemm<EPI_NONE, 5, __half, 2, 4, 64>
            <<<dim3(1, Nc / 64, BHc), 256, SM_24>>>(
            p_qkv16, QKVW, pjh, DHc, (const float*)0, p_qdiag,
            p_qp16, Mc, DHc, DN_CONST, 256, (float*)0);

        // dd_k^T direct: A=proj [256x64], B=k rows -> ddT [bh][m][n] + hmax
        hgemm<EPI_NONE, 6, float, 4, 2, 64>
            <<<dim3(Nc / 128, Mc / 128, BHc), 256, SM_44>>>(
            pjh, DHc, p_qkv16, QKVW, (const float*)0, (const float*)0,
            p_ddT, Nc, DHc, DN_CONST, 128, p_hmax);

        // merged: featk exp+ksum | v transpose
        featk_vtrans<<<dim3(288, BHc), 256>>>(p_ddT, p_kdiag, p_hmax,
                                              p_kpT, p_ksum, p_qkv16, p_vT);

        // ctx^T = vT @ kpT^T, split-K=8 disjoint slabs (BM=64), K=512
        hgemm<EPI_NONE, 2, float, 2, 2, 512>
            <<<dim3(Mc / 128, NSPLIT, BHc), 256, SM_22>>>(
            p_vT, Nc, p_kpT, Nc, (const float*)0, (const float*)0,
            p_ctxF, Mc, Nc / NSPLIT, 1.0f, 128, (float*)0);

        // merged: ctx slab-reduce + dinv
        cvt_dinv<<<1024 + (BHc * Nc) / 8, 256>>>(p_ctxF, p_ctxT,
                                                 p_qp16, p_ksum, p_dinv);

        // attnout = (qp16 @ ctxT^T) * dinv, BN=64, K=256
        hgemm<EPI_DINV, 3, __half, 4, 1, 256>
            <<<dim3(1, Nc / 128, BHc), 256, SM_41>>>(
            p_qp16, Mc, p_ctxT, Mc, (const float*)0, p_dinv,
            p_att16, Dc, Mc, 1.0f, 64, (float*)0);

        // Wo + residual, K=512
        hgemm<EPI_ADD, 0, float, 4, 2, 512>
            <<<dim3(Dc / 128, ROWSc / 128), 256, SM_44>>>(
            p_att16, Dc, p_woT + (size_t)l * Dc * Dc, Dc,
            bo + l * Dc, h, h, Dc, Dc, 1.0f, 128, (float*)0);

        ln_kernel<<<ROWSc / 8, 256>>>(h, ln2g + l * Dc, ln2b + l * Dc, p_ln16);

        // FF1 + gelu, K=512
        hgemm<EPI_GELU, 0, __half, 4, 2, 512>
            <<<dim3(FFc / 128, ROWSc / 128), 256, SM_44>>>(
            p_ln16, Dc, p_wff1T + (size_t)l * FFc * Dc, Dc,
            bff1 + l * FFc, (const float*)0, p_ff16, FFc, Dc, 1.0f, 128,
            (float*)0);

        // FF2 + residual, K=2048 runtime (avoid 64x unroll I$ blowup)
        hgemm<EPI_ADD, 0, float, 4, 2, 0>
            <<<dim3(Dc / 128, ROWSc / 128), 256, SM_44>>>(
            p_ff16, FFc, p_wff2T + (size_t)l * Dc * FFc, FFc,
            bff2 + l * Dc, h, h, Dc, FFc, 1.0f, 128, (float*)0);
    }
}